// round 1
// baseline (speedup 1.0000x reference)
#include <cuda_runtime.h>
#include <math.h>

#define BATCH 4
#define T 2048
#define DM 512
#define DI 1024
#define NH 16
#define HD 64
#define DS 16
#define CONVD 1056
#define DPROJ 2096
#define DINTER 256
#define ROWS (BATCH*T)

// ---------------- scratch (static device globals; no cudaMalloc allowed) ----------------
__device__ float g_resid[ROWS*DM];
__device__ float g_h[ROWS*DM];
__device__ float g_zx[ROWS*DPROJ];       // in_proj output (z | xBC | dt_raw)
__device__ float g_xbc[ROWS*CONVD];      // conv+silu output
__device__ float g_dt[ROWS*NH];
__device__ float g_dA[ROWS*NH];
__device__ float g_y[ROWS*DI];
__device__ float g_tmp[ROWS*DM];
__device__ float g_ff[ROWS*DM];
__device__ float g_glu[ROWS*DINTER];
__device__ float g_x[ROWS*DM];

// ---------------- residual add + LayerNorm ----------------
__global__ void add_ln_kernel(const float* __restrict__ xin, float* __restrict__ resid,
                              const float* __restrict__ w, const float* __restrict__ bch,
                              float* __restrict__ out, int first) {
    int row = blockIdx.x;
    const float* xr = xin + (size_t)row * DM;
    float* rr = resid + (size_t)row * DM;
    float* orow = out + (size_t)row * DM;
    int tid = threadIdx.x;   // 128 threads
    float v[4]; float s = 0.f, s2 = 0.f;
#pragma unroll
    for (int j = 0; j < 4; j++) {
        int c = tid + j * 128;
        float val = xr[c];
        if (!first) val += rr[c];
        v[j] = val; s += val; s2 += val * val;
    }
#pragma unroll
    for (int o = 16; o > 0; o >>= 1) {
        s  += __shfl_xor_sync(0xffffffffu, s, o);
        s2 += __shfl_xor_sync(0xffffffffu, s2, o);
    }
    __shared__ float rs[4], rs2[4];
    int wid = tid >> 5;
    if ((tid & 31) == 0) { rs[wid] = s; rs2[wid] = s2; }
    __syncthreads();
    float tot  = rs[0] + rs[1] + rs[2] + rs[3];
    float tot2 = rs2[0] + rs2[1] + rs2[2] + rs2[3];
    float mu = tot * (1.f / DM);
    float var = tot2 * (1.f / DM) - mu * mu;
    float inv = rsqrtf(var + 1e-5f);
#pragma unroll
    for (int j = 0; j < 4; j++) {
        int c = tid + j * 128;
        float val = v[j];
        rr[c] = val;
        orow[c] = (val - mu) * inv * w[c] + bch[c];
    }
}

// ---------------- fp32 NT GEMM: C[M,N] = A[M,K] * B[N,K]^T ----------------
// 64x64 tile, BK=16, 256 threads, 4x4 per thread
__global__ void sgemm_nt(int M, int N, int K,
                         const float* __restrict__ A, const float* __restrict__ Bw,
                         float* __restrict__ C) {
    __shared__ float As[16][64];
    __shared__ float Bs[16][64];
    int bm = blockIdx.y * 64, bn = blockIdx.x * 64;
    int tid = threadIdx.x;
    int tx = tid & 15, ty = tid >> 4;
    int lrow = tid >> 2;            // 0..63
    int lk4 = (tid & 3) << 2;       // 0,4,8,12
    float acc[4][4] = {};
    const float* Aptr = A + (size_t)(bm + lrow) * K + lk4;
    const float* Bptr = Bw + (size_t)(bn + lrow) * K + lk4;
    bool bvalid = (bn + lrow) < N;
    for (int k0 = 0; k0 < K; k0 += 16) {
        float4 av = *(const float4*)(Aptr + k0);
        float4 bv = bvalid ? *(const float4*)(Bptr + k0) : make_float4(0.f, 0.f, 0.f, 0.f);
        __syncthreads();
        As[lk4 + 0][lrow] = av.x; As[lk4 + 1][lrow] = av.y;
        As[lk4 + 2][lrow] = av.z; As[lk4 + 3][lrow] = av.w;
        Bs[lk4 + 0][lrow] = bv.x; Bs[lk4 + 1][lrow] = bv.y;
        Bs[lk4 + 2][lrow] = bv.z; Bs[lk4 + 3][lrow] = bv.w;
        __syncthreads();
#pragma unroll
        for (int k = 0; k < 16; k++) {
            float a0 = As[k][ty * 4 + 0], a1 = As[k][ty * 4 + 1];
            float a2 = As[k][ty * 4 + 2], a3 = As[k][ty * 4 + 3];
            float b0 = Bs[k][tx * 4 + 0], b1 = Bs[k][tx * 4 + 1];
            float b2 = Bs[k][tx * 4 + 2], b3 = Bs[k][tx * 4 + 3];
            acc[0][0] += a0 * b0; acc[0][1] += a0 * b1; acc[0][2] += a0 * b2; acc[0][3] += a0 * b3;
            acc[1][0] += a1 * b0; acc[1][1] += a1 * b1; acc[1][2] += a1 * b2; acc[1][3] += a1 * b3;
            acc[2][0] += a2 * b0; acc[2][1] += a2 * b1; acc[2][2] += a2 * b2; acc[2][3] += a2 * b3;
            acc[3][0] += a3 * b0; acc[3][1] += a3 * b1; acc[3][2] += a3 * b2; acc[3][3] += a3 * b3;
        }
    }
#pragma unroll
    for (int i = 0; i < 4; i++) {
        int m = bm + ty * 4 + i;
#pragma unroll
        for (int j = 0; j < 4; j++) {
            int n = bn + tx * 4 + j;
            if (n < N) C[(size_t)m * N + n] = acc[i][j];
        }
    }
}

// ---------------- dt = softplus(raw + dtb); dA = exp(dt * A) ----------------
__global__ void dt_kernel(const float* __restrict__ zx, const float* __restrict__ dtb,
                          const float* __restrict__ alog, float* __restrict__ dt,
                          float* __restrict__ dAo) {
    int idx = blockIdx.x * blockDim.x + threadIdx.x;
    if (idx >= ROWS * NH) return;
    int row = idx >> 4; int h = idx & 15;
    float raw = zx[(size_t)row * DPROJ + (DI + CONVD) + h] + dtb[h];
    float d = (raw > 20.f) ? raw : log1pf(expf(raw));
    float A = -expf(alog[h]);
    dt[idx] = d;
    dAo[idx] = expf(d * A);
}

// ---------------- depthwise causal conv (direction-aware) + bias + silu ----------------
__global__ void conv_silu(const float* __restrict__ zx, const float* __restrict__ cw,
                          const float* __restrict__ cb, float* __restrict__ out, int rev) {
    int idx = blockIdx.x * blockDim.x + threadIdx.x;
    if (idx >= ROWS * CONVD) return;
    int c = idx % CONVD; int r = idx / CONVD;
    int b = r / T; int t = r % T;
    const float* w = cw + c * 4;
    const float* col = zx + (size_t)b * T * DPROJ + DI + c;
    float acc = cb[c];
    if (!rev) {
#pragma unroll
        for (int k = 0; k < 4; k++) { int tt = t - 3 + k; if (tt >= 0) acc += w[k] * col[(size_t)tt * DPROJ]; }
    } else {
#pragma unroll
        for (int k = 0; k < 4; k++) { int tt = t + 3 - k; if (tt < T) acc += w[k] * col[(size_t)tt * DPROJ]; }
    }
    out[idx] = acc / (1.f + expf(-acc));
}

// ---------------- sequential SSM scan; one block per (b, head) ----------------
// 256 threads: thread t -> p = t/4 (0..63), n-group = (t%4)*4; h state in registers.
__global__ void scan_kernel(const float* __restrict__ xbc, const float* __restrict__ dt,
                            const float* __restrict__ dA, const float* __restrict__ Dp,
                            float* __restrict__ y, int rev) {
    int bh = blockIdx.x; int b = bh >> 4; int head = bh & 15;
    int tid = threadIdx.x;
    int p = tid >> 2; int ng = (tid & 3) << 2;
    __shared__ float sx[2][64], sB[2][16], sC[2][16], sS[2][2];
    float hreg[4] = {0.f, 0.f, 0.f, 0.f};
    float Dv = Dp[head];
    const size_t base = (size_t)b * T;

    // prologue: load first step into buffer 0
    {
        int t0 = rev ? (T - 1) : 0;
        size_t row = base + t0;
        if (tid < 64)       sx[0][tid]      = xbc[row * CONVD + head * HD + tid];
        else if (tid < 80)  sB[0][tid - 64] = xbc[row * CONVD + DI + (tid - 64)];
        else if (tid < 96)  sC[0][tid - 80] = xbc[row * CONVD + DI + DS + (tid - 80)];
        else if (tid == 96) { sS[0][0] = dA[row * NH + head]; sS[0][1] = dt[row * NH + head]; }
    }
    int buf = 0;
    for (int s = 0; s < T; s++) {
        __syncthreads();
        if (s + 1 < T) {
            int tn = rev ? (T - 2 - s) : (s + 1);
            size_t row = base + tn;
            int nb = buf ^ 1;
            if (tid < 64)       sx[nb][tid]      = xbc[row * CONVD + head * HD + tid];
            else if (tid < 80)  sB[nb][tid - 64] = xbc[row * CONVD + DI + (tid - 64)];
            else if (tid < 96)  sC[nb][tid - 80] = xbc[row * CONVD + DI + DS + (tid - 80)];
            else if (tid == 96) { sS[nb][0] = dA[row * NH + head]; sS[nb][1] = dt[row * NH + head]; }
        }
        int t = rev ? (T - 1 - s) : s;
        size_t row = base + t;
        float dAv = sS[buf][0], dtv = sS[buf][1];
        float xp = sx[buf][p];
        float coef = dtv * xp;
        float acc = 0.f;
#pragma unroll
        for (int j = 0; j < 4; j++) {
            hreg[j] = hreg[j] * dAv + coef * sB[buf][ng + j];
            acc += hreg[j] * sC[buf][ng + j];
        }
        acc += __shfl_xor_sync(0xffffffffu, acc, 1);
        acc += __shfl_xor_sync(0xffffffffu, acc, 2);
        if ((tid & 3) == 0) y[row * DI + head * HD + p] = acc + Dv * xp;
        buf ^= 1;
    }
}

// ---------------- y = y * silu(z); RMSNorm(y) * gw ----------------
__global__ void gate_rms(const float* __restrict__ zx, float* __restrict__ y,
                         const float* __restrict__ gw) {
    int row = blockIdx.x;
    const float* z = zx + (size_t)row * DPROJ;
    float* yr = y + (size_t)row * DI;
    int tid = threadIdx.x;  // 256
    float v[4]; float s2 = 0.f;
#pragma unroll
    for (int j = 0; j < 4; j++) {
        int c = tid + j * 256;
        float zz = z[c];
        float val = yr[c] * (zz / (1.f + expf(-zz)));
        v[j] = val; s2 += val * val;
    }
#pragma unroll
    for (int o = 16; o > 0; o >>= 1) s2 += __shfl_xor_sync(0xffffffffu, s2, o);
    __shared__ float rs[8];
    int wid = tid >> 5;
    if ((tid & 31) == 0) rs[wid] = s2;
    __syncthreads();
    float tot = 0.f;
#pragma unroll
    for (int i = 0; i < 8; i++) tot += rs[i];
    float inv = rsqrtf(tot * (1.f / DI) + 1e-5f);
#pragma unroll
    for (int j = 0; j < 4; j++) {
        int c = tid + j * 256;
        yr[c] = v[j] * inv * gw[c];
    }
}

// ---------------- GLU: a * silu(g) ----------------
__global__ void glu_kernel(const float* __restrict__ ff, float* __restrict__ out) {
    int idx = blockIdx.x * blockDim.x + threadIdx.x;
    if (idx >= ROWS * DINTER) return;
    int row = idx >> 8; int j = idx & 255;
    float a = ff[(size_t)row * DM + j];
    float g = ff[(size_t)row * DM + DINTER + j];
    out[idx] = a * g / (1.f + expf(-g));
}

// ---------------- host ----------------
static float* sym_addr(const void* sym) {
    void* p = nullptr;
    cudaGetSymbolAddress(&p, sym);
    return (float*)p;
}

extern "C" void kernel_launch(void* const* d_in, const int* in_sizes, int n_in,
                              void* d_out, int out_size) {
    const float* in_x   = (const float*)d_in[0];
    const float* n1w    = (const float*)d_in[1];
    const float* n1b    = (const float*)d_in[2];
    const float* inw    = (const float*)d_in[3];
    const float* cw     = (const float*)d_in[4];
    const float* cb     = (const float*)d_in[5];
    const float* dtb    = (const float*)d_in[6];
    const float* alog   = (const float*)d_in[7];
    const float* Dp     = (const float*)d_in[8];
    const float* gw     = (const float*)d_in[9];
    const float* ow     = (const float*)d_in[10];
    const float* n2w    = (const float*)d_in[11];
    const float* n2b    = (const float*)d_in[12];
    const float* f1w    = (const float*)d_in[13];
    const float* f2w    = (const float*)d_in[14];
    const float* nfw    = (const float*)d_in[15];
    const float* nfb    = (const float*)d_in[16];

    float* resid = sym_addr(g_resid);
    float* hbuf  = sym_addr(g_h);
    float* zx    = sym_addr(g_zx);
    float* xbc   = sym_addr(g_xbc);
    float* dtg   = sym_addr(g_dt);
    float* dAg   = sym_addr(g_dA);
    float* ybuf  = sym_addr(g_y);
    float* tmp   = sym_addr(g_tmp);
    float* ffb   = sym_addr(g_ff);
    float* glub  = sym_addr(g_glu);
    float* xb    = sym_addr(g_x);

    dim3 gemm_threads(256);

    for (int i = 0; i < 4; i++) {
        int rev = i & 1;
        const float* xin = (i == 0) ? in_x : xb;

        // 1) residual add + LN1
        add_ln_kernel<<<ROWS, 128>>>(xin, resid, n1w + i * DM, n1b + i * DM, hbuf, (i == 0) ? 1 : 0);

        // 2) in_proj: zx = h @ inw^T   [8192 x 2096]
        {
            dim3 grid((DPROJ + 63) / 64, ROWS / 64);
            sgemm_nt<<<grid, gemm_threads>>>(ROWS, DPROJ, DM, hbuf, inw + (size_t)i * DPROJ * DM, zx);
        }

        // 3) dt / dA
        dt_kernel<<<(ROWS * NH + 255) / 256, 256>>>(zx, dtb + i * NH, alog + i * NH, dtg, dAg);

        // 4) conv + silu (direction-aware)
        conv_silu<<<(ROWS * CONVD + 255) / 256, 256>>>(zx, cw + (size_t)i * CONVD * 4, cb + i * CONVD, xbc, rev);

        // 5) sequential scan (direction-aware), writes y (+ D*x)
        scan_kernel<<<BATCH * NH, 256>>>(xbc, dtg, dAg, Dp + i * NH, ybuf, rev);

        // 6) gate with silu(z), RMSNorm
        gate_rms<<<ROWS, 256>>>(zx, ybuf, gw + i * DI);

        // 7) out_proj: tmp = y @ ow^T   [8192 x 512]
        {
            dim3 grid(DM / 64, ROWS / 64);
            sgemm_nt<<<grid, gemm_threads>>>(ROWS, DM, DI, ybuf, ow + (size_t)i * DM * DI, tmp);
        }

        // 8) residual add + LN2 -> h
        add_ln_kernel<<<ROWS, 128>>>(tmp, resid, n2w + i * DM, n2b + i * DM, hbuf, 0);

        // 9) FFN f1: ff = h @ f1w^T   [8192 x 512]
        {
            dim3 grid(DM / 64, ROWS / 64);
            sgemm_nt<<<grid, gemm_threads>>>(ROWS, DM, DM, hbuf, f1w + (size_t)i * DM * DM, ffb);
        }

        // 10) GLU
        glu_kernel<<<(ROWS * DINTER + 255) / 256, 256>>>(ffb, glub);

        // 11) FFN f2: x = glu @ f2w^T   [8192 x 512]
        {
            dim3 grid(DM / 64, ROWS / 64);
            sgemm_nt<<<grid, gemm_threads>>>(ROWS, DM, DINTER, glub, f2w + (size_t)i * DM * DINTER, xb);
        }
    }

    // final: residual = x + residual; out = LN(residual, nfw, nfb)
    add_ln_kernel<<<ROWS, 128>>>(xb, resid, nfw, nfb, (float*)d_out, 0);
}

// round 2
// speedup vs baseline: 1.2598x; 1.2598x over previous
#include <cuda_runtime.h>
#include <math.h>
#include <stdint.h>

#define BATCH 4
#define T 2048
#define DM 512
#define DI 1024
#define NH 16
#define HD 64
#define DS 16
#define CONVD 1056
#define DPROJ 2096
#define DINTER 256
#define ROWS (BATCH*T)

// ---------------- scratch (static device globals; no cudaMalloc allowed) ----------------
__device__ float g_resid[ROWS*DM];
__device__ float g_h[ROWS*DM];
__device__ float g_zx[ROWS*DPROJ];       // in_proj output (z | xBC | dt_raw)
__device__ float g_xbc[ROWS*CONVD];      // conv+silu output
__device__ float g_dt[ROWS*NH];
__device__ float g_dA[ROWS*NH];
__device__ float g_y[ROWS*DI];
__device__ float g_tmp[ROWS*DM];
__device__ float g_ff[ROWS*DM];
__device__ float g_glu[ROWS*DINTER];
__device__ float g_x[ROWS*DM];

// ---------------- residual add + LayerNorm ----------------
__global__ void add_ln_kernel(const float* __restrict__ xin, float* __restrict__ resid,
                              const float* __restrict__ w, const float* __restrict__ bch,
                              float* __restrict__ out, int first) {
    int row = blockIdx.x;
    const float* xr = xin + (size_t)row * DM;
    float* rr = resid + (size_t)row * DM;
    float* orow = out + (size_t)row * DM;
    int tid = threadIdx.x;   // 128 threads
    float v[4]; float s = 0.f, s2 = 0.f;
#pragma unroll
    for (int j = 0; j < 4; j++) {
        int c = tid + j * 128;
        float val = xr[c];
        if (!first) val += rr[c];
        v[j] = val; s += val; s2 += val * val;
    }
#pragma unroll
    for (int o = 16; o > 0; o >>= 1) {
        s  += __shfl_xor_sync(0xffffffffu, s, o);
        s2 += __shfl_xor_sync(0xffffffffu, s2, o);
    }
    __shared__ float rs[4], rs2[4];
    int wid = tid >> 5;
    if ((tid & 31) == 0) { rs[wid] = s; rs2[wid] = s2; }
    __syncthreads();
    float tot  = rs[0] + rs[1] + rs[2] + rs[3];
    float tot2 = rs2[0] + rs2[1] + rs2[2] + rs2[3];
    float mu = tot * (1.f / DM);
    float var = tot2 * (1.f / DM) - mu * mu;
    float inv = rsqrtf(var + 1e-5f);
#pragma unroll
    for (int j = 0; j < 4; j++) {
        int c = tid + j * 128;
        float val = v[j];
        rr[c] = val;
        orow[c] = (val - mu) * inv * w[c] + bch[c];
    }
}

// ---------------- tf32 tensor-core NT GEMM: C[M,N] = A[M,K] * B[N,K]^T ----------------
// Block tile 128x128x32, 256 threads (8 warps as 2Mx4N), warp tile 64x32.
// Fragments: 4 m-tiles (m16) x 4 n-tiles (n8), K chunks of 8 per mma.

__device__ __forceinline__ float tf32_round(float x) {
    uint32_t u;
    asm("cvt.rna.tf32.f32 %0, %1;" : "=r"(u) : "f"(x));
    return __uint_as_float(u);
}

#define MMA_TF32(d, a, b) \
    asm volatile("mma.sync.aligned.m16n8k8.row.col.f32.tf32.tf32.f32 " \
                 "{%0,%1,%2,%3},{%4,%5,%6,%7},{%8,%9},{%0,%1,%2,%3};" \
                 : "+f"(d[0]), "+f"(d[1]), "+f"(d[2]), "+f"(d[3]) \
                 : "r"(a[0]), "r"(a[1]), "r"(a[2]), "r"(a[3]), "r"(b[0]), "r"(b[1]))

__global__ void __launch_bounds__(256) tf32_gemm_nt(int M, int N, int K,
                                                    const float* __restrict__ A,
                                                    const float* __restrict__ Bw,
                                                    float* __restrict__ C) {
    __shared__ float As[128][33];
    __shared__ float Bs[128][33];
    int bm = blockIdx.y * 128, bn = blockIdx.x * 128;
    int tid = threadIdx.x;
    int wid = tid >> 5, lane = tid & 31;
    int wm = (wid & 1) * 64;        // warp M offset (2 warps along M)
    int wn = (wid >> 1) * 32;       // warp N offset (4 warps along N)
    int g = lane >> 2, tig = lane & 3;
    float acc[4][4][4];
#pragma unroll
    for (int i = 0; i < 4; i++)
#pragma unroll
        for (int j = 0; j < 4; j++)
#pragma unroll
            for (int k = 0; k < 4; k++) acc[i][j][k] = 0.f;

    for (int k0 = 0; k0 < K; k0 += 32) {
        __syncthreads();
        // Load A tile (128x32) and B tile (128x32), converting to tf32.
#pragma unroll
        for (int i = 0; i < 4; i++) {
            int idx = i * 256 + tid;
            int r = idx >> 3;           // 0..127
            int kq = (idx & 7) << 2;    // 0,4,...,28
            float4 va = *(const float4*)(A + (size_t)(bm + r) * K + k0 + kq);
            As[r][kq + 0] = tf32_round(va.x);
            As[r][kq + 1] = tf32_round(va.y);
            As[r][kq + 2] = tf32_round(va.z);
            As[r][kq + 3] = tf32_round(va.w);
            int rb = bn + r;
            float4 vb = (rb < N) ? *(const float4*)(Bw + (size_t)rb * K + k0 + kq)
                                 : make_float4(0.f, 0.f, 0.f, 0.f);
            Bs[r][kq + 0] = tf32_round(vb.x);
            Bs[r][kq + 1] = tf32_round(vb.y);
            Bs[r][kq + 2] = tf32_round(vb.z);
            Bs[r][kq + 3] = tf32_round(vb.w);
        }
        __syncthreads();
#pragma unroll
        for (int ks = 0; ks < 4; ks++) {
            int kk = ks * 8;
            uint32_t a[4][4];
            uint32_t b[4][2];
#pragma unroll
            for (int mt = 0; mt < 4; mt++) {
                int r = wm + mt * 16 + g;
                a[mt][0] = __float_as_uint(As[r][kk + tig]);
                a[mt][1] = __float_as_uint(As[r + 8][kk + tig]);
                a[mt][2] = __float_as_uint(As[r][kk + tig + 4]);
                a[mt][3] = __float_as_uint(As[r + 8][kk + tig + 4]);
            }
#pragma unroll
            for (int nt = 0; nt < 4; nt++) {
                int c = wn + nt * 8 + g;
                b[nt][0] = __float_as_uint(Bs[c][kk + tig]);
                b[nt][1] = __float_as_uint(Bs[c][kk + tig + 4]);
            }
#pragma unroll
            for (int mt = 0; mt < 4; mt++)
#pragma unroll
                for (int nt = 0; nt < 4; nt++)
                    MMA_TF32(acc[mt][nt], a[mt], b[nt]);
        }
    }

    // Epilogue: c0:(g, tig*2) c1:(g, tig*2+1) c2:(g+8, tig*2) c3:(g+8, tig*2+1)
#pragma unroll
    for (int mt = 0; mt < 4; mt++) {
        int r0 = bm + wm + mt * 16 + g;
#pragma unroll
        for (int nt = 0; nt < 4; nt++) {
            int c0 = bn + wn + nt * 8 + tig * 2;
            if (c0 < N) {
                C[(size_t)r0 * N + c0]       = acc[mt][nt][0];
                C[(size_t)r0 * N + c0 + 1]   = acc[mt][nt][1];
                C[(size_t)(r0 + 8) * N + c0]     = acc[mt][nt][2];
                C[(size_t)(r0 + 8) * N + c0 + 1] = acc[mt][nt][3];
            }
        }
    }
}

// ---------------- dt = softplus(raw + dtb); dA = exp(dt * A) ----------------
__global__ void dt_kernel(const float* __restrict__ zx, const float* __restrict__ dtb,
                          const float* __restrict__ alog, float* __restrict__ dt,
                          float* __restrict__ dAo) {
    int idx = blockIdx.x * blockDim.x + threadIdx.x;
    if (idx >= ROWS * NH) return;
    int row = idx >> 4; int h = idx & 15;
    float raw = zx[(size_t)row * DPROJ + (DI + CONVD) + h] + dtb[h];
    float d = (raw > 20.f) ? raw : log1pf(expf(raw));
    float A = -expf(alog[h]);
    dt[idx] = d;
    dAo[idx] = expf(d * A);
}

// ---------------- depthwise causal conv (direction-aware) + bias + silu ----------------
__global__ void conv_silu(const float* __restrict__ zx, const float* __restrict__ cw,
                          const float* __restrict__ cb, float* __restrict__ out, int rev) {
    int idx = blockIdx.x * blockDim.x + threadIdx.x;
    if (idx >= ROWS * CONVD) return;
    int c = idx % CONVD; int r = idx / CONVD;
    int b = r / T; int t = r % T;
    const float* w = cw + c * 4;
    const float* col = zx + (size_t)b * T * DPROJ + DI + c;
    float acc = cb[c];
    if (!rev) {
#pragma unroll
        for (int k = 0; k < 4; k++) { int tt = t - 3 + k; if (tt >= 0) acc += w[k] * col[(size_t)tt * DPROJ]; }
    } else {
#pragma unroll
        for (int k = 0; k < 4; k++) { int tt = t + 3 - k; if (tt < T) acc += w[k] * col[(size_t)tt * DPROJ]; }
    }
    out[idx] = acc / (1.f + expf(-acc));
}

// ---------------- sequential SSM scan; one block per (b, head) ----------------
__global__ void scan_kernel(const float* __restrict__ xbc, const float* __restrict__ dt,
                            const float* __restrict__ dA, const float* __restrict__ Dp,
                            float* __restrict__ y, int rev) {
    int bh = blockIdx.x; int b = bh >> 4; int head = bh & 15;
    int tid = threadIdx.x;
    int p = tid >> 2; int ng = (tid & 3) << 2;
    __shared__ float sx[2][64], sB[2][16], sC[2][16], sS[2][2];
    float hreg[4] = {0.f, 0.f, 0.f, 0.f};
    float Dv = Dp[head];
    const size_t base = (size_t)b * T;

    {
        int t0 = rev ? (T - 1) : 0;
        size_t row = base + t0;
        if (tid < 64)       sx[0][tid]      = xbc[row * CONVD + head * HD + tid];
        else if (tid < 80)  sB[0][tid - 64] = xbc[row * CONVD + DI + (tid - 64)];
        else if (tid < 96)  sC[0][tid - 80] = xbc[row * CONVD + DI + DS + (tid - 80)];
        else if (tid == 96) { sS[0][0] = dA[row * NH + head]; sS[0][1] = dt[row * NH + head]; }
    }
    int buf = 0;
    for (int s = 0; s < T; s++) {
        __syncthreads();
        if (s + 1 < T) {
            int tn = rev ? (T - 2 - s) : (s + 1);
            size_t row = base + tn;
            int nb = buf ^ 1;
            if (tid < 64)       sx[nb][tid]      = xbc[row * CONVD + head * HD + tid];
            else if (tid < 80)  sB[nb][tid - 64] = xbc[row * CONVD + DI + (tid - 64)];
            else if (tid < 96)  sC[nb][tid - 80] = xbc[row * CONVD + DI + DS + (tid - 80)];
            else if (tid == 96) { sS[nb][0] = dA[row * NH + head]; sS[nb][1] = dt[row * NH + head]; }
        }
        int t = rev ? (T - 1 - s) : s;
        size_t row = base + t;
        float dAv = sS[buf][0], dtv = sS[buf][1];
        float xp = sx[buf][p];
        float coef = dtv * xp;
        float acc = 0.f;
#pragma unroll
        for (int j = 0; j < 4; j++) {
            hreg[j] = hreg[j] * dAv + coef * sB[buf][ng + j];
            acc += hreg[j] * sC[buf][ng + j];
        }
        acc += __shfl_xor_sync(0xffffffffu, acc, 1);
        acc += __shfl_xor_sync(0xffffffffu, acc, 2);
        if ((tid & 3) == 0) y[row * DI + head * HD + p] = acc + Dv * xp;
        buf ^= 1;
    }
}

// ---------------- y = y * silu(z); RMSNorm(y) * gw ----------------
__global__ void gate_rms(const float* __restrict__ zx, float* __restrict__ y,
                         const float* __restrict__ gw) {
    int row = blockIdx.x;
    const float* z = zx + (size_t)row * DPROJ;
    float* yr = y + (size_t)row * DI;
    int tid = threadIdx.x;  // 256
    float v[4]; float s2 = 0.f;
#pragma unroll
    for (int j = 0; j < 4; j++) {
        int c = tid + j * 256;
        float zz = z[c];
        float val = yr[c] * (zz / (1.f + expf(-zz)));
        v[j] = val; s2 += val * val;
    }
#pragma unroll
    for (int o = 16; o > 0; o >>= 1) s2 += __shfl_xor_sync(0xffffffffu, s2, o);
    __shared__ float rs[8];
    int wid = tid >> 5;
    if ((tid & 31) == 0) rs[wid] = s2;
    __syncthreads();
    float tot = 0.f;
#pragma unroll
    for (int i = 0; i < 8; i++) tot += rs[i];
    float inv = rsqrtf(tot * (1.f / DI) + 1e-5f);
#pragma unroll
    for (int j = 0; j < 4; j++) {
        int c = tid + j * 256;
        yr[c] = v[j] * inv * gw[c];
    }
}

// ---------------- GLU: a * silu(g) ----------------
__global__ void glu_kernel(const float* __restrict__ ff, float* __restrict__ out) {
    int idx = blockIdx.x * blockDim.x + threadIdx.x;
    if (idx >= ROWS * DINTER) return;
    int row = idx >> 8; int j = idx & 255;
    float a = ff[(size_t)row * DM + j];
    float g = ff[(size_t)row * DM + DINTER + j];
    out[idx] = a * g / (1.f + expf(-g));
}

// ---------------- host ----------------
static float* sym_addr(const void* sym) {
    void* p = nullptr;
    cudaGetSymbolAddress(&p, sym);
    return (float*)p;
}

extern "C" void kernel_launch(void* const* d_in, const int* in_sizes, int n_in,
                              void* d_out, int out_size) {
    const float* in_x   = (const float*)d_in[0];
    const float* n1w    = (const float*)d_in[1];
    const float* n1b    = (const float*)d_in[2];
    const float* inw    = (const float*)d_in[3];
    const float* cw     = (const float*)d_in[4];
    const float* cb     = (const float*)d_in[5];
    const float* dtb    = (const float*)d_in[6];
    const float* alog   = (const float*)d_in[7];
    const float* Dp     = (const float*)d_in[8];
    const float* gw     = (const float*)d_in[9];
    const float* ow     = (const float*)d_in[10];
    const float* n2w    = (const float*)d_in[11];
    const float* n2b    = (const float*)d_in[12];
    const float* f1w    = (const float*)d_in[13];
    const float* f2w    = (const float*)d_in[14];
    const float* nfw    = (const float*)d_in[15];
    const float* nfb    = (const float*)d_in[16];

    float* resid = sym_addr(g_resid);
    float* zx    = sym_addr(g_zx);
    float* xbc   = sym_addr(g_xbc);
    float* dtg   = sym_addr(g_dt);
    float* dAg   = sym_addr(g_dA);
    float* ybuf  = sym_addr(g_y);
    float* tmp   = sym_addr(g_tmp);
    float* ffb   = sym_addr(g_ff);
    float* glub  = sym_addr(g_glu);
    float* xb    = sym_addr(g_x);
    float* hbuf  = sym_addr(g_h);

    for (int i = 0; i < 4; i++) {
        int rev = i & 1;
        const float* xin = (i == 0) ? in_x : xb;

        // 1) residual add + LN1
        add_ln_kernel<<<ROWS, 128>>>(xin, resid, n1w + i * DM, n1b + i * DM, hbuf, (i == 0) ? 1 : 0);

        // 2) in_proj: zx = h @ inw^T   [8192 x 2096]
        {
            dim3 grid((DPROJ + 127) / 128, ROWS / 128);
            tf32_gemm_nt<<<grid, 256>>>(ROWS, DPROJ, DM, hbuf, inw + (size_t)i * DPROJ * DM, zx);
        }

        // 3) dt / dA
        dt_kernel<<<(ROWS * NH + 255) / 256, 256>>>(zx, dtb + i * NH, alog + i * NH, dtg, dAg);

        // 4) conv + silu (direction-aware)
        conv_silu<<<(ROWS * CONVD + 255) / 256, 256>>>(zx, cw + (size_t)i * CONVD * 4, cb + i * CONVD, xbc, rev);

        // 5) sequential scan (direction-aware), writes y (+ D*x)
        scan_kernel<<<BATCH * NH, 256>>>(xbc, dtg, dAg, Dp + i * NH, ybuf, rev);

        // 6) gate with silu(z), RMSNorm
        gate_rms<<<ROWS, 256>>>(zx, ybuf, gw + i * DI);

        // 7) out_proj: tmp = y @ ow^T   [8192 x 512]
        {
            dim3 grid(DM / 128, ROWS / 128);
            tf32_gemm_nt<<<grid, 256>>>(ROWS, DM, DI, ybuf, ow + (size_t)i * DM * DI, tmp);
        }

        // 8) residual add + LN2 -> h
        add_ln_kernel<<<ROWS, 128>>>(tmp, resid, n2w + i * DM, n2b + i * DM, hbuf, 0);

        // 9) FFN f1: ff = h @ f1w^T   [8192 x 512]
        {
            dim3 grid(DM / 128, ROWS / 128);
            tf32_gemm_nt<<<grid, 256>>>(ROWS, DM, DM, hbuf, f1w + (size_t)i * DM * DM, ffb);
        }

        // 10) GLU
        glu_kernel<<<(ROWS * DINTER + 255) / 256, 256>>>(ffb, glub);

        // 11) FFN f2: x = glu @ f2w^T   [8192 x 512]
        {
            dim3 grid(DM / 128, ROWS / 128);
            tf32_gemm_nt<<<grid, 256>>>(ROWS, DM, DINTER, glub, f2w + (size_t)i * DM * DINTER, xb);
        }
    }

    // final: residual = x + residual; out = LN(residual, nfw, nfb)
    add_ln_kernel<<<ROWS, 128>>>(xb, resid, nfw, nfb, (float*)d_out, 0);
}

// round 3
// speedup vs baseline: 1.4344x; 1.1386x over previous
#include <cuda_runtime.h>
#include <math.h>
#include <stdint.h>

#define BATCH 4
#define T 2048
#define DM 512
#define DI 1024
#define NH 16
#define HD 64
#define DS 16
#define CONVD 1056
#define DPROJ 2096
#define DINTER 256
#define ROWS (BATCH*T)

// GEMM tiling
#define BKK 64
#define LDT 68                 // 64 + 4 pad floats; 272B row stride = 17*16B (ldmatrix-legal, conflict-free)
#define ATILE (128*LDT)        // floats per tile per stage
#define GEMM_SMEM (4*ATILE*4)  // 2 stages * (A+B) in bytes = 139264

// ---------------- scratch (static device globals; no cudaMalloc allowed) ----------------
__device__ float g_resid[ROWS*DM];
__device__ float g_h[ROWS*DM];
__device__ float g_zx[ROWS*DPROJ];
__device__ float g_xbc[ROWS*CONVD];
__device__ float g_dt[ROWS*NH];
__device__ float g_dA[ROWS*NH];
__device__ float g_y[ROWS*DI];
__device__ float g_tmp[ROWS*DM];
__device__ float g_ff[ROWS*DM];
__device__ float g_glu[ROWS*DINTER];
__device__ float g_x[ROWS*DM];
// pre-rounded (tf32) weights
__device__ float g_winw[4*DPROJ*DM];
__device__ float g_wow[4*DM*DI];
__device__ float g_wf1[4*2*DINTER*DM];
__device__ float g_wf2[4*DM*DINTER];

__device__ __forceinline__ float tf32_round(float x) {
    uint32_t u;
    asm("cvt.rna.tf32.f32 %0, %1;" : "=r"(u) : "f"(x));
    return __uint_as_float(u);
}

// ---------------- weight rounding (per call; feeds tf32 GEMM) ----------------
__global__ void round_copy(const float* __restrict__ src, float* __restrict__ dst, int n4) {
    int i = blockIdx.x * blockDim.x + threadIdx.x;
    if (i >= n4) return;
    float4 v = ((const float4*)src)[i];
    v.x = tf32_round(v.x); v.y = tf32_round(v.y);
    v.z = tf32_round(v.z); v.w = tf32_round(v.w);
    ((float4*)dst)[i] = v;
}

// ---------------- residual add + LayerNorm ----------------
__global__ void add_ln_kernel(const float* __restrict__ xin, float* __restrict__ resid,
                              const float* __restrict__ w, const float* __restrict__ bch,
                              float* __restrict__ out, int first, int round_out) {
    int row = blockIdx.x;
    const float* xr = xin + (size_t)row * DM;
    float* rr = resid + (size_t)row * DM;
    float* orow = out + (size_t)row * DM;
    int tid = threadIdx.x;   // 128
    float v[4]; float s = 0.f, s2 = 0.f;
#pragma unroll
    for (int j = 0; j < 4; j++) {
        int c = tid + j * 128;
        float val = xr[c];
        if (!first) val += rr[c];
        v[j] = val; s += val; s2 += val * val;
    }
#pragma unroll
    for (int o = 16; o > 0; o >>= 1) {
        s  += __shfl_xor_sync(0xffffffffu, s, o);
        s2 += __shfl_xor_sync(0xffffffffu, s2, o);
    }
    __shared__ float rs[4], rs2[4];
    int wid = tid >> 5;
    if ((tid & 31) == 0) { rs[wid] = s; rs2[wid] = s2; }
    __syncthreads();
    float tot  = rs[0] + rs[1] + rs[2] + rs[3];
    float tot2 = rs2[0] + rs2[1] + rs2[2] + rs2[3];
    float mu = tot * (1.f / DM);
    float var = tot2 * (1.f / DM) - mu * mu;
    float inv = rsqrtf(var + 1e-5f);
#pragma unroll
    for (int j = 0; j < 4; j++) {
        int c = tid + j * 128;
        float val = v[j];
        rr[c] = val;
        float o2 = (val - mu) * inv * w[c] + bch[c];
        orow[c] = round_out ? tf32_round(o2) : o2;
    }
}

// ---------------- pipelined tf32 tensor-core NT GEMM ----------------
// C[M,N] = A[M,K] * B[N,K]^T. Block 128x128, BK=64, 2-stage cp.async,
// 8 warps (2M x 4N), warp tile 64x32, ldmatrix fragments.

#define MMA_TF32(d, a, b) \
    asm volatile("mma.sync.aligned.m16n8k8.row.col.f32.tf32.tf32.f32 " \
                 "{%0,%1,%2,%3},{%4,%5,%6,%7},{%8,%9},{%0,%1,%2,%3};" \
                 : "+f"(d[0]), "+f"(d[1]), "+f"(d[2]), "+f"(d[3]) \
                 : "r"(a[0]), "r"(a[1]), "r"(a[2]), "r"(a[3]), "r"(b[0]), "r"(b[1]))

#define LDSM_X4(R, addr) \
    asm volatile("ldmatrix.sync.aligned.m8n8.x4.shared.b16 {%0,%1,%2,%3}, [%4];" \
                 : "=r"((R)[0]), "=r"((R)[1]), "=r"((R)[2]), "=r"((R)[3]) : "r"(addr))
#define LDSM_X2(R, addr) \
    asm volatile("ldmatrix.sync.aligned.m8n8.x2.shared.b16 {%0,%1}, [%2];" \
                 : "=r"((R)[0]), "=r"((R)[1]) : "r"(addr))

__device__ __forceinline__ void gemm_load_stage(
    const float* __restrict__ A, const float* __restrict__ Bw,
    int K, int N, int bm, int bn, int it, int s, int tid, uint32_t sbase)
{
    uint32_t As_s = sbase + (uint32_t)(s * ATILE) * 4u;
    uint32_t Bs_s = sbase + (uint32_t)((2 + s) * ATILE) * 4u;
    int k0 = it * BKK;
#pragma unroll
    for (int i = 0; i < 8; i++) {
        int idx = i * 256 + tid;
        int row = idx >> 4;            // 0..127
        int kq  = (idx & 15) << 2;     // 0..60
        uint32_t sa = As_s + (uint32_t)(row * LDT + kq) * 4u;
        const float* gp = A + (size_t)(bm + row) * K + k0 + kq;
        asm volatile("cp.async.cg.shared.global [%0], [%1], 16;" :: "r"(sa), "l"(gp));
        int rb = bn + row;
        int valid = (rb < N);
        const float* gpb = Bw + (size_t)(valid ? rb : 0) * K + k0 + kq;
        uint32_t sb = Bs_s + (uint32_t)(row * LDT + kq) * 4u;
        int ssz = valid ? 16 : 0;
        asm volatile("cp.async.cg.shared.global [%0], [%1], 16, %2;" :: "r"(sb), "l"(gpb), "r"(ssz));
    }
    asm volatile("cp.async.commit_group;" ::: "memory");
}

__global__ void __launch_bounds__(256, 1) tf32_gemm_nt(int M, int N, int K,
                                                       const float* __restrict__ A,
                                                       const float* __restrict__ Bw,
                                                       float* __restrict__ C) {
    extern __shared__ float sm[];
    uint32_t sbase = (uint32_t)__cvta_generic_to_shared(sm);
    int bm = blockIdx.y * 128, bn = blockIdx.x * 128;
    int tid = threadIdx.x;
    int wid = tid >> 5, lane = tid & 31;
    int wm = (wid & 1) * 64;
    int wn = (wid >> 1) * 32;
    int g = lane >> 2, tig = lane & 3;

    // ldmatrix per-lane source rows/cols
    int sub = lane >> 3;                        // 0..3
    int rA = (lane & 7) + ((sub & 1) << 3);     // row within 16
    int cA = (sub >> 1) << 2;                   // 0 or 4
    int rB = lane & 7;
    int cB = ((lane >> 3) & 1) << 2;
    uint32_t aoff = (uint32_t)((wm + rA) * LDT + cA) * 4u;
    uint32_t boff = (uint32_t)((wn + rB) * LDT + cB) * 4u;

    float acc[4][4][4];
#pragma unroll
    for (int i = 0; i < 4; i++)
#pragma unroll
        for (int j = 0; j < 4; j++)
#pragma unroll
            for (int k = 0; k < 4; k++) acc[i][j][k] = 0.f;

    int NIT = K / BKK;
    gemm_load_stage(A, Bw, K, N, bm, bn, 0, 0, tid, sbase);
    if (NIT > 1) gemm_load_stage(A, Bw, K, N, bm, bn, 1, 1, tid, sbase);

    for (int it = 0; it < NIT; ++it) {
        if (it < NIT - 1) asm volatile("cp.async.wait_group 1;" ::: "memory");
        else              asm volatile("cp.async.wait_group 0;" ::: "memory");
        __syncthreads();
        int s = it & 1;
        uint32_t Abase = sbase + (uint32_t)(s * ATILE) * 4u + aoff;
        uint32_t Bbase = sbase + (uint32_t)((2 + s) * ATILE) * 4u + boff;
#pragma unroll
        for (int ks = 0; ks < 8; ks++) {
            int kk = ks * 8;
            uint32_t a[4][4], b[4][2];
#pragma unroll
            for (int mt = 0; mt < 4; mt++)
                LDSM_X4(a[mt], Abase + (uint32_t)(mt * 16 * LDT + kk) * 4u);
#pragma unroll
            for (int nt = 0; nt < 4; nt++)
                LDSM_X2(b[nt], Bbase + (uint32_t)(nt * 8 * LDT + kk) * 4u);
#pragma unroll
            for (int mt = 0; mt < 4; mt++)
#pragma unroll
                for (int nt = 0; nt < 4; nt++)
                    MMA_TF32(acc[mt][nt], a[mt], b[nt]);
        }
        __syncthreads();
        if (it + 2 < NIT) gemm_load_stage(A, Bw, K, N, bm, bn, it + 2, s, tid, sbase);
    }

    // Epilogue
#pragma unroll
    for (int mt = 0; mt < 4; mt++) {
        int r0 = bm + wm + mt * 16 + g;
#pragma unroll
        for (int nt = 0; nt < 4; nt++) {
            int c0 = bn + wn + nt * 8 + tig * 2;
            if (c0 < N) {
                float2 v0 = make_float2(acc[mt][nt][0], acc[mt][nt][1]);
                float2 v1 = make_float2(acc[mt][nt][2], acc[mt][nt][3]);
                *(float2*)&C[(size_t)r0 * N + c0] = v0;
                *(float2*)&C[(size_t)(r0 + 8) * N + c0] = v1;
            }
        }
    }
}

// ---------------- dt = softplus(raw + dtb); dA = exp(dt * A) ----------------
__global__ void dt_kernel(const float* __restrict__ zx, const float* __restrict__ dtb,
                          const float* __restrict__ alog, float* __restrict__ dt,
                          float* __restrict__ dAo) {
    int idx = blockIdx.x * blockDim.x + threadIdx.x;
    if (idx >= ROWS * NH) return;
    int row = idx >> 4; int h = idx & 15;
    float raw = zx[(size_t)row * DPROJ + (DI + CONVD) + h] + dtb[h];
    float d = (raw > 20.f) ? raw : log1pf(expf(raw));
    float A = -expf(alog[h]);
    dt[idx] = d;
    dAo[idx] = expf(d * A);
}

// ---------------- depthwise causal conv (direction-aware) + bias + silu ----------------
__global__ void conv_silu(const float* __restrict__ zx, const float* __restrict__ cw,
                          const float* __restrict__ cb, float* __restrict__ out, int rev) {
    int idx = blockIdx.x * blockDim.x + threadIdx.x;
    if (idx >= ROWS * CONVD) return;
    int c = idx % CONVD; int r = idx / CONVD;
    int b = r / T; int t = r % T;
    const float* w = cw + c * 4;
    const float* col = zx + (size_t)b * T * DPROJ + DI + c;
    float acc = cb[c];
    if (!rev) {
#pragma unroll
        for (int k = 0; k < 4; k++) { int tt = t - 3 + k; if (tt >= 0) acc += w[k] * col[(size_t)tt * DPROJ]; }
    } else {
#pragma unroll
        for (int k = 0; k < 4; k++) { int tt = t + 3 - k; if (tt < T) acc += w[k] * col[(size_t)tt * DPROJ]; }
    }
    out[idx] = acc / (1.f + expf(-acc));
}

// ---------------- sequential SSM scan; one block per (b, head) ----------------
__global__ void scan_kernel(const float* __restrict__ xbc, const float* __restrict__ dt,
                            const float* __restrict__ dA, const float* __restrict__ Dp,
                            float* __restrict__ y, int rev) {
    int bh = blockIdx.x; int b = bh >> 4; int head = bh & 15;
    int tid = threadIdx.x;
    int p = tid >> 2; int ng = (tid & 3) << 2;
    __shared__ float sx[2][64], sB[2][16], sC[2][16], sS[2][2];
    float hreg[4] = {0.f, 0.f, 0.f, 0.f};
    float Dv = Dp[head];
    const size_t base = (size_t)b * T;

    {
        int t0 = rev ? (T - 1) : 0;
        size_t row = base + t0;
        if (tid < 64)       sx[0][tid]      = xbc[row * CONVD + head * HD + tid];
        else if (tid < 80)  sB[0][tid - 64] = xbc[row * CONVD + DI + (tid - 64)];
        else if (tid < 96)  sC[0][tid - 80] = xbc[row * CONVD + DI + DS + (tid - 80)];
        else if (tid == 96) { sS[0][0] = dA[row * NH + head]; sS[0][1] = dt[row * NH + head]; }
    }
    int buf = 0;
    for (int s = 0; s < T; s++) {
        __syncthreads();
        if (s + 1 < T) {
            int tn = rev ? (T - 2 - s) : (s + 1);
            size_t row = base + tn;
            int nb = buf ^ 1;
            if (tid < 64)       sx[nb][tid]      = xbc[row * CONVD + head * HD + tid];
            else if (tid < 80)  sB[nb][tid - 64] = xbc[row * CONVD + DI + (tid - 64)];
            else if (tid < 96)  sC[nb][tid - 80] = xbc[row * CONVD + DI + DS + (tid - 80)];
            else if (tid == 96) { sS[nb][0] = dA[row * NH + head]; sS[nb][1] = dt[row * NH + head]; }
        }
        int t = rev ? (T - 1 - s) : s;
        size_t row = base + t;
        float dAv = sS[buf][0], dtv = sS[buf][1];
        float xp = sx[buf][p];
        float coef = dtv * xp;
        float acc = 0.f;
#pragma unroll
        for (int j = 0; j < 4; j++) {
            hreg[j] = hreg[j] * dAv + coef * sB[buf][ng + j];
            acc += hreg[j] * sC[buf][ng + j];
        }
        acc += __shfl_xor_sync(0xffffffffu, acc, 1);
        acc += __shfl_xor_sync(0xffffffffu, acc, 2);
        if ((tid & 3) == 0) y[row * DI + head * HD + p] = acc + Dv * xp;
        buf ^= 1;
    }
}

// ---------------- y = y * silu(z); RMSNorm(y) * gw (tf32-rounded out) ----------------
__global__ void gate_rms(const float* __restrict__ zx, float* __restrict__ y,
                         const float* __restrict__ gw) {
    int row = blockIdx.x;
    const float* z = zx + (size_t)row * DPROJ;
    float* yr = y + (size_t)row * DI;
    int tid = threadIdx.x;  // 256
    float v[4]; float s2 = 0.f;
#pragma unroll
    for (int j = 0; j < 4; j++) {
        int c = tid + j * 256;
        float zz = z[c];
        float val = yr[c] * (zz / (1.f + expf(-zz)));
        v[j] = val; s2 += val * val;
    }
#pragma unroll
    for (int o = 16; o > 0; o >>= 1) s2 += __shfl_xor_sync(0xffffffffu, s2, o);
    __shared__ float rs[8];
    int wid = tid >> 5;
    if ((tid & 31) == 0) rs[wid] = s2;
    __syncthreads();
    float tot = 0.f;
#pragma unroll
    for (int i = 0; i < 8; i++) tot += rs[i];
    float inv = rsqrtf(tot * (1.f / DI) + 1e-5f);
#pragma unroll
    for (int j = 0; j < 4; j++) {
        int c = tid + j * 256;
        yr[c] = tf32_round(v[j] * inv * gw[c]);
    }
}

// ---------------- GLU: a * silu(g) (tf32-rounded out) ----------------
__global__ void glu_kernel(const float* __restrict__ ff, float* __restrict__ out) {
    int idx = blockIdx.x * blockDim.x + threadIdx.x;
    if (idx >= ROWS * DINTER) return;
    int row = idx >> 8; int j = idx & 255;
    float a = ff[(size_t)row * DM + j];
    float g = ff[(size_t)row * DM + DINTER + j];
    out[idx] = tf32_round(a * g / (1.f + expf(-g)));
}

// ---------------- host ----------------
static float* sym_addr(const void* sym) {
    void* p = nullptr;
    cudaGetSymbolAddress(&p, sym);
    return (float*)p;
}

extern "C" void kernel_launch(void* const* d_in, const int* in_sizes, int n_in,
                              void* d_out, int out_size) {
    const float* in_x   = (const float*)d_in[0];
    const float* n1w    = (const float*)d_in[1];
    const float* n1b    = (const float*)d_in[2];
    const float* inw    = (const float*)d_in[3];
    const float* cw     = (const float*)d_in[4];
    const float* cb     = (const float*)d_in[5];
    const float* dtb    = (const float*)d_in[6];
    const float* alog   = (const float*)d_in[7];
    const float* Dp     = (const float*)d_in[8];
    const float* gw     = (const float*)d_in[9];
    const float* ow     = (const float*)d_in[10];
    const float* n2w    = (const float*)d_in[11];
    const float* n2b    = (const float*)d_in[12];
    const float* f1w    = (const float*)d_in[13];
    const float* f2w    = (const float*)d_in[14];
    const float* nfw    = (const float*)d_in[15];
    const float* nfb    = (const float*)d_in[16];

    float* resid = sym_addr(g_resid);
    float* zx    = sym_addr(g_zx);
    float* xbc   = sym_addr(g_xbc);
    float* dtg   = sym_addr(g_dt);
    float* dAg   = sym_addr(g_dA);
    float* ybuf  = sym_addr(g_y);
    float* tmp   = sym_addr(g_tmp);
    float* ffb   = sym_addr(g_ff);
    float* glub  = sym_addr(g_glu);
    float* xb    = sym_addr(g_x);
    float* hbuf  = sym_addr(g_h);
    float* winw  = sym_addr(g_winw);
    float* wow   = sym_addr(g_wow);
    float* wf1   = sym_addr(g_wf1);
    float* wf2   = sym_addr(g_wf2);

    static int smem_set = 0;
    if (!smem_set) {
        cudaFuncSetAttribute(tf32_gemm_nt, cudaFuncAttributeMaxDynamicSharedMemorySize, GEMM_SMEM);
        smem_set = 1;
    }

    // pre-round all weights to tf32
    {
        int n;
        n = 4 * DPROJ * DM / 4;   round_copy<<<(n + 255) / 256, 256>>>(inw, winw, n);
        n = 4 * DM * DI / 4;      round_copy<<<(n + 255) / 256, 256>>>(ow, wow, n);
        n = 4 * 2 * DINTER * DM / 4; round_copy<<<(n + 255) / 256, 256>>>(f1w, wf1, n);
        n = 4 * DM * DINTER / 4;  round_copy<<<(n + 255) / 256, 256>>>(f2w, wf2, n);
    }

    for (int i = 0; i < 4; i++) {
        int rev = i & 1;
        const float* xin = (i == 0) ? in_x : xb;

        // 1) residual add + LN1 (tf32-rounded output -> GEMM A)
        add_ln_kernel<<<ROWS, 128>>>(xin, resid, n1w + i * DM, n1b + i * DM, hbuf, (i == 0) ? 1 : 0, 1);

        // 2) in_proj: zx = h @ inw^T   [8192 x 2096 x 512]
        {
            dim3 grid((DPROJ + 127) / 128, ROWS / 128);
            tf32_gemm_nt<<<grid, 256, GEMM_SMEM>>>(ROWS, DPROJ, DM, hbuf, winw + (size_t)i * DPROJ * DM, zx);
        }

        // 3) dt / dA
        dt_kernel<<<(ROWS * NH + 255) / 256, 256>>>(zx, dtb + i * NH, alog + i * NH, dtg, dAg);

        // 4) conv + silu
        conv_silu<<<(ROWS * CONVD + 255) / 256, 256>>>(zx, cw + (size_t)i * CONVD * 4, cb + i * CONVD, xbc, rev);

        // 5) scan
        scan_kernel<<<BATCH * NH, 256>>>(xbc, dtg, dAg, Dp + i * NH, ybuf, rev);

        // 6) gate + RMSNorm (rounded)
        gate_rms<<<ROWS, 256>>>(zx, ybuf, gw + i * DI);

        // 7) out_proj: tmp = y @ ow^T   [8192 x 512 x 1024]
        {
            dim3 grid(DM / 128, ROWS / 128);
            tf32_gemm_nt<<<grid, 256, GEMM_SMEM>>>(ROWS, DM, DI, ybuf, wow + (size_t)i * DM * DI, tmp);
        }

        // 8) residual add + LN2 (rounded)
        add_ln_kernel<<<ROWS, 128>>>(tmp, resid, n2w + i * DM, n2b + i * DM, hbuf, 0, 1);

        // 9) FFN f1: ff = h @ f1w^T   [8192 x 512 x 512]
        {
            dim3 grid(DM / 128, ROWS / 128);
            tf32_gemm_nt<<<grid, 256, GEMM_SMEM>>>(ROWS, DM, DM, hbuf, wf1 + (size_t)i * DM * DM, ffb);
        }

        // 10) GLU (rounded)
        glu_kernel<<<(ROWS * DINTER + 255) / 256, 256>>>(ffb, glub);

        // 11) FFN f2: x = glu @ f2w^T   [8192 x 512 x 256]
        {
            dim3 grid(DM / 128, ROWS / 128);
            tf32_gemm_nt<<<grid, 256, GEMM_SMEM>>>(ROWS, DM, DINTER, glub, wf2 + (size_t)i * DM * DINTER, xb);
        }
    }

    // final: residual = x + residual; out = LN(residual) — NOT rounded
    add_ln_kernel<<<ROWS, 128>>>(xb, resid, nfw, nfb, (float*)d_out, 0, 0);
}

// round 4
// speedup vs baseline: 1.4622x; 1.0194x over previous
#include <cuda_runtime.h>
#include <math.h>
#include <stdint.h>

#define BATCH 4
#define T 2048
#define DM 512
#define DI 1024
#define NH 16
#define HD 64
#define DS 16
#define CONVD 1056
#define DPROJ 2096
#define DINTER 256
#define ROWS (BATCH*T)

// GEMM tiling
#define BKK 64
#define LDT 68                 // 64 + 4 pad floats; 272B row stride = 17*16B (ldmatrix-legal, conflict-free)
#define ATILE (128*LDT)        // floats per tile per stage
#define GEMM_SMEM (4*ATILE*4)  // 2 stages * (A+B) in bytes = 139264

// ---------------- scratch (static device globals; no cudaMalloc allowed) ----------------
__device__ float g_resid[ROWS*DM];
__device__ float g_h[ROWS*DM];
__device__ float g_zx[ROWS*DPROJ];
__device__ float g_xbc[ROWS*CONVD];
__device__ float g_dt[ROWS*NH];
__device__ float g_dA[ROWS*NH];
__device__ float g_y[ROWS*DI];
__device__ float g_tmp[ROWS*DM];
__device__ float g_ff[ROWS*DM];
__device__ float g_glu[ROWS*DINTER];
__device__ float g_x[ROWS*DM];
// pre-rounded (tf32) weights
__device__ float g_winw[4*DPROJ*DM];
__device__ float g_wow[4*DM*DI];
__device__ float g_wf1[4*2*DINTER*DM];
__device__ float g_wf2[4*DM*DINTER];

__device__ __forceinline__ float tf32_round(float x) {
    uint32_t u;
    asm("cvt.rna.tf32.f32 %0, %1;" : "=r"(u) : "f"(x));
    return __uint_as_float(u);
}

// ---------------- weight rounding (per call; feeds tf32 GEMM) ----------------
__global__ void round_copy(const float* __restrict__ src, float* __restrict__ dst, int n4) {
    int i = blockIdx.x * blockDim.x + threadIdx.x;
    if (i >= n4) return;
    float4 v = ((const float4*)src)[i];
    v.x = tf32_round(v.x); v.y = tf32_round(v.y);
    v.z = tf32_round(v.z); v.w = tf32_round(v.w);
    ((float4*)dst)[i] = v;
}

// ---------------- residual add + LayerNorm ----------------
__global__ void add_ln_kernel(const float* __restrict__ xin, float* __restrict__ resid,
                              const float* __restrict__ w, const float* __restrict__ bch,
                              float* __restrict__ out, int first, int round_out) {
    int row = blockIdx.x;
    const float* xr = xin + (size_t)row * DM;
    float* rr = resid + (size_t)row * DM;
    float* orow = out + (size_t)row * DM;
    int tid = threadIdx.x;   // 128
    float v[4]; float s = 0.f, s2 = 0.f;
#pragma unroll
    for (int j = 0; j < 4; j++) {
        int c = tid + j * 128;
        float val = xr[c];
        if (!first) val += rr[c];
        v[j] = val; s += val; s2 += val * val;
    }
#pragma unroll
    for (int o = 16; o > 0; o >>= 1) {
        s  += __shfl_xor_sync(0xffffffffu, s, o);
        s2 += __shfl_xor_sync(0xffffffffu, s2, o);
    }
    __shared__ float rs[4], rs2[4];
    int wid = tid >> 5;
    if ((tid & 31) == 0) { rs[wid] = s; rs2[wid] = s2; }
    __syncthreads();
    float tot  = rs[0] + rs[1] + rs[2] + rs[3];
    float tot2 = rs2[0] + rs2[1] + rs2[2] + rs2[3];
    float mu = tot * (1.f / DM);
    float var = tot2 * (1.f / DM) - mu * mu;
    float inv = rsqrtf(var + 1e-5f);
#pragma unroll
    for (int j = 0; j < 4; j++) {
        int c = tid + j * 128;
        float val = v[j];
        rr[c] = val;
        float o2 = (val - mu) * inv * w[c] + bch[c];
        orow[c] = round_out ? tf32_round(o2) : o2;
    }
}

// ---------------- pipelined tf32 tensor-core NT GEMM ----------------
// C[M,N] = A[M,K] * B[N,K]^T. Block 128x128, BK=64, 2-stage cp.async,
// 8 warps (2M x 4N), warp tile 64x32, ldmatrix fragments.

#define MMA_TF32(d, a, b) \
    asm volatile("mma.sync.aligned.m16n8k8.row.col.f32.tf32.tf32.f32 " \
                 "{%0,%1,%2,%3},{%4,%5,%6,%7},{%8,%9},{%0,%1,%2,%3};" \
                 : "+f"(d[0]), "+f"(d[1]), "+f"(d[2]), "+f"(d[3]) \
                 : "r"(a[0]), "r"(a[1]), "r"(a[2]), "r"(a[3]), "r"(b[0]), "r"(b[1]))

#define LDSM_X4(R, addr) \
    asm volatile("ldmatrix.sync.aligned.m8n8.x4.shared.b16 {%0,%1,%2,%3}, [%4];" \
                 : "=r"((R)[0]), "=r"((R)[1]), "=r"((R)[2]), "=r"((R)[3]) : "r"(addr))
#define LDSM_X2(R, addr) \
    asm volatile("ldmatrix.sync.aligned.m8n8.x2.shared.b16 {%0,%1}, [%2];" \
                 : "=r"((R)[0]), "=r"((R)[1]) : "r"(addr))

__device__ __forceinline__ void gemm_load_stage(
    const float* __restrict__ A, const float* __restrict__ Bw,
    int K, int N, int bm, int bn, int it, int s, int tid, uint32_t sbase)
{
    uint32_t As_s = sbase + (uint32_t)(s * ATILE) * 4u;
    uint32_t Bs_s = sbase + (uint32_t)((2 + s) * ATILE) * 4u;
    int k0 = it * BKK;
#pragma unroll
    for (int i = 0; i < 8; i++) {
        int idx = i * 256 + tid;
        int row = idx >> 4;            // 0..127
        int kq  = (idx & 15) << 2;     // 0..60
        uint32_t sa = As_s + (uint32_t)(row * LDT + kq) * 4u;
        const float* gp = A + (size_t)(bm + row) * K + k0 + kq;
        asm volatile("cp.async.cg.shared.global [%0], [%1], 16;" :: "r"(sa), "l"(gp));
        int rb = bn + row;
        int valid = (rb < N);
        const float* gpb = Bw + (size_t)(valid ? rb : 0) * K + k0 + kq;
        uint32_t sb = Bs_s + (uint32_t)(row * LDT + kq) * 4u;
        int ssz = valid ? 16 : 0;
        asm volatile("cp.async.cg.shared.global [%0], [%1], 16, %2;" :: "r"(sb), "l"(gpb), "r"(ssz));
    }
    asm volatile("cp.async.commit_group;" ::: "memory");
}

__global__ void __launch_bounds__(256, 1) tf32_gemm_nt(int M, int N, int K,
                                                       const float* __restrict__ A,
                                                       const float* __restrict__ Bw,
                                                       float* __restrict__ C) {
    extern __shared__ float sm[];
    uint32_t sbase = (uint32_t)__cvta_generic_to_shared(sm);
    int bm = blockIdx.y * 128, bn = blockIdx.x * 128;
    int tid = threadIdx.x;
    int wid = tid >> 5, lane = tid & 31;
    int wm = (wid & 1) * 64;
    int wn = (wid >> 1) * 32;
    int g = lane >> 2, tig = lane & 3;

    // ldmatrix per-lane source rows/cols
    int sub = lane >> 3;                        // 0..3
    int rA = (lane & 7) + ((sub & 1) << 3);     // row within 16
    int cA = (sub >> 1) << 2;                   // 0 or 4
    int rB = lane & 7;
    int cB = ((lane >> 3) & 1) << 2;
    uint32_t aoff = (uint32_t)((wm + rA) * LDT + cA) * 4u;
    uint32_t boff = (uint32_t)((wn + rB) * LDT + cB) * 4u;

    float acc[4][4][4];
#pragma unroll
    for (int i = 0; i < 4; i++)
#pragma unroll
        for (int j = 0; j < 4; j++)
#pragma unroll
            for (int k = 0; k < 4; k++) acc[i][j][k] = 0.f;

    int NIT = K / BKK;
    gemm_load_stage(A, Bw, K, N, bm, bn, 0, 0, tid, sbase);
    if (NIT > 1) gemm_load_stage(A, Bw, K, N, bm, bn, 1, 1, tid, sbase);

    for (int it = 0; it < NIT; ++it) {
        if (it < NIT - 1) asm volatile("cp.async.wait_group 1;" ::: "memory");
        else              asm volatile("cp.async.wait_group 0;" ::: "memory");
        __syncthreads();
        int s = it & 1;
        uint32_t Abase = sbase + (uint32_t)(s * ATILE) * 4u + aoff;
        uint32_t Bbase = sbase + (uint32_t)((2 + s) * ATILE) * 4u + boff;
#pragma unroll
        for (int ks = 0; ks < 8; ks++) {
            int kk = ks * 8;
            uint32_t a[4][4], b[4][2];
#pragma unroll
            for (int mt = 0; mt < 4; mt++)
                LDSM_X4(a[mt], Abase + (uint32_t)(mt * 16 * LDT + kk) * 4u);
#pragma unroll
            for (int nt = 0; nt < 4; nt++)
                LDSM_X2(b[nt], Bbase + (uint32_t)(nt * 8 * LDT + kk) * 4u);
#pragma unroll
            for (int mt = 0; mt < 4; mt++)
#pragma unroll
                for (int nt = 0; nt < 4; nt++)
                    MMA_TF32(acc[mt][nt], a[mt], b[nt]);
        }
        __syncthreads();
        if (it + 2 < NIT) gemm_load_stage(A, Bw, K, N, bm, bn, it + 2, s, tid, sbase);
    }

    // Epilogue
#pragma unroll
    for (int mt = 0; mt < 4; mt++) {
        int r0 = bm + wm + mt * 16 + g;
#pragma unroll
        for (int nt = 0; nt < 4; nt++) {
            int c0 = bn + wn + nt * 8 + tig * 2;
            if (c0 < N) {
                float2 v0 = make_float2(acc[mt][nt][0], acc[mt][nt][1]);
                float2 v1 = make_float2(acc[mt][nt][2], acc[mt][nt][3]);
                *(float2*)&C[(size_t)r0 * N + c0] = v0;
                *(float2*)&C[(size_t)(r0 + 8) * N + c0] = v1;
            }
        }
    }
}

// ---------------- dt = softplus(raw + dtb); dA = exp(dt * A) ----------------
__global__ void dt_kernel(const float* __restrict__ zx, const float* __restrict__ dtb,
                          const float* __restrict__ alog, float* __restrict__ dt,
                          float* __restrict__ dAo) {
    int idx = blockIdx.x * blockDim.x + threadIdx.x;
    if (idx >= ROWS * NH) return;
    int row = idx >> 4; int h = idx & 15;
    float raw = zx[(size_t)row * DPROJ + (DI + CONVD) + h] + dtb[h];
    float d = (raw > 20.f) ? raw : log1pf(expf(raw));
    float A = -expf(alog[h]);
    dt[idx] = d;
    dAo[idx] = expf(d * A);
}

// ---------------- depthwise causal conv (direction-aware) + bias + silu ----------------
__global__ void conv_silu(const float* __restrict__ zx, const float* __restrict__ cw,
                          const float* __restrict__ cb, float* __restrict__ out, int rev) {
    int idx = blockIdx.x * blockDim.x + threadIdx.x;
    if (idx >= ROWS * CONVD) return;
    int c = idx % CONVD; int r = idx / CONVD;
    int b = r / T; int t = r % T;
    const float* w = cw + c * 4;
    const float* col = zx + (size_t)b * T * DPROJ + DI + c;
    float acc = cb[c];
    if (!rev) {
#pragma unroll
        for (int k = 0; k < 4; k++) { int tt = t - 3 + k; if (tt >= 0) acc += w[k] * col[(size_t)tt * DPROJ]; }
    } else {
#pragma unroll
        for (int k = 0; k < 4; k++) { int tt = t + 3 - k; if (tt < T) acc += w[k] * col[(size_t)tt * DPROJ]; }
    }
    out[idx] = acc / (1.f + expf(-acc));
}

// ---------------- sequential SSM scan; one block per (b, head) ----------------
__global__ void scan_kernel(const float* __restrict__ xbc, const float* __restrict__ dt,
                            const float* __restrict__ dA, const float* __restrict__ Dp,
                            float* __restrict__ y, int rev) {
    int bh = blockIdx.x; int b = bh >> 4; int head = bh & 15;
    int tid = threadIdx.x;
    int p = tid >> 2; int ng = (tid & 3) << 2;
    __shared__ float sx[2][64], sB[2][16], sC[2][16], sS[2][2];
    float hreg[4] = {0.f, 0.f, 0.f, 0.f};
    float Dv = Dp[head];
    const size_t base = (size_t)b * T;

    {
        int t0 = rev ? (T - 1) : 0;
        size_t row = base + t0;
        if (tid < 64)       sx[0][tid]      = xbc[row * CONVD + head * HD + tid];
        else if (tid < 80)  sB[0][tid - 64] = xbc[row * CONVD + DI + (tid - 64)];
        else if (tid < 96)  sC[0][tid - 80] = xbc[row * CONVD + DI + DS + (tid - 80)];
        else if (tid == 96) { sS[0][0] = dA[row * NH + head]; sS[0][1] = dt[row * NH + head]; }
    }
    int buf = 0;
    for (int s = 0; s < T; s++) {
        __syncthreads();
        if (s + 1 < T) {
            int tn = rev ? (T - 2 - s) : (s + 1);
            size_t row = base + tn;
            int nb = buf ^ 1;
            if (tid < 64)       sx[nb][tid]      = xbc[row * CONVD + head * HD + tid];
            else if (tid < 80)  sB[nb][tid - 64] = xbc[row * CONVD + DI + (tid - 64)];
            else if (tid < 96)  sC[nb][tid - 80] = xbc[row * CONVD + DI + DS + (tid - 80)];
            else if (tid == 96) { sS[nb][0] = dA[row * NH + head]; sS[nb][1] = dt[row * NH + head]; }
        }
        int t = rev ? (T - 1 - s) : s;
        size_t row = base + t;
        float dAv = sS[buf][0], dtv = sS[buf][1];
        float xp = sx[buf][p];
        float coef = dtv * xp;
        float acc = 0.f;
#pragma unroll
        for (int j = 0; j < 4; j++) {
            hreg[j] = hreg[j] * dAv + coef * sB[buf][ng + j];
            acc += hreg[j] * sC[buf][ng + j];
        }
        acc += __shfl_xor_sync(0xffffffffu, acc, 1);
        acc += __shfl_xor_sync(0xffffffffu, acc, 2);
        if ((tid & 3) == 0) y[row * DI + head * HD + p] = acc + Dv * xp;
        buf ^= 1;
    }
}

// ---------------- y = y * silu(z); RMSNorm(y) * gw (tf32-rounded out) ----------------
__global__ void gate_rms(const float* __restrict__ zx, float* __restrict__ y,
                         const float* __restrict__ gw) {
    int row = blockIdx.x;
    const float* z = zx + (size_t)row * DPROJ;
    float* yr = y + (size_t)row * DI;
    int tid = threadIdx.x;  // 256
    float v[4]; float s2 = 0.f;
#pragma unroll
    for (int j = 0; j < 4; j++) {
        int c = tid + j * 256;
        float zz = z[c];
        float val = yr[c] * (zz / (1.f + expf(-zz)));
        v[j] = val; s2 += val * val;
    }
#pragma unroll
    for (int o = 16; o > 0; o >>= 1) s2 += __shfl_xor_sync(0xffffffffu, s2, o);
    __shared__ float rs[8];
    int wid = tid >> 5;
    if ((tid & 31) == 0) rs[wid] = s2;
    __syncthreads();
    float tot = 0.f;
#pragma unroll
    for (int i = 0; i < 8; i++) tot += rs[i];
    float inv = rsqrtf(tot * (1.f / DI) + 1e-5f);
#pragma unroll
    for (int j = 0; j < 4; j++) {
        int c = tid + j * 256;
        yr[c] = tf32_round(v[j] * inv * gw[c]);
    }
}

// ---------------- GLU: a * silu(g) (tf32-rounded out) ----------------
__global__ void glu_kernel(const float* __restrict__ ff, float* __restrict__ out) {
    int idx = blockIdx.x * blockDim.x + threadIdx.x;
    if (idx >= ROWS * DINTER) return;
    int row = idx >> 8; int j = idx & 255;
    float a = ff[(size_t)row * DM + j];
    float g = ff[(size_t)row * DM + DINTER + j];
    out[idx] = tf32_round(a * g / (1.f + expf(-g)));
}

// ---------------- host ----------------
static float* sym_addr(const void* sym) {
    void* p = nullptr;
    cudaGetSymbolAddress(&p, sym);
    return (float*)p;
}

extern "C" void kernel_launch(void* const* d_in, const int* in_sizes, int n_in,
                              void* d_out, int out_size) {
    const float* in_x   = (const float*)d_in[0];
    const float* n1w    = (const float*)d_in[1];
    const float* n1b    = (const float*)d_in[2];
    const float* inw    = (const float*)d_in[3];
    const float* cw     = (const float*)d_in[4];
    const float* cb     = (const float*)d_in[5];
    const float* dtb    = (const float*)d_in[6];
    const float* alog   = (const float*)d_in[7];
    const float* Dp     = (const float*)d_in[8];
    const float* gw     = (const float*)d_in[9];
    const float* ow     = (const float*)d_in[10];
    const float* n2w    = (const float*)d_in[11];
    const float* n2b    = (const float*)d_in[12];
    const float* f1w    = (const float*)d_in[13];
    const float* f2w    = (const float*)d_in[14];
    const float* nfw    = (const float*)d_in[15];
    const float* nfb    = (const float*)d_in[16];

    float* resid = sym_addr(g_resid);
    float* zx    = sym_addr(g_zx);
    float* xbc   = sym_addr(g_xbc);
    float* dtg   = sym_addr(g_dt);
    float* dAg   = sym_addr(g_dA);
    float* ybuf  = sym_addr(g_y);
    float* tmp   = sym_addr(g_tmp);
    float* ffb   = sym_addr(g_ff);
    float* glub  = sym_addr(g_glu);
    float* xb    = sym_addr(g_x);
    float* hbuf  = sym_addr(g_h);
    float* winw  = sym_addr(g_winw);
    float* wow   = sym_addr(g_wow);
    float* wf1   = sym_addr(g_wf1);
    float* wf2   = sym_addr(g_wf2);

    static int smem_set = 0;
    if (!smem_set) {
        cudaFuncSetAttribute(tf32_gemm_nt, cudaFuncAttributeMaxDynamicSharedMemorySize, GEMM_SMEM);
        smem_set = 1;
    }

    // pre-round all weights to tf32
    {
        int n;
        n = 4 * DPROJ * DM / 4;   round_copy<<<(n + 255) / 256, 256>>>(inw, winw, n);
        n = 4 * DM * DI / 4;      round_copy<<<(n + 255) / 256, 256>>>(ow, wow, n);
        n = 4 * 2 * DINTER * DM / 4; round_copy<<<(n + 255) / 256, 256>>>(f1w, wf1, n);
        n = 4 * DM * DINTER / 4;  round_copy<<<(n + 255) / 256, 256>>>(f2w, wf2, n);
    }

    for (int i = 0; i < 4; i++) {
        int rev = i & 1;
        const float* xin = (i == 0) ? in_x : xb;

        // 1) residual add + LN1 (tf32-rounded output -> GEMM A)
        add_ln_kernel<<<ROWS, 128>>>(xin, resid, n1w + i * DM, n1b + i * DM, hbuf, (i == 0) ? 1 : 0, 1);

        // 2) in_proj: zx = h @ inw^T   [8192 x 2096 x 512]
        {
            dim3 grid((DPROJ + 127) / 128, ROWS / 128);
            tf32_gemm_nt<<<grid, 256, GEMM_SMEM>>>(ROWS, DPROJ, DM, hbuf, winw + (size_t)i * DPROJ * DM, zx);
        }

        // 3) dt / dA
        dt_kernel<<<(ROWS * NH + 255) / 256, 256>>>(zx, dtb + i * NH, alog + i * NH, dtg, dAg);

        // 4) conv + silu
        conv_silu<<<(ROWS * CONVD + 255) / 256, 256>>>(zx, cw + (size_t)i * CONVD * 4, cb + i * CONVD, xbc, rev);

        // 5) scan
        scan_kernel<<<BATCH * NH, 256>>>(xbc, dtg, dAg, Dp + i * NH, ybuf, rev);

        // 6) gate + RMSNorm (rounded)
        gate_rms<<<ROWS, 256>>>(zx, ybuf, gw + i * DI);

        // 7) out_proj: tmp = y @ ow^T   [8192 x 512 x 1024]
        {
            dim3 grid(DM / 128, ROWS / 128);
            tf32_gemm_nt<<<grid, 256, GEMM_SMEM>>>(ROWS, DM, DI, ybuf, wow + (size_t)i * DM * DI, tmp);
        }

        // 8) residual add + LN2 (rounded)
        add_ln_kernel<<<ROWS, 128>>>(tmp, resid, n2w + i * DM, n2b + i * DM, hbuf, 0, 1);

        // 9) FFN f1: ff = h @ f1w^T   [8192 x 512 x 512]
        {
            dim3 grid(DM / 128, ROWS / 128);
            tf32_gemm_nt<<<grid, 256, GEMM_SMEM>>>(ROWS, DM, DM, hbuf, wf1 + (size_t)i * DM * DM, ffb);
        }

        // 10) GLU (rounded)
        glu_kernel<<<(ROWS * DINTER + 255) / 256, 256>>>(ffb, glub);

        // 11) FFN f2: x = glu @ f2w^T   [8192 x 512 x 256]
        {
            dim3 grid(DM / 128, ROWS / 128);
            tf32_gemm_nt<<<grid, 256, GEMM_SMEM>>>(ROWS, DM, DINTER, glub, wf2 + (size_t)i * DM * DINTER, xb);
        }
    }

    // final: residual = x + residual; out = LN(residual) — NOT rounded
    add_ln_kernel<<<ROWS, 128>>>(xb, resid, nfw, nfb, (float*)d_out, 0, 0);
}

// round 5
// speedup vs baseline: 4.4900x; 3.0708x over previous
#include <cuda_runtime.h>
#include <math.h>
#include <stdint.h>

#define BATCH 4
#define T 2048
#define DM 512
#define DI 1024
#define NH 16
#define HD 64
#define DS 16
#define CONVD 1056
#define DPROJ 2096
#define DINTER 256
#define ROWS (BATCH*T)

// chunked scan
#define CQ 64
#define NC (T/CQ)

// GEMM tiling
#define BKK 64
#define LDT 68                 // 64 + 4 pad floats; 272B row stride (ldmatrix-legal, conflict-free)
#define ATILE (128*LDT)        // floats per tile per stage
#define NSTAGE 3
#define GEMM_SMEM (NSTAGE*2*ATILE*4)   // 208896 bytes

// ---------------- scratch ----------------
__device__ float g_resid[ROWS*DM];
__device__ float g_h[ROWS*DM];
__device__ float g_zx[ROWS*DPROJ];
__device__ float g_xbc[ROWS*CONVD];
__device__ float g_dt[ROWS*NH];
__device__ float g_y[ROWS*DI];
__device__ float g_tmp[ROWS*DM];
__device__ float g_ff[ROWS*DM];
__device__ float g_glu[ROWS*DINTER];
__device__ float g_x[ROWS*DM];
__device__ float g_sloc[BATCH*NH*NC*HD*DS];
__device__ float g_hinit[BATCH*NH*NC*HD*DS];
__device__ float g_cdecay[BATCH*NH*NC];
// pre-rounded (tf32) weights
__device__ float g_winw[4*DPROJ*DM];
__device__ float g_wow[4*DM*DI];
__device__ float g_wf1[4*2*DINTER*DM];
__device__ float g_wf2[4*DM*DINTER];

__device__ __forceinline__ float tf32_round(float x) {
    uint32_t u;
    asm("cvt.rna.tf32.f32 %0, %1;" : "=r"(u) : "f"(x));
    return __uint_as_float(u);
}

// ---------------- weight rounding ----------------
__global__ void round_copy(const float* __restrict__ src, float* __restrict__ dst, int n4) {
    int i = blockIdx.x * blockDim.x + threadIdx.x;
    if (i >= n4) return;
    float4 v = ((const float4*)src)[i];
    v.x = tf32_round(v.x); v.y = tf32_round(v.y);
    v.z = tf32_round(v.z); v.w = tf32_round(v.w);
    ((float4*)dst)[i] = v;
}

// ---------------- residual add + LayerNorm ----------------
__global__ void add_ln_kernel(const float* __restrict__ xin, float* __restrict__ resid,
                              const float* __restrict__ w, const float* __restrict__ bch,
                              float* __restrict__ out, int first, int round_out) {
    int row = blockIdx.x;
    const float* xr = xin + (size_t)row * DM;
    float* rr = resid + (size_t)row * DM;
    float* orow = out + (size_t)row * DM;
    int tid = threadIdx.x;   // 128
    float v[4]; float s = 0.f, s2 = 0.f;
#pragma unroll
    for (int j = 0; j < 4; j++) {
        int c = tid + j * 128;
        float val = xr[c];
        if (!first) val += rr[c];
        v[j] = val; s += val; s2 += val * val;
    }
#pragma unroll
    for (int o = 16; o > 0; o >>= 1) {
        s  += __shfl_xor_sync(0xffffffffu, s, o);
        s2 += __shfl_xor_sync(0xffffffffu, s2, o);
    }
    __shared__ float rs[4], rs2[4];
    int wid = tid >> 5;
    if ((tid & 31) == 0) { rs[wid] = s; rs2[wid] = s2; }
    __syncthreads();
    float tot  = rs[0] + rs[1] + rs[2] + rs[3];
    float tot2 = rs2[0] + rs2[1] + rs2[2] + rs2[3];
    float mu = tot * (1.f / DM);
    float var = tot2 * (1.f / DM) - mu * mu;
    float inv = rsqrtf(var + 1e-5f);
#pragma unroll
    for (int j = 0; j < 4; j++) {
        int c = tid + j * 128;
        float val = v[j];
        rr[c] = val;
        float o2 = (val - mu) * inv * w[c] + bch[c];
        orow[c] = round_out ? tf32_round(o2) : o2;
    }
}

// ---------------- pipelined tf32 tensor-core NT GEMM (3-stage) ----------------
#define MMA_TF32(d, a, b) \
    asm volatile("mma.sync.aligned.m16n8k8.row.col.f32.tf32.tf32.f32 " \
                 "{%0,%1,%2,%3},{%4,%5,%6,%7},{%8,%9},{%0,%1,%2,%3};" \
                 : "+f"(d[0]), "+f"(d[1]), "+f"(d[2]), "+f"(d[3]) \
                 : "r"(a[0]), "r"(a[1]), "r"(a[2]), "r"(a[3]), "r"(b[0]), "r"(b[1]))

#define LDSM_X4(R, addr) \
    asm volatile("ldmatrix.sync.aligned.m8n8.x4.shared.b16 {%0,%1,%2,%3}, [%4];" \
                 : "=r"((R)[0]), "=r"((R)[1]), "=r"((R)[2]), "=r"((R)[3]) : "r"(addr))
#define LDSM_X2(R, addr) \
    asm volatile("ldmatrix.sync.aligned.m8n8.x2.shared.b16 {%0,%1}, [%2];" \
                 : "=r"((R)[0]), "=r"((R)[1]) : "r"(addr))

__device__ __forceinline__ void gemm_load_stage(
    const float* __restrict__ A, const float* __restrict__ Bw,
    int K, int N, int bm, int bn, int it, int s, int tid, uint32_t sbase)
{
    uint32_t As_s = sbase + (uint32_t)(s * ATILE) * 4u;
    uint32_t Bs_s = sbase + (uint32_t)((NSTAGE + s) * ATILE) * 4u;
    int k0 = it * BKK;
#pragma unroll
    for (int i = 0; i < 8; i++) {
        int idx = i * 256 + tid;
        int row = idx >> 4;            // 0..127
        int kq  = (idx & 15) << 2;     // 0..60
        uint32_t sa = As_s + (uint32_t)(row * LDT + kq) * 4u;
        const float* gp = A + (size_t)(bm + row) * K + k0 + kq;
        asm volatile("cp.async.cg.shared.global [%0], [%1], 16;" :: "r"(sa), "l"(gp));
        int rb = bn + row;
        int valid = (rb < N);
        const float* gpb = Bw + (size_t)(valid ? rb : 0) * K + k0 + kq;
        uint32_t sb = Bs_s + (uint32_t)(row * LDT + kq) * 4u;
        int ssz = valid ? 16 : 0;
        asm volatile("cp.async.cg.shared.global [%0], [%1], 16, %2;" :: "r"(sb), "l"(gpb), "r"(ssz));
    }
    asm volatile("cp.async.commit_group;" ::: "memory");
}

__global__ void __launch_bounds__(256, 1) tf32_gemm_nt(int M, int N, int K,
                                                       const float* __restrict__ A,
                                                       const float* __restrict__ Bw,
                                                       float* __restrict__ C) {
    extern __shared__ float sm[];
    uint32_t sbase = (uint32_t)__cvta_generic_to_shared(sm);
    int bm = blockIdx.y * 128, bn = blockIdx.x * 128;
    int tid = threadIdx.x;
    int wid = tid >> 5, lane = tid & 31;
    int wm = (wid & 1) * 64;
    int wn = (wid >> 1) * 32;
    int g = lane >> 2, tig = lane & 3;

    int sub = lane >> 3;
    int rA = (lane & 7) + ((sub & 1) << 3);
    int cA = (sub >> 1) << 2;
    int rB = lane & 7;
    int cB = ((lane >> 3) & 1) << 2;
    uint32_t aoff = (uint32_t)((wm + rA) * LDT + cA) * 4u;
    uint32_t boff = (uint32_t)((wn + rB) * LDT + cB) * 4u;

    float acc[4][4][4];
#pragma unroll
    for (int i = 0; i < 4; i++)
#pragma unroll
        for (int j = 0; j < 4; j++)
#pragma unroll
            for (int k = 0; k < 4; k++) acc[i][j][k] = 0.f;

    int NIT = K / BKK;
    gemm_load_stage(A, Bw, K, N, bm, bn, 0, 0, tid, sbase);
    if (NIT > 1) gemm_load_stage(A, Bw, K, N, bm, bn, 1, 1, tid, sbase);
    if (NIT > 2) gemm_load_stage(A, Bw, K, N, bm, bn, 2, 2, tid, sbase);

    for (int it = 0; it < NIT; ++it) {
        int pend = NIT - it - 1;
        if (pend > NSTAGE - 1) pend = NSTAGE - 1;
        if (pend == 2)      asm volatile("cp.async.wait_group 2;" ::: "memory");
        else if (pend == 1) asm volatile("cp.async.wait_group 1;" ::: "memory");
        else                asm volatile("cp.async.wait_group 0;" ::: "memory");
        __syncthreads();
        int s = it % NSTAGE;
        uint32_t Abase = sbase + (uint32_t)(s * ATILE) * 4u + aoff;
        uint32_t Bbase = sbase + (uint32_t)((NSTAGE + s) * ATILE) * 4u + boff;
#pragma unroll
        for (int ks = 0; ks < 8; ks++) {
            int kk = ks * 8;
            uint32_t a[4][4], b[4][2];
#pragma unroll
            for (int mt = 0; mt < 4; mt++)
                LDSM_X4(a[mt], Abase + (uint32_t)(mt * 16 * LDT + kk) * 4u);
#pragma unroll
            for (int nt = 0; nt < 4; nt++)
                LDSM_X2(b[nt], Bbase + (uint32_t)(nt * 8 * LDT + kk) * 4u);
#pragma unroll
            for (int mt = 0; mt < 4; mt++)
#pragma unroll
                for (int nt = 0; nt < 4; nt++)
                    MMA_TF32(acc[mt][nt], a[mt], b[nt]);
        }
        __syncthreads();
        if (it + NSTAGE < NIT) gemm_load_stage(A, Bw, K, N, bm, bn, it + NSTAGE, s, tid, sbase);
    }

#pragma unroll
    for (int mt = 0; mt < 4; mt++) {
        int r0 = bm + wm + mt * 16 + g;
#pragma unroll
        for (int nt = 0; nt < 4; nt++) {
            int c0 = bn + wn + nt * 8 + tig * 2;
            if (c0 < N) {
                float2 v0 = make_float2(acc[mt][nt][0], acc[mt][nt][1]);
                float2 v1 = make_float2(acc[mt][nt][2], acc[mt][nt][3]);
                *(float2*)&C[(size_t)r0 * N + c0] = v0;
                *(float2*)&C[(size_t)(r0 + 8) * N + c0] = v1;
            }
        }
    }
}

// ---------------- dt = softplus(raw + dtb) ----------------
__global__ void dt_kernel(const float* __restrict__ zx, const float* __restrict__ dtb,
                          float* __restrict__ dt) {
    int idx = blockIdx.x * blockDim.x + threadIdx.x;
    if (idx >= ROWS * NH) return;
    int row = idx >> 4; int h = idx & 15;
    float raw = zx[(size_t)row * DPROJ + (DI + CONVD) + h] + dtb[h];
    float d = (raw > 20.f) ? raw : log1pf(expf(raw));
    dt[idx] = d;
}

// ---------------- depthwise causal conv + bias + silu ----------------
__global__ void conv_silu(const float* __restrict__ zx, const float* __restrict__ cw,
                          const float* __restrict__ cb, float* __restrict__ out, int rev) {
    int idx = blockIdx.x * blockDim.x + threadIdx.x;
    if (idx >= ROWS * CONVD) return;
    int c = idx % CONVD; int r = idx / CONVD;
    int b = r / T; int t = r % T;
    const float* w = cw + c * 4;
    const float* col = zx + (size_t)b * T * DPROJ + DI + c;
    float acc = cb[c];
    if (!rev) {
#pragma unroll
        for (int k = 0; k < 4; k++) { int tt = t - 3 + k; if (tt >= 0) acc += w[k] * col[(size_t)tt * DPROJ]; }
    } else {
#pragma unroll
        for (int k = 0; k < 4; k++) { int tt = t + 3 - k; if (tt < T) acc += w[k] * col[(size_t)tt * DPROJ]; }
    }
    out[idx] = acc / (1.f + expf(-acc));
}

// ---------------- chunked SSD scan ----------------
// S1: per-chunk local state  Sloc[p][n] = sum_j exp(Lend-L_j)*dt_j*x_j[p]*B_j[n]
__global__ void __launch_bounds__(256) chunk_state_kernel(
    const float* __restrict__ xbc, const float* __restrict__ dt,
    const float* __restrict__ alog, float* __restrict__ sloc,
    float* __restrict__ cdecay, int rev)
{
    int c = blockIdx.x, head = blockIdx.y, b = blockIdx.z;
    int tid = threadIdx.x;
    __shared__ float Xs[CQ][HD + 4];
    __shared__ float Bs[CQ][DS + 1];
    __shared__ float Ls[CQ];
    __shared__ float wdt[CQ];
    size_t tbase = (size_t)b * T;
    float A = -expf(alog[head]);

    for (int i = tid; i < CQ * HD; i += 256) {
        int j = i >> 6, p = i & 63;
        int s = c * CQ + j;
        int t = rev ? (T - 1 - s) : s;
        Xs[j][p] = xbc[(tbase + t) * CONVD + head * HD + p];
    }
    for (int i = tid; i < CQ * DS; i += 256) {
        int j = i >> 4, n = i & 15;
        int s = c * CQ + j;
        int t = rev ? (T - 1 - s) : s;
        Bs[j][n] = xbc[(tbase + t) * CONVD + DI + n];
    }
    if (tid < CQ) {
        int s = c * CQ + tid;
        int t = rev ? (T - 1 - s) : s;
        float d = dt[(tbase + t) * NH + head];
        wdt[tid] = d;
        Ls[tid] = d * A;
    }
    __syncthreads();
    // inclusive scan of Ls (Hillis-Steele)
    for (int off = 1; off < CQ; off <<= 1) {
        float v = 0.f;
        if (tid < CQ) v = Ls[tid] + ((tid >= off) ? Ls[tid - off] : 0.f);
        __syncthreads();
        if (tid < CQ) Ls[tid] = v;
        __syncthreads();
    }
    float Lend = Ls[CQ - 1];

    int p = tid >> 2, ng = (tid & 3) << 2;
    float acc0 = 0.f, acc1 = 0.f, acc2 = 0.f, acc3 = 0.f;
    for (int j = 0; j < CQ; j++) {
        float w = expf(Lend - Ls[j]) * wdt[j];
        float xv = w * Xs[j][p];
        acc0 += xv * Bs[j][ng + 0];
        acc1 += xv * Bs[j][ng + 1];
        acc2 += xv * Bs[j][ng + 2];
        acc3 += xv * Bs[j][ng + 3];
    }
    size_t o = ((((size_t)b * NH + head) * NC + c) * HD + p) * DS + ng;
    sloc[o + 0] = acc0; sloc[o + 1] = acc1; sloc[o + 2] = acc2; sloc[o + 3] = acc3;
    if (tid == 0) cdecay[((size_t)b * NH + head) * NC + c] = expf(Lend);
}

// S2: serial over chunks, parallel over (b,h) and state elems
__global__ void __launch_bounds__(256) chunk_scan_state(
    const float* __restrict__ sloc, const float* __restrict__ cdecay,
    float* __restrict__ hinit)
{
    int bh = blockIdx.x;
    int tid = threadIdx.x;
    float h0 = 0.f, h1 = 0.f, h2 = 0.f, h3 = 0.f;
    for (int c = 0; c < NC; c++) {
        size_t base = ((size_t)bh * NC + c) * (HD * DS);
        float d = cdecay[(size_t)bh * NC + c];
        size_t i0 = base + tid, i1 = base + tid + 256, i2 = base + tid + 512, i3 = base + tid + 768;
        hinit[i0] = h0; hinit[i1] = h1; hinit[i2] = h2; hinit[i3] = h3;
        h0 = d * h0 + sloc[i0];
        h1 = d * h1 + sloc[i1];
        h2 = d * h2 + sloc[i2];
        h3 = d * h3 + sloc[i3];
    }
}

// S3: per-chunk output  y[t] = S@x + exp(L_t)*C_t.h0 + D*x_t
__global__ void __launch_bounds__(256) chunk_output_kernel(
    const float* __restrict__ xbc, const float* __restrict__ dt,
    const float* __restrict__ alog, const float* __restrict__ hinit,
    const float* __restrict__ Dp, float* __restrict__ y, int rev)
{
    int c = blockIdx.x, head = blockIdx.y, b = blockIdx.z;
    int tid = threadIdx.x;
    __shared__ float Xs[CQ][HD + 4];      // 64x68
    __shared__ float Bs[CQ][DS + 1];
    __shared__ float Cs[CQ][DS + 1];
    __shared__ float h0s[HD][DS + 1];
    __shared__ float Ls[CQ];
    __shared__ float wdt[CQ];
    __shared__ float Ss[CQ][CQ + 1];      // 64x65
    size_t tbase = (size_t)b * T;
    float A = -expf(alog[head]);

    for (int i = tid; i < CQ * HD; i += 256) {
        int j = i >> 6, p = i & 63;
        int s = c * CQ + j;
        int t = rev ? (T - 1 - s) : s;
        Xs[j][p] = xbc[(tbase + t) * CONVD + head * HD + p];
    }
    for (int i = tid; i < CQ * DS; i += 256) {
        int j = i >> 4, n = i & 15;
        int s = c * CQ + j;
        int t = rev ? (T - 1 - s) : s;
        size_t row = (tbase + t) * CONVD + DI;
        Bs[j][n] = xbc[row + n];
        Cs[j][n] = xbc[row + DS + n];
    }
    {
        size_t hb = ((((size_t)b * NH + head) * NC + c) * HD) * DS;
        for (int i = tid; i < HD * DS; i += 256) {
            int p = i >> 4, n = i & 15;
            h0s[p][n] = hinit[hb + i];
        }
    }
    if (tid < CQ) {
        int s = c * CQ + tid;
        int t = rev ? (T - 1 - s) : s;
        float d = dt[(tbase + t) * NH + head];
        wdt[tid] = d;
        Ls[tid] = d * A;
    }
    __syncthreads();
    for (int off = 1; off < CQ; off <<= 1) {
        float v = 0.f;
        if (tid < CQ) v = Ls[tid] + ((tid >= off) ? Ls[tid - off] : 0.f);
        __syncthreads();
        if (tid < CQ) Ls[tid] = v;
        __syncthreads();
    }

    int t = tid >> 2;            // 0..63
    int quad = tid & 3;
    float Ct[DS];
#pragma unroll
    for (int n = 0; n < DS; n++) Ct[n] = Cs[t][n];
    float Lt = Ls[t];

    // scores: this thread fills S[t][quad*16 .. quad*16+15]
    int jb = quad * 16;
#pragma unroll
    for (int q = 0; q < 16; q++) {
        int j = jb + q;
        float sv = 0.f;
        if (j <= t) {
            float dot = 0.f;
#pragma unroll
            for (int n = 0; n < DS; n++) dot += Ct[n] * Bs[j][n];
            sv = expf(Lt - Ls[j]) * wdt[j] * dot;
        }
        Ss[t][j] = sv;
    }
    __syncthreads();

    // Y = S @ X (+ state + D*x); this thread covers p in [pb, pb+16)
    int pb = quad * 16;
    float acc[16];
#pragma unroll
    for (int k = 0; k < 16; k++) acc[k] = 0.f;
    for (int j = 0; j <= t; j++) {
        float sv = Ss[t][j];
#pragma unroll
        for (int k4 = 0; k4 < 4; k4++) {
            float4 xv = *(const float4*)&Xs[j][pb + k4 * 4];
            acc[k4 * 4 + 0] += sv * xv.x;
            acc[k4 * 4 + 1] += sv * xv.y;
            acc[k4 * 4 + 2] += sv * xv.z;
            acc[k4 * 4 + 3] += sv * xv.w;
        }
    }
    float et = expf(Lt);
    float Dv = Dp[head];
#pragma unroll
    for (int k = 0; k < 16; k++) {
        int p = pb + k;
        float dot = 0.f;
#pragma unroll
        for (int n = 0; n < DS; n++) dot += Ct[n] * h0s[p][n];
        acc[k] += et * dot + Dv * Xs[t][p];
    }
    int s_idx = c * CQ + t;
    int trow = rev ? (T - 1 - s_idx) : s_idx;
    float* yr = y + (tbase + trow) * DI + head * HD + pb;
#pragma unroll
    for (int k4 = 0; k4 < 4; k4++) {
        float4 v = make_float4(acc[k4 * 4 + 0], acc[k4 * 4 + 1], acc[k4 * 4 + 2], acc[k4 * 4 + 3]);
        *(float4*)(yr + k4 * 4) = v;
    }
}

// ---------------- y = y * silu(z); RMSNorm(y) * gw (tf32-rounded) ----------------
__global__ void gate_rms(const float* __restrict__ zx, float* __restrict__ y,
                         const float* __restrict__ gw) {
    int row = blockIdx.x;
    const float* z = zx + (size_t)row * DPROJ;
    float* yr = y + (size_t)row * DI;
    int tid = threadIdx.x;  // 256
    float v[4]; float s2 = 0.f;
#pragma unroll
    for (int j = 0; j < 4; j++) {
        int c = tid + j * 256;
        float zz = z[c];
        float val = yr[c] * (zz / (1.f + expf(-zz)));
        v[j] = val; s2 += val * val;
    }
#pragma unroll
    for (int o = 16; o > 0; o >>= 1) s2 += __shfl_xor_sync(0xffffffffu, s2, o);
    __shared__ float rs[8];
    int wid = tid >> 5;
    if ((tid & 31) == 0) rs[wid] = s2;
    __syncthreads();
    float tot = 0.f;
#pragma unroll
    for (int i = 0; i < 8; i++) tot += rs[i];
    float inv = rsqrtf(tot * (1.f / DI) + 1e-5f);
#pragma unroll
    for (int j = 0; j < 4; j++) {
        int c = tid + j * 256;
        yr[c] = tf32_round(v[j] * inv * gw[c]);
    }
}

// ---------------- GLU ----------------
__global__ void glu_kernel(const float* __restrict__ ff, float* __restrict__ out) {
    int idx = blockIdx.x * blockDim.x + threadIdx.x;
    if (idx >= ROWS * DINTER) return;
    int row = idx >> 8; int j = idx & 255;
    float a = ff[(size_t)row * DM + j];
    float g = ff[(size_t)row * DM + DINTER + j];
    out[idx] = tf32_round(a * g / (1.f + expf(-g)));
}

// ---------------- host ----------------
static float* sym_addr(const void* sym) {
    void* p = nullptr;
    cudaGetSymbolAddress(&p, sym);
    return (float*)p;
}

extern "C" void kernel_launch(void* const* d_in, const int* in_sizes, int n_in,
                              void* d_out, int out_size) {
    const float* in_x   = (const float*)d_in[0];
    const float* n1w    = (const float*)d_in[1];
    const float* n1b    = (const float*)d_in[2];
    const float* inw    = (const float*)d_in[3];
    const float* cw     = (const float*)d_in[4];
    const float* cb     = (const float*)d_in[5];
    const float* dtb    = (const float*)d_in[6];
    const float* alog   = (const float*)d_in[7];
    const float* Dp     = (const float*)d_in[8];
    const float* gw     = (const float*)d_in[9];
    const float* ow     = (const float*)d_in[10];
    const float* n2w    = (const float*)d_in[11];
    const float* n2b    = (const float*)d_in[12];
    const float* f1w    = (const float*)d_in[13];
    const float* f2w    = (const float*)d_in[14];
    const float* nfw    = (const float*)d_in[15];
    const float* nfb    = (const float*)d_in[16];

    float* resid = sym_addr(g_resid);
    float* zx    = sym_addr(g_zx);
    float* xbc   = sym_addr(g_xbc);
    float* dtg   = sym_addr(g_dt);
    float* ybuf  = sym_addr(g_y);
    float* tmp   = sym_addr(g_tmp);
    float* ffb   = sym_addr(g_ff);
    float* glub  = sym_addr(g_glu);
    float* xb    = sym_addr(g_x);
    float* hbuf  = sym_addr(g_h);
    float* sloc  = sym_addr(g_sloc);
    float* hinit = sym_addr(g_hinit);
    float* cdec  = sym_addr(g_cdecay);
    float* winw  = sym_addr(g_winw);
    float* wow   = sym_addr(g_wow);
    float* wf1   = sym_addr(g_wf1);
    float* wf2   = sym_addr(g_wf2);

    static int smem_set = 0;
    if (!smem_set) {
        cudaFuncSetAttribute(tf32_gemm_nt, cudaFuncAttributeMaxDynamicSharedMemorySize, GEMM_SMEM);
        smem_set = 1;
    }

    // pre-round weights to tf32
    {
        int n;
        n = 4 * DPROJ * DM / 4;      round_copy<<<(n + 255) / 256, 256>>>(inw, winw, n);
        n = 4 * DM * DI / 4;         round_copy<<<(n + 255) / 256, 256>>>(ow, wow, n);
        n = 4 * 2 * DINTER * DM / 4; round_copy<<<(n + 255) / 256, 256>>>(f1w, wf1, n);
        n = 4 * DM * DINTER / 4;     round_copy<<<(n + 255) / 256, 256>>>(f2w, wf2, n);
    }

    for (int i = 0; i < 4; i++) {
        int rev = i & 1;
        const float* xin = (i == 0) ? in_x : xb;

        add_ln_kernel<<<ROWS, 128>>>(xin, resid, n1w + i * DM, n1b + i * DM, hbuf, (i == 0) ? 1 : 0, 1);

        {
            dim3 grid((DPROJ + 127) / 128, ROWS / 128);
            tf32_gemm_nt<<<grid, 256, GEMM_SMEM>>>(ROWS, DPROJ, DM, hbuf, winw + (size_t)i * DPROJ * DM, zx);
        }

        dt_kernel<<<(ROWS * NH + 255) / 256, 256>>>(zx, dtb + i * NH, dtg);

        conv_silu<<<(ROWS * CONVD + 255) / 256, 256>>>(zx, cw + (size_t)i * CONVD * 4, cb + i * CONVD, xbc, rev);

        // chunked scan: S1 -> S2 -> S3
        {
            dim3 gs(NC, NH, BATCH);
            chunk_state_kernel<<<gs, 256>>>(xbc, dtg, alog + i * NH, sloc, cdec, rev);
            chunk_scan_state<<<BATCH * NH, 256>>>(sloc, cdec, hinit);
            chunk_output_kernel<<<gs, 256>>>(xbc, dtg, alog + i * NH, hinit, Dp + i * NH, ybuf, rev);
        }

        gate_rms<<<ROWS, 256>>>(zx, ybuf, gw + i * DI);

        {
            dim3 grid(DM / 128, ROWS / 128);
            tf32_gemm_nt<<<grid, 256, GEMM_SMEM>>>(ROWS, DM, DI, ybuf, wow + (size_t)i * DM * DI, tmp);
        }

        add_ln_kernel<<<ROWS, 128>>>(tmp, resid, n2w + i * DM, n2b + i * DM, hbuf, 0, 1);

        {
            dim3 grid(DM / 128, ROWS / 128);
            tf32_gemm_nt<<<grid, 256, GEMM_SMEM>>>(ROWS, DM, DM, hbuf, wf1 + (size_t)i * DM * DM, ffb);
        }

        glu_kernel<<<(ROWS * DINTER + 255) / 256, 256>>>(ffb, glub);

        {
            dim3 grid(DM / 128, ROWS / 128);
            tf32_gemm_nt<<<grid, 256, GEMM_SMEM>>>(ROWS, DM, DINTER, glub, wf2 + (size_t)i * DM * DINTER, xb);
        }
    }

    add_ln_kernel<<<ROWS, 128>>>(xb, resid, nfw, nfb, (float*)d_out, 0, 0);
}

// round 6
// speedup vs baseline: 4.9774x; 1.1085x over previous
#include <cuda_runtime.h>
#include <math.h>
#include <stdint.h>

#define BATCH 4
#define T 2048
#define DM 512
#define DI 1024
#define NH 16
#define HD 64
#define DS 16
#define CONVD 1056
#define DPROJ 2096
#define DINTER 256
#define ROWS (BATCH*T)

// chunked scan
#define CQ 64
#define NC (T/CQ)

// GEMM tiling: block 128(M) x 256(N), BK=64, 2 stages
#define BKK 64
#define LDT 68
#define ATILE_A (128*LDT)
#define ATILE_B (256*LDT)
#define GEMM_SMEM ((2*ATILE_A + 2*ATILE_B)*4)   // 208896 bytes

// ---------------- scratch ----------------
__device__ float g_resid[ROWS*DM];
__device__ float g_h[ROWS*DM];
__device__ float g_zx[ROWS*DPROJ];
__device__ float g_xbc[ROWS*CONVD];
__device__ float g_dt[ROWS*NH];
__device__ float g_y[ROWS*DI];
__device__ float g_tmp[ROWS*DM];
__device__ float g_glu[ROWS*DINTER];
__device__ float g_x[ROWS*DM];
__device__ float g_sloc[BATCH*NH*NC*HD*DS];
__device__ float g_hinit[BATCH*NH*NC*HD*DS];
__device__ float g_cdecay[BATCH*NH*NC];
// pre-rounded (tf32) weights
__device__ float g_winw[4*DPROJ*DM];
__device__ float g_wow[4*DM*DI];
__device__ float g_wf1[4*2*DINTER*DM];   // row-interleaved (a,g pairs)
__device__ float g_wf2[4*DM*DINTER];

__device__ __forceinline__ float tf32_round(float x) {
    uint32_t u;
    asm("cvt.rna.tf32.f32 %0, %1;" : "=r"(u) : "f"(x));
    return __uint_as_float(u);
}

// ---------------- weight rounding ----------------
__global__ void round_copy(const float* __restrict__ src, float* __restrict__ dst, int n4) {
    int i = blockIdx.x * blockDim.x + threadIdx.x;
    if (i >= n4) return;
    float4 v = ((const float4*)src)[i];
    v.x = tf32_round(v.x); v.y = tf32_round(v.y);
    v.z = tf32_round(v.z); v.w = tf32_round(v.w);
    ((float4*)dst)[i] = v;
}

// f1 weights: round + interleave rows so (a_j, g_j) become adjacent output cols (2j, 2j+1)
__global__ void round_interleave_f1(const float* __restrict__ src, float* __restrict__ dst) {
    // src: [4][512][512]; dst row within layer: r<256 -> 2r, else 2(r-256)+1
    int i = blockIdx.x * blockDim.x + threadIdx.x;   // float4 index
    int total4 = 4 * 512 * 512 / 4;
    if (i >= total4) return;
    int k4 = i & 127;            // 512/4 float4 per row
    int row = (i >> 7) & 511;
    int l = i >> 16;             // 128*512 float4 per layer
    float4 v = ((const float4*)src)[i];
    v.x = tf32_round(v.x); v.y = tf32_round(v.y);
    v.z = tf32_round(v.z); v.w = tf32_round(v.w);
    int drow = (row < 256) ? (2 * row) : (2 * (row - 256) + 1);
    ((float4*)dst)[((size_t)l * 512 + drow) * 128 + k4] = v;
}

// ---------------- residual add + LayerNorm ----------------
__global__ void add_ln_kernel(const float* __restrict__ xin, float* __restrict__ resid,
                              const float* __restrict__ w, const float* __restrict__ bch,
                              float* __restrict__ out, int first, int round_out) {
    int row = blockIdx.x;
    const float* xr = xin + (size_t)row * DM;
    float* rr = resid + (size_t)row * DM;
    float* orow = out + (size_t)row * DM;
    int tid = threadIdx.x;   // 128
    float v[4]; float s = 0.f, s2 = 0.f;
#pragma unroll
    for (int j = 0; j < 4; j++) {
        int c = tid + j * 128;
        float val = xr[c];
        if (!first) val += rr[c];
        v[j] = val; s += val; s2 += val * val;
    }
#pragma unroll
    for (int o = 16; o > 0; o >>= 1) {
        s  += __shfl_xor_sync(0xffffffffu, s, o);
        s2 += __shfl_xor_sync(0xffffffffu, s2, o);
    }
    __shared__ float rs[4], rs2[4];
    int wid = tid >> 5;
    if ((tid & 31) == 0) { rs[wid] = s; rs2[wid] = s2; }
    __syncthreads();
    float tot  = rs[0] + rs[1] + rs[2] + rs[3];
    float tot2 = rs2[0] + rs2[1] + rs2[2] + rs2[3];
    float mu = tot * (1.f / DM);
    float var = tot2 * (1.f / DM) - mu * mu;
    float inv = rsqrtf(var + 1e-5f);
#pragma unroll
    for (int j = 0; j < 4; j++) {
        int c = tid + j * 128;
        float val = v[j];
        rr[c] = val;
        float o2 = (val - mu) * inv * w[c] + bch[c];
        orow[c] = round_out ? tf32_round(o2) : o2;
    }
}

// ---------------- tf32 tensor-core NT GEMM (128x256 block, 2-stage) ----------------
#define MMA_TF32(d, a, b) \
    asm volatile("mma.sync.aligned.m16n8k8.row.col.f32.tf32.tf32.f32 " \
                 "{%0,%1,%2,%3},{%4,%5,%6,%7},{%8,%9},{%0,%1,%2,%3};" \
                 : "+f"(d[0]), "+f"(d[1]), "+f"(d[2]), "+f"(d[3]) \
                 : "r"(a[0]), "r"(a[1]), "r"(a[2]), "r"(a[3]), "r"(b[0]), "r"(b[1]))

#define LDSM_X4(R, addr) \
    asm volatile("ldmatrix.sync.aligned.m8n8.x4.shared.b16 {%0,%1,%2,%3}, [%4];" \
                 : "=r"((R)[0]), "=r"((R)[1]), "=r"((R)[2]), "=r"((R)[3]) : "r"(addr))
#define LDSM_X2(R, addr) \
    asm volatile("ldmatrix.sync.aligned.m8n8.x2.shared.b16 {%0,%1}, [%2];" \
                 : "=r"((R)[0]), "=r"((R)[1]) : "r"(addr))

__device__ __forceinline__ void gemm_load_stage(
    const float* __restrict__ A, const float* __restrict__ Bw,
    int K, int N, int bm, int bn, int it, int s, int tid, uint32_t sbase)
{
    uint32_t As_s = sbase + (uint32_t)(s * ATILE_A) * 4u;
    uint32_t Bs_s = sbase + (uint32_t)(2 * ATILE_A + s * ATILE_B) * 4u;
    int k0 = it * BKK;
#pragma unroll
    for (int i = 0; i < 8; i++) {
        int idx = i * 256 + tid;
        int row = idx >> 4;
        int kq  = (idx & 15) << 2;
        uint32_t sa = As_s + (uint32_t)(row * LDT + kq) * 4u;
        const float* gp = A + (size_t)(bm + row) * K + k0 + kq;
        asm volatile("cp.async.cg.shared.global [%0], [%1], 16;" :: "r"(sa), "l"(gp));
    }
#pragma unroll
    for (int i = 0; i < 16; i++) {
        int idx = i * 256 + tid;
        int row = idx >> 4;
        int kq  = (idx & 15) << 2;
        int rb = bn + row;
        int valid = (rb < N);
        const float* gpb = Bw + (size_t)(valid ? rb : 0) * K + k0 + kq;
        uint32_t sb = Bs_s + (uint32_t)(row * LDT + kq) * 4u;
        int ssz = valid ? 16 : 0;
        asm volatile("cp.async.cg.shared.global [%0], [%1], 16, %2;" :: "r"(sb), "l"(gpb), "r"(ssz));
    }
    asm volatile("cp.async.commit_group;" ::: "memory");
}

// fuse_glu: N is the (interleaved) GEMM width; output written as a*silu(g) to N/2 cols.
__global__ void __launch_bounds__(256) tf32_gemm_nt(int M, int N, int K,
                                                    const float* __restrict__ A,
                                                    const float* __restrict__ Bw,
                                                    float* __restrict__ C, int fuse_glu) {
    extern __shared__ float sm[];
    uint32_t sbase = (uint32_t)__cvta_generic_to_shared(sm);
    int bm = blockIdx.y * 128, bn = blockIdx.x * 256;
    int tid = threadIdx.x;
    int wid = tid >> 5, lane = tid & 31;
    int wm = (wid & 1) * 64;
    int wn = (wid >> 1) * 64;
    int g = lane >> 2, tig = lane & 3;

    int sub = lane >> 3;
    int rA = (lane & 7) + ((sub & 1) << 3);
    int cA = (sub >> 1) << 2;
    int rB = lane & 7;
    int cB = ((lane >> 3) & 1) << 2;
    uint32_t aoff = (uint32_t)((wm + rA) * LDT + cA) * 4u;
    uint32_t boff = (uint32_t)((wn + rB) * LDT + cB) * 4u;

    float acc[4][8][4];
#pragma unroll
    for (int i = 0; i < 4; i++)
#pragma unroll
        for (int j = 0; j < 8; j++)
#pragma unroll
            for (int k = 0; k < 4; k++) acc[i][j][k] = 0.f;

    int NIT = K / BKK;
    gemm_load_stage(A, Bw, K, N, bm, bn, 0, 0, tid, sbase);
    if (NIT > 1) gemm_load_stage(A, Bw, K, N, bm, bn, 1, 1, tid, sbase);

    for (int it = 0; it < NIT; ++it) {
        if (it < NIT - 1) asm volatile("cp.async.wait_group 1;" ::: "memory");
        else              asm volatile("cp.async.wait_group 0;" ::: "memory");
        __syncthreads();
        int s = it & 1;
        uint32_t Abase = sbase + (uint32_t)(s * ATILE_A) * 4u + aoff;
        uint32_t Bbase = sbase + (uint32_t)(2 * ATILE_A + s * ATILE_B) * 4u + boff;
#pragma unroll
        for (int ks = 0; ks < 8; ks++) {
            int kk = ks * 8;
            uint32_t a[4][4], b[8][2];
#pragma unroll
            for (int mt = 0; mt < 4; mt++)
                LDSM_X4(a[mt], Abase + (uint32_t)(mt * 16 * LDT + kk) * 4u);
#pragma unroll
            for (int nt = 0; nt < 8; nt++)
                LDSM_X2(b[nt], Bbase + (uint32_t)(nt * 8 * LDT + kk) * 4u);
#pragma unroll
            for (int mt = 0; mt < 4; mt++)
#pragma unroll
                for (int nt = 0; nt < 8; nt++)
                    MMA_TF32(acc[mt][nt], a[mt], b[nt]);
        }
        __syncthreads();
        if (it + 2 < NIT) gemm_load_stage(A, Bw, K, N, bm, bn, it + 2, s, tid, sbase);
    }

    if (!fuse_glu) {
#pragma unroll
        for (int mt = 0; mt < 4; mt++) {
            int r0 = bm + wm + mt * 16 + g;
#pragma unroll
            for (int nt = 0; nt < 8; nt++) {
                int c0 = bn + wn + nt * 8 + tig * 2;
                if (c0 < N) {
                    *(float2*)&C[(size_t)r0 * N + c0] = make_float2(acc[mt][nt][0], acc[mt][nt][1]);
                    *(float2*)&C[(size_t)(r0 + 8) * N + c0] = make_float2(acc[mt][nt][2], acc[mt][nt][3]);
                }
            }
        }
    } else {
        int No = N >> 1;
#pragma unroll
        for (int mt = 0; mt < 4; mt++) {
            int r0 = bm + wm + mt * 16 + g;
#pragma unroll
            for (int nt = 0; nt < 8; nt++) {
                int c0 = bn + wn + nt * 8 + tig * 2;   // always even
                if (c0 < N) {
                    float a0 = acc[mt][nt][0], g0 = acc[mt][nt][1];
                    float a1 = acc[mt][nt][2], g1 = acc[mt][nt][3];
                    C[(size_t)r0 * No + (c0 >> 1)] = tf32_round(a0 * g0 / (1.f + expf(-g0)));
                    C[(size_t)(r0 + 8) * No + (c0 >> 1)] = tf32_round(a1 * g1 / (1.f + expf(-g1)));
                }
            }
        }
    }
}

// ---------------- dt = softplus(raw + dtb) ----------------
__global__ void dt_kernel(const float* __restrict__ zx, const float* __restrict__ dtb,
                          float* __restrict__ dt) {
    int idx = blockIdx.x * blockDim.x + threadIdx.x;
    if (idx >= ROWS * NH) return;
    int row = idx >> 4; int h = idx & 15;
    float raw = zx[(size_t)row * DPROJ + (DI + CONVD) + h] + dtb[h];
    float d = (raw > 20.f) ? raw : log1pf(expf(raw));
    dt[idx] = d;
}

// ---------------- depthwise causal conv: 4 t-steps per thread ----------------
__global__ void conv_silu(const float* __restrict__ zx, const float* __restrict__ cw,
                          const float* __restrict__ cb, float* __restrict__ out, int rev) {
    int idx = blockIdx.x * blockDim.x + threadIdx.x;
    if (idx >= (ROWS / 4) * CONVD) return;
    int c = idx % CONVD; int tt = idx / CONVD;
    int b = tt / (T / 4); int t0 = (tt % (T / 4)) * 4;
    const float* w = cw + c * 4;
    const float* col = zx + (size_t)b * T * DPROJ + DI + c;
    float bias = cb[c];
    float win[7];
    if (!rev) {
#pragma unroll
        for (int j = 0; j < 7; j++) {
            int t = t0 - 3 + j;
            win[j] = (t >= 0) ? col[(size_t)t * DPROJ] : 0.f;
        }
#pragma unroll
        for (int i = 0; i < 4; i++) {
            float acc = bias;
#pragma unroll
            for (int k = 0; k < 4; k++) acc += w[k] * win[i + k];
            float o = acc / (1.f + expf(-acc));
            out[((size_t)b * T + t0 + i) * CONVD + c] = o;
        }
    } else {
#pragma unroll
        for (int j = 0; j < 7; j++) {
            int t = t0 + j;
            win[j] = (t < T) ? col[(size_t)t * DPROJ] : 0.f;
        }
#pragma unroll
        for (int i = 0; i < 4; i++) {
            float acc = bias;
#pragma unroll
            for (int k = 0; k < 4; k++) acc += w[k] * win[i + 3 - k];
            float o = acc / (1.f + expf(-acc));
            out[((size_t)b * T + t0 + i) * CONVD + c] = o;
        }
    }
}

// ---------------- chunked SSD scan ----------------
__global__ void __launch_bounds__(256) chunk_state_kernel(
    const float* __restrict__ xbc, const float* __restrict__ dt,
    const float* __restrict__ alog, float* __restrict__ sloc,
    float* __restrict__ cdecay, int rev)
{
    int c = blockIdx.x, head = blockIdx.y, b = blockIdx.z;
    int tid = threadIdx.x;
    __shared__ float Xs[CQ][HD + 4];
    __shared__ float Bs[CQ][DS + 1];
    __shared__ float Ls[CQ];
    __shared__ float wdt[CQ];
    size_t tbase = (size_t)b * T;
    float A = -expf(alog[head]);

    for (int i = tid; i < CQ * HD; i += 256) {
        int j = i >> 6, p = i & 63;
        int s = c * CQ + j;
        int t = rev ? (T - 1 - s) : s;
        Xs[j][p] = xbc[(tbase + t) * CONVD + head * HD + p];
    }
    for (int i = tid; i < CQ * DS; i += 256) {
        int j = i >> 4, n = i & 15;
        int s = c * CQ + j;
        int t = rev ? (T - 1 - s) : s;
        Bs[j][n] = xbc[(tbase + t) * CONVD + DI + n];
    }
    if (tid < CQ) {
        int s = c * CQ + tid;
        int t = rev ? (T - 1 - s) : s;
        float d = dt[(tbase + t) * NH + head];
        wdt[tid] = d;
        Ls[tid] = d * A;
    }
    __syncthreads();
    for (int off = 1; off < CQ; off <<= 1) {
        float v = 0.f;
        if (tid < CQ) v = Ls[tid] + ((tid >= off) ? Ls[tid - off] : 0.f);
        __syncthreads();
        if (tid < CQ) Ls[tid] = v;
        __syncthreads();
    }
    float Lend = Ls[CQ - 1];

    int p = tid >> 2, ng = (tid & 3) << 2;
    float acc0 = 0.f, acc1 = 0.f, acc2 = 0.f, acc3 = 0.f;
    for (int j = 0; j < CQ; j++) {
        float w = expf(Lend - Ls[j]) * wdt[j];
        float xv = w * Xs[j][p];
        acc0 += xv * Bs[j][ng + 0];
        acc1 += xv * Bs[j][ng + 1];
        acc2 += xv * Bs[j][ng + 2];
        acc3 += xv * Bs[j][ng + 3];
    }
    size_t o = ((((size_t)b * NH + head) * NC + c) * HD + p) * DS + ng;
    sloc[o + 0] = acc0; sloc[o + 1] = acc1; sloc[o + 2] = acc2; sloc[o + 3] = acc3;
    if (tid == 0) cdecay[((size_t)b * NH + head) * NC + c] = expf(Lend);
}

__global__ void __launch_bounds__(256) chunk_scan_state(
    const float* __restrict__ sloc, const float* __restrict__ cdecay,
    float* __restrict__ hinit)
{
    int bh = blockIdx.x;
    int tid = threadIdx.x;
    float h0 = 0.f, h1 = 0.f, h2 = 0.f, h3 = 0.f;
    for (int c = 0; c < NC; c++) {
        size_t base = ((size_t)bh * NC + c) * (HD * DS);
        float d = cdecay[(size_t)bh * NC + c];
        size_t i0 = base + tid, i1 = base + tid + 256, i2 = base + tid + 512, i3 = base + tid + 768;
        hinit[i0] = h0; hinit[i1] = h1; hinit[i2] = h2; hinit[i3] = h3;
        h0 = d * h0 + sloc[i0];
        h1 = d * h1 + sloc[i1];
        h2 = d * h2 + sloc[i2];
        h3 = d * h3 + sloc[i3];
    }
}

__global__ void __launch_bounds__(256) chunk_output_kernel(
    const float* __restrict__ xbc, const float* __restrict__ dt,
    const float* __restrict__ alog, const float* __restrict__ hinit,
    const float* __restrict__ Dp, float* __restrict__ y, int rev)
{
    int c = blockIdx.x, head = blockIdx.y, b = blockIdx.z;
    int tid = threadIdx.x;
    __shared__ float Xs[CQ][HD + 4];
    __shared__ float Bs[CQ][DS + 1];
    __shared__ float Cs[CQ][DS + 1];
    __shared__ float h0s[HD][DS + 1];
    __shared__ float Ls[CQ];
    __shared__ float wdt[CQ];
    __shared__ float Ss[CQ][CQ + 1];
    size_t tbase = (size_t)b * T;
    float A = -expf(alog[head]);

    for (int i = tid; i < CQ * HD; i += 256) {
        int j = i >> 6, p = i & 63;
        int s = c * CQ + j;
        int t = rev ? (T - 1 - s) : s;
        Xs[j][p] = xbc[(tbase + t) * CONVD + head * HD + p];
    }
    for (int i = tid; i < CQ * DS; i += 256) {
        int j = i >> 4, n = i & 15;
        int s = c * CQ + j;
        int t = rev ? (T - 1 - s) : s;
        size_t row = (tbase + t) * CONVD + DI;
        Bs[j][n] = xbc[row + n];
        Cs[j][n] = xbc[row + DS + n];
    }
    {
        size_t hb = ((((size_t)b * NH + head) * NC + c) * HD) * DS;
        for (int i = tid; i < HD * DS; i += 256) {
            int p = i >> 4, n = i & 15;
            h0s[p][n] = hinit[hb + i];
        }
    }
    if (tid < CQ) {
        int s = c * CQ + tid;
        int t = rev ? (T - 1 - s) : s;
        float d = dt[(tbase + t) * NH + head];
        wdt[tid] = d;
        Ls[tid] = d * A;
    }
    __syncthreads();
    for (int off = 1; off < CQ; off <<= 1) {
        float v = 0.f;
        if (tid < CQ) v = Ls[tid] + ((tid >= off) ? Ls[tid - off] : 0.f);
        __syncthreads();
        if (tid < CQ) Ls[tid] = v;
        __syncthreads();
    }

    int t = tid >> 2;
    int quad = tid & 3;
    float Ct[DS];
#pragma unroll
    for (int n = 0; n < DS; n++) Ct[n] = Cs[t][n];
    float Lt = Ls[t];

    int jb = quad * 16;
#pragma unroll
    for (int q = 0; q < 16; q++) {
        int j = jb + q;
        float sv = 0.f;
        if (j <= t) {
            float dot = 0.f;
#pragma unroll
            for (int n = 0; n < DS; n++) dot += Ct[n] * Bs[j][n];
            sv = expf(Lt - Ls[j]) * wdt[j] * dot;
        }
        Ss[t][j] = sv;
    }
    __syncthreads();

    int pb = quad * 16;
    float acc[16];
#pragma unroll
    for (int k = 0; k < 16; k++) acc[k] = 0.f;
    for (int j = 0; j <= t; j++) {
        float sv = Ss[t][j];
#pragma unroll
        for (int k4 = 0; k4 < 4; k4++) {
            float4 xv = *(const float4*)&Xs[j][pb + k4 * 4];
            acc[k4 * 4 + 0] += sv * xv.x;
            acc[k4 * 4 + 1] += sv * xv.y;
            acc[k4 * 4 + 2] += sv * xv.z;
            acc[k4 * 4 + 3] += sv * xv.w;
        }
    }
    float et = expf(Lt);
    float Dv = Dp[head];
#pragma unroll
    for (int k = 0; k < 16; k++) {
        int p = pb + k;
        float dot = 0.f;
#pragma unroll
        for (int n = 0; n < DS; n++) dot += Ct[n] * h0s[p][n];
        acc[k] += et * dot + Dv * Xs[t][p];
    }
    int s_idx = c * CQ + t;
    int trow = rev ? (T - 1 - s_idx) : s_idx;
    float* yr = y + (tbase + trow) * DI + head * HD + pb;
#pragma unroll
    for (int k4 = 0; k4 < 4; k4++) {
        *(float4*)(yr + k4 * 4) = make_float4(acc[k4 * 4 + 0], acc[k4 * 4 + 1], acc[k4 * 4 + 2], acc[k4 * 4 + 3]);
    }
}

// ---------------- y = y * silu(z); RMSNorm(y) * gw (tf32-rounded) ----------------
__global__ void gate_rms(const float* __restrict__ zx, float* __restrict__ y,
                         const float* __restrict__ gw) {
    int row = blockIdx.x;
    const float* z = zx + (size_t)row * DPROJ;
    float* yr = y + (size_t)row * DI;
    int tid = threadIdx.x;  // 256
    float v[4]; float s2 = 0.f;
#pragma unroll
    for (int j = 0; j < 4; j++) {
        int c = tid + j * 256;
        float zz = z[c];
        float val = yr[c] * (zz / (1.f + expf(-zz)));
        v[j] = val; s2 += val * val;
    }
#pragma unroll
    for (int o = 16; o > 0; o >>= 1) s2 += __shfl_xor_sync(0xffffffffu, s2, o);
    __shared__ float rs[8];
    int wid = tid >> 5;
    if ((tid & 31) == 0) rs[wid] = s2;
    __syncthreads();
    float tot = 0.f;
#pragma unroll
    for (int i = 0; i < 8; i++) tot += rs[i];
    float inv = rsqrtf(tot * (1.f / DI) + 1e-5f);
#pragma unroll
    for (int j = 0; j < 4; j++) {
        int c = tid + j * 256;
        yr[c] = tf32_round(v[j] * inv * gw[c]);
    }
}

// ---------------- host ----------------
static float* sym_addr(const void* sym) {
    void* p = nullptr;
    cudaGetSymbolAddress(&p, sym);
    return (float*)p;
}

extern "C" void kernel_launch(void* const* d_in, const int* in_sizes, int n_in,
                              void* d_out, int out_size) {
    const float* in_x   = (const float*)d_in[0];
    const float* n1w    = (const float*)d_in[1];
    const float* n1b    = (const float*)d_in[2];
    const float* inw    = (const float*)d_in[3];
    const float* cw     = (const float*)d_in[4];
    const float* cb     = (const float*)d_in[5];
    const float* dtb    = (const float*)d_in[6];
    const float* alog   = (const float*)d_in[7];
    const float* Dp     = (const float*)d_in[8];
    const float* gw     = (const float*)d_in[9];
    const float* ow     = (const float*)d_in[10];
    const float* n2w    = (const float*)d_in[11];
    const float* n2b    = (const float*)d_in[12];
    const float* f1w    = (const float*)d_in[13];
    const float* f2w    = (const float*)d_in[14];
    const float* nfw    = (const float*)d_in[15];
    const float* nfb    = (const float*)d_in[16];

    float* resid = sym_addr(g_resid);
    float* zx    = sym_addr(g_zx);
    float* xbc   = sym_addr(g_xbc);
    float* dtg   = sym_addr(g_dt);
    float* ybuf  = sym_addr(g_y);
    float* tmp   = sym_addr(g_tmp);
    float* glub  = sym_addr(g_glu);
    float* xb    = sym_addr(g_x);
    float* hbuf  = sym_addr(g_h);
    float* sloc  = sym_addr(g_sloc);
    float* hinit = sym_addr(g_hinit);
    float* cdec  = sym_addr(g_cdecay);
    float* winw  = sym_addr(g_winw);
    float* wow   = sym_addr(g_wow);
    float* wf1   = sym_addr(g_wf1);
    float* wf2   = sym_addr(g_wf2);

    static int smem_set = 0;
    if (!smem_set) {
        cudaFuncSetAttribute(tf32_gemm_nt, cudaFuncAttributeMaxDynamicSharedMemorySize, GEMM_SMEM);
        smem_set = 1;
    }

    // pre-round weights to tf32 (f1 also row-interleaved for fused GLU)
    {
        int n;
        n = 4 * DPROJ * DM / 4;      round_copy<<<(n + 255) / 256, 256>>>(inw, winw, n);
        n = 4 * DM * DI / 4;         round_copy<<<(n + 255) / 256, 256>>>(ow, wow, n);
        n = 4 * 2 * DINTER * DM / 4; round_interleave_f1<<<(n + 255) / 256, 256>>>(f1w, wf1);
        n = 4 * DM * DINTER / 4;     round_copy<<<(n + 255) / 256, 256>>>(f2w, wf2, n);
    }

    for (int i = 0; i < 4; i++) {
        int rev = i & 1;
        const float* xin = (i == 0) ? in_x : xb;

        add_ln_kernel<<<ROWS, 128>>>(xin, resid, n1w + i * DM, n1b + i * DM, hbuf, (i == 0) ? 1 : 0, 1);

        {   // in_proj [8192 x 2096 x 512]
            dim3 grid((DPROJ + 255) / 256, ROWS / 128);
            tf32_gemm_nt<<<grid, 256, GEMM_SMEM>>>(ROWS, DPROJ, DM, hbuf, winw + (size_t)i * DPROJ * DM, zx, 0);
        }

        dt_kernel<<<(ROWS * NH + 255) / 256, 256>>>(zx, dtb + i * NH, dtg);

        conv_silu<<<((ROWS / 4) * CONVD + 255) / 256, 256>>>(zx, cw + (size_t)i * CONVD * 4, cb + i * CONVD, xbc, rev);

        {
            dim3 gs(NC, NH, BATCH);
            chunk_state_kernel<<<gs, 256>>>(xbc, dtg, alog + i * NH, sloc, cdec, rev);
            chunk_scan_state<<<BATCH * NH, 256>>>(sloc, cdec, hinit);
            chunk_output_kernel<<<gs, 256>>>(xbc, dtg, alog + i * NH, hinit, Dp + i * NH, ybuf, rev);
        }

        gate_rms<<<ROWS, 256>>>(zx, ybuf, gw + i * DI);

        {   // out_proj [8192 x 512 x 1024]
            dim3 grid(DM / 256, ROWS / 128);
            tf32_gemm_nt<<<grid, 256, GEMM_SMEM>>>(ROWS, DM, DI, ybuf, wow + (size_t)i * DM * DI, tmp, 0);
        }

        add_ln_kernel<<<ROWS, 128>>>(tmp, resid, n2w + i * DM, n2b + i * DM, hbuf, 0, 1);

        {   // FFN f1 + fused GLU: [8192 x 512(interleaved) x 512] -> glu [8192 x 256]
            dim3 grid(DM / 256, ROWS / 128);
            tf32_gemm_nt<<<grid, 256, GEMM_SMEM>>>(ROWS, DM, DM, hbuf, wf1 + (size_t)i * DM * DM, glub, 1);
        }

        {   // FFN f2 [8192 x 512 x 256]
            dim3 grid(DM / 256, ROWS / 128);
            tf32_gemm_nt<<<grid, 256, GEMM_SMEM>>>(ROWS, DM, DINTER, glub, wf2 + (size_t)i * DM * DINTER, xb, 0);
        }
    }

    add_ln_kernel<<<ROWS, 128>>>(xb, resid, nfw, nfb, (float*)d_out, 0, 0);
}

// round 8
// speedup vs baseline: 6.3114x; 1.2680x over previous
#include <cuda_runtime.h>
#include <cuda_fp16.h>
#include <math.h>
#include <stdint.h>

#define BATCH 4
#define T 2048
#define DM 512
#define DI 1024
#define NH 16
#define HD 64
#define DS 16
#define CONVD 1056
#define DPROJ 2096
#define DINTER 256
#define ROWS (BATCH*T)

// chunked scan
#define CQ 64
#define NC (T/CQ)

// fp16 GEMM tiling: block 128(M) x 256(N), BK=64 halves, 4 stages
#define BKH 64
#define LDA 72                      // halves per smem row (144 B = 9*16B)
#define A_ST_BYTES (128*144)        // 18432
#define B_ST_BYTES (256*144)        // 36864
#define ST_BYTES (A_ST_BYTES+B_ST_BYTES)   // 55296
#define STG 4
#define GEMM_SMEM (STG*ST_BYTES)    // 221184

// ---------------- scratch ----------------
__device__ float g_resid[ROWS*DM];
__device__ __half g_hh[ROWS*DM];          // LN output (fp16, GEMM A)
__device__ float g_zx[ROWS*DPROJ];
__device__ float g_xbc[ROWS*CONVD];
__device__ float g_dt[ROWS*NH];
__device__ float g_y[ROWS*DI];            // scan output fp32
__device__ __half g_yh[ROWS*DI];          // gated+rms output (fp16, GEMM A)
__device__ float g_tmp[ROWS*DM];
__device__ __half g_gluh[ROWS*DINTER];    // fused GLU output (fp16, GEMM A)
__device__ float g_x[ROWS*DM];
__device__ float g_sloc[BATCH*NH*NC*HD*DS];
__device__ float g_hinit[BATCH*NH*NC*HD*DS];
__device__ float g_cdecay[BATCH*NH*NC];
// fp16 weights
__device__ __half g_winw[4*DPROJ*DM];
__device__ __half g_wow[4*DM*DI];
__device__ __half g_wf1[4*2*DINTER*DM];   // row-interleaved (a,g pairs)
__device__ __half g_wf2[4*DM*DINTER];

// ---------------- weight conversion ----------------
__global__ void conv_copy_h(const float* __restrict__ src, __half* __restrict__ dst, int n4) {
    int i = blockIdx.x * blockDim.x + threadIdx.x;
    if (i >= n4) return;
    float4 v = ((const float4*)src)[i];
    __half2 lo = __floats2half2_rn(v.x, v.y);
    __half2 hi = __floats2half2_rn(v.z, v.w);
    ((__half2*)dst)[2 * i] = lo;
    ((__half2*)dst)[2 * i + 1] = hi;
}

__global__ void conv_interleave_f1_h(const float* __restrict__ src, __half* __restrict__ dst) {
    int i = blockIdx.x * blockDim.x + threadIdx.x;
    int total4 = 4 * 512 * 512 / 4;
    if (i >= total4) return;
    int k4 = i & 127;
    int row = (i >> 7) & 511;
    int l = i >> 16;
    float4 v = ((const float4*)src)[i];
    int drow = (row < 256) ? (2 * row) : (2 * (row - 256) + 1);
    size_t o = (((size_t)l * 512 + drow) * 512 + k4 * 4);
    __half2 lo = __floats2half2_rn(v.x, v.y);
    __half2 hi = __floats2half2_rn(v.z, v.w);
    ((__half2*)(dst + o))[0] = lo;
    ((__half2*)(dst + o))[1] = hi;
}

// ---------------- residual add + LayerNorm ----------------
__global__ void add_ln_kernel(const float* __restrict__ xin, float* __restrict__ resid,
                              const float* __restrict__ w, const float* __restrict__ bch,
                              void* __restrict__ out, int first, int to_half) {
    int row = blockIdx.x;
    const float* xr = xin + (size_t)row * DM;
    float* rr = resid + (size_t)row * DM;
    int tid = threadIdx.x;
    float v[4]; float s = 0.f, s2 = 0.f;
#pragma unroll
    for (int j = 0; j < 4; j++) {
        int c = tid + j * 128;
        float val = xr[c];
        if (!first) val += rr[c];
        v[j] = val; s += val; s2 += val * val;
    }
#pragma unroll
    for (int o = 16; o > 0; o >>= 1) {
        s  += __shfl_xor_sync(0xffffffffu, s, o);
        s2 += __shfl_xor_sync(0xffffffffu, s2, o);
    }
    __shared__ float rs[4], rs2[4];
    int wid = tid >> 5;
    if ((tid & 31) == 0) { rs[wid] = s; rs2[wid] = s2; }
    __syncthreads();
    float tot  = rs[0] + rs[1] + rs[2] + rs[3];
    float tot2 = rs2[0] + rs2[1] + rs2[2] + rs2[3];
    float mu = tot * (1.f / DM);
    float var = tot2 * (1.f / DM) - mu * mu;
    float inv = rsqrtf(var + 1e-5f);
#pragma unroll
    for (int j = 0; j < 4; j++) {
        int c = tid + j * 128;
        float val = v[j];
        rr[c] = val;
        float o2 = (val - mu) * inv * w[c] + bch[c];
        if (to_half) ((__half*)out)[(size_t)row * DM + c] = __float2half_rn(o2);
        else         ((float*)out)[(size_t)row * DM + c] = o2;
    }
}

// ---------------- fp16 tensor-core NT GEMM (128x256 block, 4-stage) ----------------
#define MMA_F16(d, a, b) \
    asm volatile("mma.sync.aligned.m16n8k16.row.col.f32.f16.f16.f32 " \
                 "{%0,%1,%2,%3},{%4,%5,%6,%7},{%8,%9},{%0,%1,%2,%3};" \
                 : "+f"(d[0]), "+f"(d[1]), "+f"(d[2]), "+f"(d[3]) \
                 : "r"(a[0]), "r"(a[1]), "r"(a[2]), "r"(a[3]), "r"(b[0]), "r"(b[1]))

#define LDSM_X4(R, addr) \
    asm volatile("ldmatrix.sync.aligned.m8n8.x4.shared.b16 {%0,%1,%2,%3}, [%4];" \
                 : "=r"((R)[0]), "=r"((R)[1]), "=r"((R)[2]), "=r"((R)[3]) : "r"(addr))

__device__ __forceinline__ void gemm_load_stage(
    const __half* __restrict__ A, const __half* __restrict__ Bw,
    int K, int N, int bm, int bn, int it, int s, int tid, uint32_t sbase)
{
    int k0 = it * BKH;
    uint32_t stA = sbase + (uint32_t)s * ST_BYTES;
    uint32_t stB = stA + A_ST_BYTES;
    // A: 128 rows x 64 halves = 1024 x 16B
#pragma unroll
    for (int i = 0; i < 4; i++) {
        int idx = i * 256 + tid;
        int row = idx >> 3, c = idx & 7;
        uint32_t dst = stA + (uint32_t)row * 144u + (uint32_t)(c << 4);
        const __half* gp = A + (size_t)(bm + row) * K + k0 + c * 8;
        asm volatile("cp.async.cg.shared.global [%0], [%1], 16;" :: "r"(dst), "l"(gp));
    }
    // B: 256 rows
#pragma unroll
    for (int i = 0; i < 8; i++) {
        int idx = i * 256 + tid;
        int row = idx >> 3, c = idx & 7;
        int rb = bn + row;
        int valid = (rb < N);
        uint32_t dst = stB + (uint32_t)row * 144u + (uint32_t)(c << 4);
        const __half* gp = Bw + (size_t)(valid ? rb : 0) * K + k0 + c * 8;
        int ssz = valid ? 16 : 0;
        asm volatile("cp.async.cg.shared.global [%0], [%1], 16, %2;" :: "r"(dst), "l"(gp), "r"(ssz));
    }
    asm volatile("cp.async.commit_group;" ::: "memory");
}

// fuse_glu: output N/2 half values a*silu(g) per row; else fp32 C.
__global__ void __launch_bounds__(256) h16_gemm_nt(int M, int N, int K,
                                                   const __half* __restrict__ A,
                                                   const __half* __restrict__ Bw,
                                                   void* __restrict__ Cv, int fuse_glu) {
    extern __shared__ char smem[];
    uint32_t sbase = (uint32_t)__cvta_generic_to_shared(smem);
    int bm = blockIdx.y * 128, bn = blockIdx.x * 256;
    int tid = threadIdx.x;
    int wid = tid >> 5, lane = tid & 31;
    int wm = (wid & 1) * 64;        // 2 warps along M
    int wn = (wid >> 1) * 64;       // 4 warps along N
    int g = lane >> 2, tig = lane & 3;

    // ldmatrix lane addressing
    int arow = lane & 15;                 // within m16
    int acol = (lane >> 4) << 3;          // 0 or 8
    int brow = ((lane >> 4) << 3) + (lane & 7);   // within n16 (pair of ntiles)
    int bcol = ((lane >> 3) & 1) << 3;    // 0 or 8
    uint32_t aoff = ((uint32_t)((wm + arow) * LDA + acol)) * 2u;
    uint32_t boff = ((uint32_t)((wn + brow) * LDA + bcol)) * 2u + A_ST_BYTES;

    float acc[4][8][4];
#pragma unroll
    for (int i = 0; i < 4; i++)
#pragma unroll
        for (int j = 0; j < 8; j++)
#pragma unroll
            for (int k = 0; k < 4; k++) acc[i][j][k] = 0.f;

    int NIT = K / BKH;
#pragma unroll
    for (int p = 0; p < STG; p++)
        if (p < NIT) gemm_load_stage(A, Bw, K, N, bm, bn, p, p, tid, sbase);

    for (int it = 0; it < NIT; ++it) {
        int pend = NIT - it - 1; if (pend > STG - 1) pend = STG - 1;
        if (pend == 3)      asm volatile("cp.async.wait_group 3;" ::: "memory");
        else if (pend == 2) asm volatile("cp.async.wait_group 2;" ::: "memory");
        else if (pend == 1) asm volatile("cp.async.wait_group 1;" ::: "memory");
        else                asm volatile("cp.async.wait_group 0;" ::: "memory");
        __syncthreads();
        int s = it & (STG - 1);
        uint32_t Ab = sbase + (uint32_t)s * ST_BYTES + aoff;
        uint32_t Bb = sbase + (uint32_t)s * ST_BYTES + boff;
#pragma unroll
        for (int ks = 0; ks < 4; ks++) {         // k16 steps within BK=64
            uint32_t kbyte = (uint32_t)(ks * 16 * 2);
            uint32_t a[4][4], b[4][4];
#pragma unroll
            for (int mt = 0; mt < 4; mt++)
                LDSM_X4(a[mt], Ab + (uint32_t)(mt * 16 * LDA) * 2u + kbyte);
#pragma unroll
            for (int np = 0; np < 4; np++)       // pairs of ntiles
                LDSM_X4(b[np], Bb + (uint32_t)(np * 16 * LDA) * 2u + kbyte);
#pragma unroll
            for (int mt = 0; mt < 4; mt++)
#pragma unroll
                for (int np = 0; np < 4; np++) {
                    MMA_F16(acc[mt][2 * np], a[mt], b[np]);
                    uint32_t bhi[2] = { b[np][2], b[np][3] };
                    MMA_F16(acc[mt][2 * np + 1], a[mt], bhi);
                }
        }
        __syncthreads();
        if (it + STG < NIT) gemm_load_stage(A, Bw, K, N, bm, bn, it + STG, s, tid, sbase);
    }

    if (!fuse_glu) {
        float* C = (float*)Cv;
#pragma unroll
        for (int mt = 0; mt < 4; mt++) {
            int r0 = bm + wm + mt * 16 + g;
#pragma unroll
            for (int nt = 0; nt < 8; nt++) {
                int c0 = bn + wn + nt * 8 + tig * 2;
                if (c0 < N) {
                    *(float2*)&C[(size_t)r0 * N + c0] = make_float2(acc[mt][nt][0], acc[mt][nt][1]);
                    *(float2*)&C[(size_t)(r0 + 8) * N + c0] = make_float2(acc[mt][nt][2], acc[mt][nt][3]);
                }
            }
        }
    } else {
        __half* C = (__half*)Cv;
        int No = N >> 1;
#pragma unroll
        for (int mt = 0; mt < 4; mt++) {
            int r0 = bm + wm + mt * 16 + g;
#pragma unroll
            for (int nt = 0; nt < 8; nt++) {
                int c0 = bn + wn + nt * 8 + tig * 2;   // even
                if (c0 < N) {
                    float a0 = acc[mt][nt][0], g0 = acc[mt][nt][1];
                    float a1 = acc[mt][nt][2], g1 = acc[mt][nt][3];
                    C[(size_t)r0 * No + (c0 >> 1)] = __float2half_rn(a0 * g0 / (1.f + expf(-g0)));
                    C[(size_t)(r0 + 8) * No + (c0 >> 1)] = __float2half_rn(a1 * g1 / (1.f + expf(-g1)));
                }
            }
        }
    }
}

// ---------------- dt = softplus(raw + dtb) ----------------
__global__ void dt_kernel(const float* __restrict__ zx, const float* __restrict__ dtb,
                          float* __restrict__ dt) {
    int idx = blockIdx.x * blockDim.x + threadIdx.x;
    if (idx >= ROWS * NH) return;
    int row = idx >> 4; int h = idx & 15;
    float raw = zx[(size_t)row * DPROJ + (DI + CONVD) + h] + dtb[h];
    float d = (raw > 20.f) ? raw : log1pf(expf(raw));
    dt[idx] = d;
}

// ---------------- depthwise causal conv: 4 t-steps per thread ----------------
__global__ void conv_silu(const float* __restrict__ zx, const float* __restrict__ cw,
                          const float* __restrict__ cb, float* __restrict__ out, int rev) {
    int idx = blockIdx.x * blockDim.x + threadIdx.x;
    if (idx >= (ROWS / 4) * CONVD) return;
    int c = idx % CONVD; int tt = idx / CONVD;
    int b = tt / (T / 4); int t0 = (tt % (T / 4)) * 4;
    const float* w = cw + c * 4;
    const float* col = zx + (size_t)b * T * DPROJ + DI + c;
    float bias = cb[c];
    float win[7];
    if (!rev) {
#pragma unroll
        for (int j = 0; j < 7; j++) {
            int t = t0 - 3 + j;
            win[j] = (t >= 0) ? col[(size_t)t * DPROJ] : 0.f;
        }
#pragma unroll
        for (int i = 0; i < 4; i++) {
            float acc = bias;
#pragma unroll
            for (int k = 0; k < 4; k++) acc += w[k] * win[i + k];
            out[((size_t)b * T + t0 + i) * CONVD + c] = acc / (1.f + expf(-acc));
        }
    } else {
#pragma unroll
        for (int j = 0; j < 7; j++) {
            int t = t0 + j;
            win[j] = (t < T) ? col[(size_t)t * DPROJ] : 0.f;
        }
#pragma unroll
        for (int i = 0; i < 4; i++) {
            float acc = bias;
#pragma unroll
            for (int k = 0; k < 4; k++) acc += w[k] * win[i + 3 - k];
            out[((size_t)b * T + t0 + i) * CONVD + c] = acc / (1.f + expf(-acc));
        }
    }
}

// ---------------- chunked SSD scan ----------------
__global__ void __launch_bounds__(256) chunk_state_kernel(
    const float* __restrict__ xbc, const float* __restrict__ dt,
    const float* __restrict__ alog, float* __restrict__ sloc,
    float* __restrict__ cdecay, int rev)
{
    int c = blockIdx.x, head = blockIdx.y, b = blockIdx.z;
    int tid = threadIdx.x;
    __shared__ float Xs[CQ][HD + 4];
    __shared__ float Bs[CQ][DS + 1];
    __shared__ float Ls[CQ];
    __shared__ float wdt[CQ];
    size_t tbase = (size_t)b * T;
    float A = -expf(alog[head]);

    for (int i = tid; i < CQ * HD; i += 256) {
        int j = i >> 6, p = i & 63;
        int s = c * CQ + j;
        int t = rev ? (T - 1 - s) : s;
        Xs[j][p] = xbc[(tbase + t) * CONVD + head * HD + p];
    }
    for (int i = tid; i < CQ * DS; i += 256) {
        int j = i >> 4, n = i & 15;
        int s = c * CQ + j;
        int t = rev ? (T - 1 - s) : s;
        Bs[j][n] = xbc[(tbase + t) * CONVD + DI + n];
    }
    if (tid < CQ) {
        int s = c * CQ + tid;
        int t = rev ? (T - 1 - s) : s;
        float d = dt[(tbase + t) * NH + head];
        wdt[tid] = d;
        Ls[tid] = d * A;
    }
    __syncthreads();
    for (int off = 1; off < CQ; off <<= 1) {
        float v = 0.f;
        if (tid < CQ) v = Ls[tid] + ((tid >= off) ? Ls[tid - off] : 0.f);
        __syncthreads();
        if (tid < CQ) Ls[tid] = v;
        __syncthreads();
    }
    float Lend = Ls[CQ - 1];

    int p = tid >> 2, ng = (tid & 3) << 2;
    float acc0 = 0.f, acc1 = 0.f, acc2 = 0.f, acc3 = 0.f;
    for (int j = 0; j < CQ; j++) {
        float w = expf(Lend - Ls[j]) * wdt[j];
        float xv = w * Xs[j][p];
        acc0 += xv * Bs[j][ng + 0];
        acc1 += xv * Bs[j][ng + 1];
        acc2 += xv * Bs[j][ng + 2];
        acc3 += xv * Bs[j][ng + 3];
    }
    size_t o = ((((size_t)b * NH + head) * NC + c) * HD + p) * DS + ng;
    sloc[o + 0] = acc0; sloc[o + 1] = acc1; sloc[o + 2] = acc2; sloc[o + 3] = acc3;
    if (tid == 0) cdecay[((size_t)b * NH + head) * NC + c] = expf(Lend);
}

__global__ void __launch_bounds__(256) chunk_scan_state(
    const float* __restrict__ sloc, const float* __restrict__ cdecay,
    float* __restrict__ hinit)
{
    int bh = blockIdx.x;
    int tid = threadIdx.x;
    float h0 = 0.f, h1 = 0.f, h2 = 0.f, h3 = 0.f;
    for (int c = 0; c < NC; c++) {
        size_t base = ((size_t)bh * NC + c) * (HD * DS);
        float d = cdecay[(size_t)bh * NC + c];
        size_t i0 = base + tid, i1 = base + tid + 256, i2 = base + tid + 512, i3 = base + tid + 768;
        hinit[i0] = h0; hinit[i1] = h1; hinit[i2] = h2; hinit[i3] = h3;
        h0 = d * h0 + sloc[i0];
        h1 = d * h1 + sloc[i1];
        h2 = d * h2 + sloc[i2];
        h3 = d * h3 + sloc[i3];
    }
}

__global__ void __launch_bounds__(256) chunk_output_kernel(
    const float* __restrict__ xbc, const float* __restrict__ dt,
    const float* __restrict__ alog, const float* __restrict__ hinit,
    const float* __restrict__ Dp, float* __restrict__ y, int rev)
{
    int c = blockIdx.x, head = blockIdx.y, b = blockIdx.z;
    int tid = threadIdx.x;
    __shared__ float Xs[CQ][HD + 4];
    __shared__ float Bs[CQ][DS + 1];
    __shared__ float Cs[CQ][DS + 1];
    __shared__ float h0s[HD][DS + 1];
    __shared__ float Ls[CQ];
    __shared__ float wdt[CQ];
    __shared__ float Ss[CQ][CQ + 1];
    size_t tbase = (size_t)b * T;
    float A = -expf(alog[head]);

    for (int i = tid; i < CQ * HD; i += 256) {
        int j = i >> 6, p = i & 63;
        int s = c * CQ + j;
        int t = rev ? (T - 1 - s) : s;
        Xs[j][p] = xbc[(tbase + t) * CONVD + head * HD + p];
    }
    for (int i = tid; i < CQ * DS; i += 256) {
        int j = i >> 4, n = i & 15;
        int s = c * CQ + j;
        int t = rev ? (T - 1 - s) : s;
        size_t row = (tbase + t) * CONVD + DI;
        Bs[j][n] = xbc[row + n];
        Cs[j][n] = xbc[row + DS + n];
    }
    {
        size_t hb = ((((size_t)b * NH + head) * NC + c) * HD) * DS;
        for (int i = tid; i < HD * DS; i += 256) {
            int p = i >> 4, n = i & 15;
            h0s[p][n] = hinit[hb + i];
        }
    }
    if (tid < CQ) {
        int s = c * CQ + tid;
        int t = rev ? (T - 1 - s) : s;
        float d = dt[(tbase + t) * NH + head];
        wdt[tid] = d;
        Ls[tid] = d * A;
    }
    __syncthreads();
    for (int off = 1; off < CQ; off <<= 1) {
        float v = 0.f;
        if (tid < CQ) v = Ls[tid] + ((tid >= off) ? Ls[tid - off] : 0.f);
        __syncthreads();
        if (tid < CQ) Ls[tid] = v;
        __syncthreads();
    }

    int t = tid >> 2;
    int quad = tid & 3;
    float Ct[DS];
#pragma unroll
    for (int n = 0; n < DS; n++) Ct[n] = Cs[t][n];
    float Lt = Ls[t];

    int jb = quad * 16;
#pragma unroll
    for (int q = 0; q < 16; q++) {
        int j = jb + q;
        float sv = 0.f;
        if (j <= t) {
            float dot = 0.f;
#pragma unroll
            for (int n = 0; n < DS; n++) dot += Ct[n] * Bs[j][n];
            sv = expf(Lt - Ls[j]) * wdt[j] * dot;
        }
        Ss[t][j] = sv;
    }
    __syncthreads();

    int pb = quad * 16;
    float acc[16];
#pragma unroll
    for (int k = 0; k < 16; k++) acc[k] = 0.f;
    for (int j = 0; j <= t; j++) {
        float sv = Ss[t][j];
#pragma unroll
        for (int k4 = 0; k4 < 4; k4++) {
            float4 xv = *(const float4*)&Xs[j][pb + k4 * 4];
            acc[k4 * 4 + 0] += sv * xv.x;
            acc[k4 * 4 + 1] += sv * xv.y;
            acc[k4 * 4 + 2] += sv * xv.z;
            acc[k4 * 4 + 3] += sv * xv.w;
        }
    }
    float et = expf(Lt);
    float Dv = Dp[head];
#pragma unroll
    for (int k = 0; k < 16; k++) {
        int p = pb + k;
        float dot = 0.f;
#pragma unroll
        for (int n = 0; n < DS; n++) dot += Ct[n] * h0s[p][n];
        acc[k] += et * dot + Dv * Xs[t][p];
    }
    int s_idx = c * CQ + t;
    int trow = rev ? (T - 1 - s_idx) : s_idx;
    float* yr = y + (tbase + trow) * DI + head * HD + pb;
#pragma unroll
    for (int k4 = 0; k4 < 4; k4++) {
        *(float4*)(yr + k4 * 4) = make_float4(acc[k4 * 4 + 0], acc[k4 * 4 + 1], acc[k4 * 4 + 2], acc[k4 * 4 + 3]);
    }
}

// ---------------- y = y * silu(z); RMSNorm(y) * gw -> fp16 ----------------
__global__ void gate_rms(const float* __restrict__ zx, const float* __restrict__ y,
                         const float* __restrict__ gw, __half* __restrict__ yh) {
    int row = blockIdx.x;
    const float* z = zx + (size_t)row * DPROJ;
    const float* yr = y + (size_t)row * DI;
    __half* yo = yh + (size_t)row * DI;
    int tid = threadIdx.x;
    float v[4]; float s2 = 0.f;
#pragma unroll
    for (int j = 0; j < 4; j++) {
        int c = tid + j * 256;
        float zz = z[c];
        float val = yr[c] * (zz / (1.f + expf(-zz)));
        v[j] = val; s2 += val * val;
    }
#pragma unroll
    for (int o = 16; o > 0; o >>= 1) s2 += __shfl_xor_sync(0xffffffffu, s2, o);
    __shared__ float rs[8];
    int wid = tid >> 5;
    if ((tid & 31) == 0) rs[wid] = s2;
    __syncthreads();
    float tot = 0.f;
#pragma unroll
    for (int i = 0; i < 8; i++) tot += rs[i];
    float inv = rsqrtf(tot * (1.f / DI) + 1e-5f);
#pragma unroll
    for (int j = 0; j < 4; j++) {
        int c = tid + j * 256;
        yo[c] = __float2half_rn(v[j] * inv * gw[c]);
    }
}

// ---------------- host ----------------
static void* sym_addr_v(const void* sym) {
    void* p = nullptr;
    cudaGetSymbolAddress(&p, sym);
    return p;
}

extern "C" void kernel_launch(void* const* d_in, const int* in_sizes, int n_in,
                              void* d_out, int out_size) {
    const float* in_x   = (const float*)d_in[0];
    const float* n1w    = (const float*)d_in[1];
    const float* n1b    = (const float*)d_in[2];
    const float* inw    = (const float*)d_in[3];
    const float* cw     = (const float*)d_in[4];
    const float* cb     = (const float*)d_in[5];
    const float* dtb    = (const float*)d_in[6];
    const float* alog   = (const float*)d_in[7];
    const float* Dp     = (const float*)d_in[8];
    const float* gw     = (const float*)d_in[9];
    const float* ow     = (const float*)d_in[10];
    const float* n2w    = (const float*)d_in[11];
    const float* n2b    = (const float*)d_in[12];
    const float* f1w    = (const float*)d_in[13];
    const float* f2w    = (const float*)d_in[14];
    const float* nfw    = (const float*)d_in[15];
    const float* nfb    = (const float*)d_in[16];

    float*  resid = (float*) sym_addr_v(g_resid);
    __half* hh    = (__half*)sym_addr_v(g_hh);
    float*  zx    = (float*) sym_addr_v(g_zx);
    float*  xbc   = (float*) sym_addr_v(g_xbc);
    float*  dtg   = (float*) sym_addr_v(g_dt);
    float*  ybuf  = (float*) sym_addr_v(g_y);
    __half* yh    = (__half*)sym_addr_v(g_yh);
    float*  tmp   = (float*) sym_addr_v(g_tmp);
    __half* gluh  = (__half*)sym_addr_v(g_gluh);
    float*  xb    = (float*) sym_addr_v(g_x);
    float*  sloc  = (float*) sym_addr_v(g_sloc);
    float*  hinit = (float*) sym_addr_v(g_hinit);
    float*  cdec  = (float*) sym_addr_v(g_cdecay);
    __half* winw  = (__half*)sym_addr_v(g_winw);
    __half* wow   = (__half*)sym_addr_v(g_wow);
    __half* wf1   = (__half*)sym_addr_v(g_wf1);
    __half* wf2   = (__half*)sym_addr_v(g_wf2);

    static int smem_set = 0;
    if (!smem_set) {
        cudaFuncSetAttribute(h16_gemm_nt, cudaFuncAttributeMaxDynamicSharedMemorySize, GEMM_SMEM);
        smem_set = 1;
    }

    // convert weights to fp16 (f1 also row-interleaved for fused GLU)
    {
        int n;
        n = 4 * DPROJ * DM / 4;      conv_copy_h<<<(n + 255) / 256, 256>>>(inw, winw, n);
        n = 4 * DM * DI / 4;         conv_copy_h<<<(n + 255) / 256, 256>>>(ow, wow, n);
        n = 4 * 2 * DINTER * DM / 4; conv_interleave_f1_h<<<(n + 255) / 256, 256>>>(f1w, wf1);
        n = 4 * DM * DINTER / 4;     conv_copy_h<<<(n + 255) / 256, 256>>>(f2w, wf2, n);
    }

    for (int i = 0; i < 4; i++) {
        int rev = i & 1;
        const float* xin = (i == 0) ? in_x : xb;

        add_ln_kernel<<<ROWS, 128>>>(xin, resid, n1w + i * DM, n1b + i * DM, hh, (i == 0) ? 1 : 0, 1);

        {   // in_proj [8192 x 2096 x 512]
            dim3 grid((DPROJ + 255) / 256, ROWS / 128);
            h16_gemm_nt<<<grid, 256, GEMM_SMEM>>>(ROWS, DPROJ, DM, hh, winw + (size_t)i * DPROJ * DM, zx, 0);
        }

        dt_kernel<<<(ROWS * NH + 255) / 256, 256>>>(zx, dtb + i * NH, dtg);

        conv_silu<<<((ROWS / 4) * CONVD + 255) / 256, 256>>>(zx, cw + (size_t)i * CONVD * 4, cb + i * CONVD, xbc, rev);

        {
            dim3 gs(NC, NH, BATCH);
            chunk_state_kernel<<<gs, 256>>>(xbc, dtg, alog + i * NH, sloc, cdec, rev);
            chunk_scan_state<<<BATCH * NH, 256>>>(sloc, cdec, hinit);
            chunk_output_kernel<<<gs, 256>>>(xbc, dtg, alog + i * NH, hinit, Dp + i * NH, ybuf, rev);
        }

        gate_rms<<<ROWS, 256>>>(zx, ybuf, gw + i * DI, yh);

        {   // out_proj [8192 x 512 x 1024]
            dim3 grid(DM / 256, ROWS / 128);
            h16_gemm_nt<<<grid, 256, GEMM_SMEM>>>(ROWS, DM, DI, yh, wow + (size_t)i * DM * DI, tmp, 0);
        }

        add_ln_kernel<<<ROWS, 128>>>(tmp, resid, n2w + i * DM, n2b + i * DM, hh, 0, 1);

        {   // FFN f1 + fused GLU: [8192 x 512(interleaved) x 512] -> gluh [8192 x 256] fp16
            dim3 grid(DM / 256, ROWS / 128);
            h16_gemm_nt<<<grid, 256, GEMM_SMEM>>>(ROWS, DM, DM, hh, wf1 + (size_t)i * DM * DM, gluh, 1);
        }

        {   // FFN f2 [8192 x 512 x 256]
            dim3 grid(DM / 256, ROWS / 128);
            h16_gemm_nt<<<grid, 256, GEMM_SMEM>>>(ROWS, DM, DINTER, gluh, wf2 + (size_t)i * DM * DINTER, xb, 0);
        }
    }

    add_ln_kernel<<<ROWS, 128>>>(xb, resid, nfw, nfb, (float*)d_out, 0, 0);
}

// round 10
// speedup vs baseline: 6.3462x; 1.0055x over previous
#include <cuda_runtime.h>
#include <cuda_fp16.h>
#include <math.h>
#include <stdint.h>

#define BATCH 4
#define T 2048
#define DM 512
#define DI 1024
#define NH 16
#define HD 64
#define DS 16
#define CONVD 1056
#define DPROJ 2096
#define DINTER 256
#define ROWS (BATCH*T)

// chunked scan
#define CQ 64
#define NC (T/CQ)

// fp16 GEMM tiling: block 128(M) x 256(N), BK=64 halves, 4 stages
#define BKH 64
#define LDA 72                      // halves per smem row (144 B)
#define A_ST_BYTES (128*144)
#define B_ST_BYTES (256*144)
#define ST_BYTES (A_ST_BYTES+B_ST_BYTES)   // 55296
#define STG 4
#define GEMM_SMEM (STG*ST_BYTES)    // 221184

// ---------------- scratch ----------------
__device__ float g_resid[ROWS*DM];
__device__ __half g_hh[ROWS*DM];          // LN output (fp16, GEMM A)
__device__ __half g_zx[ROWS*DPROJ];       // in_proj output (fp16)
__device__ float g_xbc[ROWS*CONVD];
__device__ float g_y[ROWS*DI];
__device__ __half g_yh[ROWS*DI];
__device__ float g_tmp[ROWS*DM];
__device__ __half g_gluh[ROWS*DINTER];
__device__ float g_x[ROWS*DM];
__device__ float g_sloc[BATCH*NH*NC*HD*DS];
__device__ float g_hinit[BATCH*NH*NC*HD*DS];
__device__ float g_cdecay[BATCH*NH*NC];
// fp16 weights
__device__ __half g_winw[4*DPROJ*DM];
__device__ __half g_wow[4*DM*DI];
__device__ __half g_wf1[4*2*DINTER*DM];
__device__ __half g_wf2[4*DM*DINTER];

// ---------------- weight conversion ----------------
__global__ void conv_copy_h(const float* __restrict__ src, __half* __restrict__ dst, int n4) {
    int i = blockIdx.x * blockDim.x + threadIdx.x;
    if (i >= n4) return;
    float4 v = ((const float4*)src)[i];
    ((__half2*)dst)[2 * i]     = __floats2half2_rn(v.x, v.y);
    ((__half2*)dst)[2 * i + 1] = __floats2half2_rn(v.z, v.w);
}

__global__ void conv_interleave_f1_h(const float* __restrict__ src, __half* __restrict__ dst) {
    int i = blockIdx.x * blockDim.x + threadIdx.x;
    int total4 = 4 * 512 * 512 / 4;
    if (i >= total4) return;
    int k4 = i & 127;
    int row = (i >> 7) & 511;
    int l = i >> 16;
    float4 v = ((const float4*)src)[i];
    int drow = (row < 256) ? (2 * row) : (2 * (row - 256) + 1);
    size_t o = (((size_t)l * 512 + drow) * 512 + k4 * 4);
    ((__half2*)(dst + o))[0] = __floats2half2_rn(v.x, v.y);
    ((__half2*)(dst + o))[1] = __floats2half2_rn(v.z, v.w);
}

// ---------------- residual add + LayerNorm ----------------
__global__ void add_ln_kernel(const float* __restrict__ xin, float* __restrict__ resid,
                              const float* __restrict__ w, const float* __restrict__ bch,
                              void* __restrict__ out, int first, int to_half) {
    int row = blockIdx.x;
    const float* xr = xin + (size_t)row * DM;
    float* rr = resid + (size_t)row * DM;
    int tid = threadIdx.x;
    float v[4]; float s = 0.f, s2 = 0.f;
#pragma unroll
    for (int j = 0; j < 4; j++) {
        int c = tid + j * 128;
        float val = xr[c];
        if (!first) val += rr[c];
        v[j] = val; s += val; s2 += val * val;
    }
#pragma unroll
    for (int o = 16; o > 0; o >>= 1) {
        s  += __shfl_xor_sync(0xffffffffu, s, o);
        s2 += __shfl_xor_sync(0xffffffffu, s2, o);
    }
    __shared__ float rs[4], rs2[4];
    int wid = tid >> 5;
    if ((tid & 31) == 0) { rs[wid] = s; rs2[wid] = s2; }
    __syncthreads();
    float tot  = rs[0] + rs[1] + rs[2] + rs[3];
    float tot2 = rs2[0] + rs2[1] + rs2[2] + rs2[3];
    float mu = tot * (1.f / DM);
    float var = tot2 * (1.f / DM) - mu * mu;
    float inv = rsqrtf(var + 1e-5f);
#pragma unroll
    for (int j = 0; j < 4; j++) {
        int c = tid + j * 128;
        float val = v[j];
        rr[c] = val;
        float o2 = (val - mu) * inv * w[c] + bch[c];
        if (to_half) ((__half*)out)[(size_t)row * DM + c] = __float2half_rn(o2);
        else         ((float*)out)[(size_t)row * DM + c] = o2;
    }
}

// ---------------- fp16 tensor-core NT GEMM (128x256 block, 4-stage) ----------------
#define MMA_F16(d, a, b) \
    asm volatile("mma.sync.aligned.m16n8k16.row.col.f32.f16.f16.f32 " \
                 "{%0,%1,%2,%3},{%4,%5,%6,%7},{%8,%9},{%0,%1,%2,%3};" \
                 : "+f"(d[0]), "+f"(d[1]), "+f"(d[2]), "+f"(d[3]) \
                 : "r"(a[0]), "r"(a[1]), "r"(a[2]), "r"(a[3]), "r"(b[0]), "r"(b[1]))

#define LDSM_X4(R, addr) \
    asm volatile("ldmatrix.sync.aligned.m8n8.x4.shared.b16 {%0,%1,%2,%3}, [%4];" \
                 : "=r"((R)[0]), "=r"((R)[1]), "=r"((R)[2]), "=r"((R)[3]) : "r"(addr))

__device__ __forceinline__ void gemm_load_stage(
    const __half* __restrict__ A, const __half* __restrict__ Bw,
    int K, int N, int bm, int bn, int it, int s, int tid, uint32_t sbase)
{
    int k0 = it * BKH;
    uint32_t stA = sbase + (uint32_t)s * ST_BYTES;
    uint32_t stB = stA + A_ST_BYTES;
#pragma unroll
    for (int i = 0; i < 4; i++) {
        int idx = i * 256 + tid;
        int row = idx >> 3, c = idx & 7;
        uint32_t dst = stA + (uint32_t)row * 144u + (uint32_t)(c << 4);
        const __half* gp = A + (size_t)(bm + row) * K + k0 + c * 8;
        asm volatile("cp.async.cg.shared.global [%0], [%1], 16;" :: "r"(dst), "l"(gp));
    }
#pragma unroll
    for (int i = 0; i < 8; i++) {
        int idx = i * 256 + tid;
        int row = idx >> 3, c = idx & 7;
        int rb = bn + row;
        int valid = (rb < N);
        uint32_t dst = stB + (uint32_t)row * 144u + (uint32_t)(c << 4);
        const __half* gp = Bw + (size_t)(valid ? rb : 0) * K + k0 + c * 8;
        int ssz = valid ? 16 : 0;
        asm volatile("cp.async.cg.shared.global [%0], [%1], 16, %2;" :: "r"(dst), "l"(gp), "r"(ssz));
    }
    asm volatile("cp.async.commit_group;" ::: "memory");
}

// out_mode: 0 = fp32 C, 1 = fused GLU (fp16, N/2 cols), 2 = fp16 C
__global__ void __launch_bounds__(256) h16_gemm_nt(int M, int N, int K,
                                                   const __half* __restrict__ A,
                                                   const __half* __restrict__ Bw,
                                                   void* __restrict__ Cv, int out_mode) {
    extern __shared__ char smem[];
    uint32_t sbase = (uint32_t)__cvta_generic_to_shared(smem);
    int bm = blockIdx.y * 128, bn = blockIdx.x * 256;
    int tid = threadIdx.x;
    int wid = tid >> 5, lane = tid & 31;
    int wm = (wid & 1) * 64;
    int wn = (wid >> 1) * 64;
    int g = lane >> 2, tig = lane & 3;

    int arow = lane & 15;
    int acol = (lane >> 4) << 3;
    int brow = ((lane >> 4) << 3) + (lane & 7);
    int bcol = ((lane >> 3) & 1) << 3;
    uint32_t aoff = ((uint32_t)((wm + arow) * LDA + acol)) * 2u;
    uint32_t boff = ((uint32_t)((wn + brow) * LDA + bcol)) * 2u + A_ST_BYTES;

    float acc[4][8][4];
#pragma unroll
    for (int i = 0; i < 4; i++)
#pragma unroll
        for (int j = 0; j < 8; j++)
#pragma unroll
            for (int k = 0; k < 4; k++) acc[i][j][k] = 0.f;

    int NIT = K / BKH;
#pragma unroll
    for (int p = 0; p < STG; p++)
        if (p < NIT) gemm_load_stage(A, Bw, K, N, bm, bn, p, p, tid, sbase);

    for (int it = 0; it < NIT; ++it) {
        int pend = NIT - it - 1; if (pend > STG - 1) pend = STG - 1;
        if (pend == 3)      asm volatile("cp.async.wait_group 3;" ::: "memory");
        else if (pend == 2) asm volatile("cp.async.wait_group 2;" ::: "memory");
        else if (pend == 1) asm volatile("cp.async.wait_group 1;" ::: "memory");
        else                asm volatile("cp.async.wait_group 0;" ::: "memory");
        __syncthreads();
        int s = it & (STG - 1);
        uint32_t Ab = sbase + (uint32_t)s * ST_BYTES + aoff;
        uint32_t Bb = sbase + (uint32_t)s * ST_BYTES + boff;
#pragma unroll
        for (int ks = 0; ks < 4; ks++) {
            uint32_t kbyte = (uint32_t)(ks * 16 * 2);
            uint32_t a[4][4], b[4][4];
#pragma unroll
            for (int mt = 0; mt < 4; mt++)
                LDSM_X4(a[mt], Ab + (uint32_t)(mt * 16 * LDA) * 2u + kbyte);
#pragma unroll
            for (int np = 0; np < 4; np++)
                LDSM_X4(b[np], Bb + (uint32_t)(np * 16 * LDA) * 2u + kbyte);
#pragma unroll
            for (int mt = 0; mt < 4; mt++)
#pragma unroll
                for (int np = 0; np < 4; np++) {
                    MMA_F16(acc[mt][2 * np], a[mt], b[np]);
                    uint32_t bhi[2] = { b[np][2], b[np][3] };
                    MMA_F16(acc[mt][2 * np + 1], a[mt], bhi);
                }
        }
        __syncthreads();
        if (it + STG < NIT) gemm_load_stage(A, Bw, K, N, bm, bn, it + STG, s, tid, sbase);
    }

    if (out_mode == 0) {
        float* C = (float*)Cv;
#pragma unroll
        for (int mt = 0; mt < 4; mt++) {
            int r0 = bm + wm + mt * 16 + g;
#pragma unroll
            for (int nt = 0; nt < 8; nt++) {
                int c0 = bn + wn + nt * 8 + tig * 2;
                if (c0 < N) {
                    *(float2*)&C[(size_t)r0 * N + c0] = make_float2(acc[mt][nt][0], acc[mt][nt][1]);
                    *(float2*)&C[(size_t)(r0 + 8) * N + c0] = make_float2(acc[mt][nt][2], acc[mt][nt][3]);
                }
            }
        }
    } else if (out_mode == 2) {
        __half* C = (__half*)Cv;
#pragma unroll
        for (int mt = 0; mt < 4; mt++) {
            int r0 = bm + wm + mt * 16 + g;
#pragma unroll
            for (int nt = 0; nt < 8; nt++) {
                int c0 = bn + wn + nt * 8 + tig * 2;
                if (c0 < N) {
                    *(__half2*)&C[(size_t)r0 * N + c0] = __floats2half2_rn(acc[mt][nt][0], acc[mt][nt][1]);
                    *(__half2*)&C[(size_t)(r0 + 8) * N + c0] = __floats2half2_rn(acc[mt][nt][2], acc[mt][nt][3]);
                }
            }
        }
    } else {
        __half* C = (__half*)Cv;
        int No = N >> 1;
#pragma unroll
        for (int mt = 0; mt < 4; mt++) {
            int r0 = bm + wm + mt * 16 + g;
#pragma unroll
            for (int nt = 0; nt < 8; nt++) {
                int c0 = bn + wn + nt * 8 + tig * 2;
                if (c0 < N) {
                    float a0 = acc[mt][nt][0], g0 = acc[mt][nt][1];
                    float a1 = acc[mt][nt][2], g1 = acc[mt][nt][3];
                    C[(size_t)r0 * No + (c0 >> 1)] = __float2half_rn(a0 * g0 / (1.f + expf(-g0)));
                    C[(size_t)(r0 + 8) * No + (c0 >> 1)] = __float2half_rn(a1 * g1 / (1.f + expf(-g1)));
                }
            }
        }
    }
}

// ---------------- depthwise causal conv (fp16 in, fp32 out): 4 t-steps/thread ----------------
__global__ void conv_silu(const __half* __restrict__ zx, const float* __restrict__ cw,
                          const float* __restrict__ cb, float* __restrict__ out, int rev) {
    int idx = blockIdx.x * blockDim.x + threadIdx.x;
    if (idx >= (ROWS / 4) * CONVD) return;
    int c = idx % CONVD; int tt = idx / CONVD;
    int b = tt / (T / 4); int t0 = (tt % (T / 4)) * 4;
    const float* w = cw + c * 4;
    const __half* col = zx + (size_t)b * T * DPROJ + DI + c;
    float bias = cb[c];
    float win[7];
    if (!rev) {
#pragma unroll
        for (int j = 0; j < 7; j++) {
            int t = t0 - 3 + j;
            win[j] = (t >= 0) ? __half2float(col[(size_t)t * DPROJ]) : 0.f;
        }
#pragma unroll
        for (int i = 0; i < 4; i++) {
            float acc = bias;
#pragma unroll
            for (int k = 0; k < 4; k++) acc += w[k] * win[i + k];
            out[((size_t)b * T + t0 + i) * CONVD + c] = acc / (1.f + expf(-acc));
        }
    } else {
#pragma unroll
        for (int j = 0; j < 7; j++) {
            int t = t0 + j;
            win[j] = (t < T) ? __half2float(col[(size_t)t * DPROJ]) : 0.f;
        }
#pragma unroll
        for (int i = 0; i < 4; i++) {
            float acc = bias;
#pragma unroll
            for (int k = 0; k < 4; k++) acc += w[k] * win[i + 3 - k];
            out[((size_t)b * T + t0 + i) * CONVD + c] = acc / (1.f + expf(-acc));
        }
    }
}

// ---------------- chunked SSD scan (dt computed inline from zx) ----------------
__global__ void __launch_bounds__(256) chunk_state_kernel(
    const float* __restrict__ xbc, const __half* __restrict__ zx,
    const float* __restrict__ dtb, const float* __restrict__ alog,
    float* __restrict__ sloc, float* __restrict__ cdecay, int rev)
{
    int c = blockIdx.x, head = blockIdx.y, b = blockIdx.z;
    int tid = threadIdx.x;
    __shared__ float Xs[CQ][HD + 4];
    __shared__ float Bs[CQ][DS + 1];
    __shared__ float Ls[CQ];
    __shared__ float wdt[CQ];
    size_t tbase = (size_t)b * T;
    float A = -expf(alog[head]);

    for (int i = tid; i < CQ * HD; i += 256) {
        int j = i >> 6, p = i & 63;
        int s = c * CQ + j;
        int t = rev ? (T - 1 - s) : s;
        Xs[j][p] = xbc[(tbase + t) * CONVD + head * HD + p];
    }
    for (int i = tid; i < CQ * DS; i += 256) {
        int j = i >> 4, n = i & 15;
        int s = c * CQ + j;
        int t = rev ? (T - 1 - s) : s;
        Bs[j][n] = xbc[(tbase + t) * CONVD + DI + n];
    }
    if (tid < CQ) {
        int s = c * CQ + tid;
        int t = rev ? (T - 1 - s) : s;
        float raw = __half2float(zx[(tbase + t) * DPROJ + (DI + CONVD) + head]) + dtb[head];
        float d = (raw > 20.f) ? raw : log1pf(expf(raw));
        wdt[tid] = d;
        Ls[tid] = d * A;
    }
    __syncthreads();
    for (int off = 1; off < CQ; off <<= 1) {
        float v = 0.f;
        if (tid < CQ) v = Ls[tid] + ((tid >= off) ? Ls[tid - off] : 0.f);
        __syncthreads();
        if (tid < CQ) Ls[tid] = v;
        __syncthreads();
    }
    float Lend = Ls[CQ - 1];

    int p = tid >> 2, ng = (tid & 3) << 2;
    float acc0 = 0.f, acc1 = 0.f, acc2 = 0.f, acc3 = 0.f;
    for (int j = 0; j < CQ; j++) {
        float w = expf(Lend - Ls[j]) * wdt[j];
        float xv = w * Xs[j][p];
        acc0 += xv * Bs[j][ng + 0];
        acc1 += xv * Bs[j][ng + 1];
        acc2 += xv * Bs[j][ng + 2];
        acc3 += xv * Bs[j][ng + 3];
    }
    size_t o = ((((size_t)b * NH + head) * NC + c) * HD + p) * DS + ng;
    sloc[o + 0] = acc0; sloc[o + 1] = acc1; sloc[o + 2] = acc2; sloc[o + 3] = acc3;
    if (tid == 0) cdecay[((size_t)b * NH + head) * NC + c] = expf(Lend);
}

__global__ void __launch_bounds__(256) chunk_scan_state(
    const float* __restrict__ sloc, const float* __restrict__ cdecay,
    float* __restrict__ hinit)
{
    int bh = blockIdx.x;
    int tid = threadIdx.x;
    float h0 = 0.f, h1 = 0.f, h2 = 0.f, h3 = 0.f;
    for (int c = 0; c < NC; c++) {
        size_t base = ((size_t)bh * NC + c) * (HD * DS);
        float d = cdecay[(size_t)bh * NC + c];
        size_t i0 = base + tid, i1 = base + tid + 256, i2 = base + tid + 512, i3 = base + tid + 768;
        hinit[i0] = h0; hinit[i1] = h1; hinit[i2] = h2; hinit[i3] = h3;
        h0 = d * h0 + sloc[i0];
        h1 = d * h1 + sloc[i1];
        h2 = d * h2 + sloc[i2];
        h3 = d * h3 + sloc[i3];
    }
}

__global__ void __launch_bounds__(256) chunk_output_kernel(
    const float* __restrict__ xbc, const __half* __restrict__ zx,
    const float* __restrict__ dtb, const float* __restrict__ alog,
    const float* __restrict__ hinit, const float* __restrict__ Dp,
    float* __restrict__ y, int rev)
{
    int c = blockIdx.x, head = blockIdx.y, b = blockIdx.z;
    int tid = threadIdx.x;
    __shared__ float Xs[CQ][HD + 4];
    __shared__ float Bs[CQ][DS + 1];
    __shared__ float Cs[CQ][DS + 1];
    __shared__ float h0s[HD][DS + 1];
    __shared__ float Ls[CQ];
    __shared__ float wdt[CQ];
    __shared__ float Ss[CQ][CQ + 1];
    size_t tbase = (size_t)b * T;
    float A = -expf(alog[head]);

    for (int i = tid; i < CQ * HD; i += 256) {
        int j = i >> 6, p = i & 63;
        int s = c * CQ + j;
        int t = rev ? (T - 1 - s) : s;
        Xs[j][p] = xbc[(tbase + t) * CONVD + head * HD + p];
    }
    for (int i = tid; i < CQ * DS; i += 256) {
        int j = i >> 4, n = i & 15;
        int s = c * CQ + j;
        int t = rev ? (T - 1 - s) : s;
        size_t row = (tbase + t) * CONVD + DI;
        Bs[j][n] = xbc[row + n];
        Cs[j][n] = xbc[row + DS + n];
    }
    {
        size_t hb = ((((size_t)b * NH + head) * NC + c) * HD) * DS;
        for (int i = tid; i < HD * DS; i += 256) {
            int p = i >> 4, n = i & 15;
            h0s[p][n] = hinit[hb + i];
        }
    }
    if (tid < CQ) {
        int s = c * CQ + tid;
        int t = rev ? (T - 1 - s) : s;
        float raw = __half2float(zx[(tbase + t) * DPROJ + (DI + CONVD) + head]) + dtb[head];
        float d = (raw > 20.f) ? raw : log1pf(expf(raw));
        wdt[tid] = d;
        Ls[tid] = d * A;
    }
    __syncthreads();
    for (int off = 1; off < CQ; off <<= 1) {
        float v = 0.f;
        if (tid < CQ) v = Ls[tid] + ((tid >= off) ? Ls[tid - off] : 0.f);
        __syncthreads();
        if (tid < CQ) Ls[tid] = v;
        __syncthreads();
    }

    int t = tid >> 2;
    int quad = tid & 3;
    float Ct[DS];
#pragma unroll
    for (int n = 0; n < DS; n++) Ct[n] = Cs[t][n];
    float Lt = Ls[t];

    int jb = quad * 16;
#pragma unroll
    for (int q = 0; q < 16; q++) {
        int j = jb + q;
        float sv = 0.f;
        if (j <= t) {
            float dot = 0.f;
#pragma unroll
            for (int n = 0; n < DS; n++) dot += Ct[n] * Bs[j][n];
            sv = expf(Lt - Ls[j]) * wdt[j] * dot;
        }
        Ss[t][j] = sv;
    }
    __syncthreads();

    int pb = quad * 16;
    float acc[16];
#pragma unroll
    for (int k = 0; k < 16; k++) acc[k] = 0.f;
    for (int j = 0; j <= t; j++) {
        float sv = Ss[t][j];
#pragma unroll
        for (int k4 = 0; k4 < 4; k4++) {
            float4 xv = *(const float4*)&Xs[j][pb + k4 * 4];
            acc[k4 * 4 + 0] += sv * xv.x;
            acc[k4 * 4 + 1] += sv * xv.y;
            acc[k4 * 4 + 2] += sv * xv.z;
            acc[k4 * 4 + 3] += sv * xv.w;
        }
    }
    float et = expf(Lt);
    float Dv = Dp[head];
#pragma unroll
    for (int k = 0; k < 16; k++) {
        int p = pb + k;
        float dot = 0.f;
#pragma unroll
        for (int n = 0; n < DS; n++) dot += Ct[n] * h0s[p][n];
        acc[k] += et * dot + Dv * Xs[t][p];
    }
    int s_idx = c * CQ + t;
    int trow = rev ? (T - 1 - s_idx) : s_idx;
    float* yr = y + (tbase + trow) * DI + head * HD + pb;
#pragma unroll
    for (int k4 = 0; k4 < 4; k4++) {
        *(float4*)(yr + k4 * 4) = make_float4(acc[k4 * 4 + 0], acc[k4 * 4 + 1], acc[k4 * 4 + 2], acc[k4 * 4 + 3]);
    }
}

// ---------------- y = y * silu(z); RMSNorm(y) * gw -> fp16 ----------------
__global__ void gate_rms(const __half* __restrict__ zx, const float* __restrict__ y,
                         const float* __restrict__ gw, __half* __restrict__ yh) {
    int row = blockIdx.x;
    const __half* z = zx + (size_t)row * DPROJ;
    const float* yr = y + (size_t)row * DI;
    __half* yo = yh + (size_t)row * DI;
    int tid = threadIdx.x;
    float v[4]; float s2 = 0.f;
#pragma unroll
    for (int j = 0; j < 4; j++) {
        int c = tid + j * 256;
        float zz = __half2float(z[c]);
        float val = yr[c] * (zz / (1.f + expf(-zz)));
        v[j] = val; s2 += val * val;
    }
#pragma unroll
    for (int o = 16; o > 0; o >>= 1) s2 += __shfl_xor_sync(0xffffffffu, s2, o);
    __shared__ float rs[8];
    int wid = tid >> 5;
    if ((tid & 31) == 0) rs[wid] = s2;
    __syncthreads();
    float tot = 0.f;
#pragma unroll
    for (int i = 0; i < 8; i++) tot += rs[i];
    float inv = rsqrtf(tot * (1.f / DI) + 1e-5f);
#pragma unroll
    for (int j = 0; j < 4; j++) {
        int c = tid + j * 256;
        yo[c] = __float2half_rn(v[j] * inv * gw[c]);
    }
}

// ---------------- host ----------------
static void* sym_addr_v(const void* sym) {
    void* p = nullptr;
    cudaGetSymbolAddress(&p, sym);
    return p;
}

extern "C" void kernel_launch(void* const* d_in, const int* in_sizes, int n_in,
                              void* d_out, int out_size) {
    const float* in_x   = (const float*)d_in[0];
    const float* n1w    = (const float*)d_in[1];
    const float* n1b    = (const float*)d_in[2];
    const float* inw    = (const float*)d_in[3];
    const float* cw     = (const float*)d_in[4];
    const float* cb     = (const float*)d_in[5];
    const float* dtb    = (const float*)d_in[6];
    const float* alog   = (const float*)d_in[7];
    const float* Dp     = (const float*)d_in[8];
    const float* gw     = (const float*)d_in[9];
    const float* ow     = (const float*)d_in[10];
    const float* n2w    = (const float*)d_in[11];
    const float* n2b    = (const float*)d_in[12];
    const float* f1w    = (const float*)d_in[13];
    const float* f2w    = (const float*)d_in[14];
    const float* nfw    = (const float*)d_in[15];
    const float* nfb    = (const float*)d_in[16];

    float*  resid = (float*) sym_addr_v(g_resid);
    __half* hh    = (__half*)sym_addr_v(g_hh);
    __half* zx    = (__half*)sym_addr_v(g_zx);
    float*  xbc   = (float*) sym_addr_v(g_xbc);
    float*  ybuf  = (float*) sym_addr_v(g_y);
    __half* yh    = (__half*)sym_addr_v(g_yh);
    float*  tmp   = (float*) sym_addr_v(g_tmp);
    __half* gluh  = (__half*)sym_addr_v(g_gluh);
    float*  xb    = (float*) sym_addr_v(g_x);
    float*  sloc  = (float*) sym_addr_v(g_sloc);
    float*  hinit = (float*) sym_addr_v(g_hinit);
    float*  cdec  = (float*) sym_addr_v(g_cdecay);
    __half* winw  = (__half*)sym_addr_v(g_winw);
    __half* wow   = (__half*)sym_addr_v(g_wow);
    __half* wf1   = (__half*)sym_addr_v(g_wf1);
    __half* wf2   = (__half*)sym_addr_v(g_wf2);

    static int smem_set = 0;
    if (!smem_set) {
        cudaFuncSetAttribute(h16_gemm_nt, cudaFuncAttributeMaxDynamicSharedMemorySize, GEMM_SMEM);
        smem_set = 1;
    }

    // convert weights to fp16 (f1 also row-interleaved for fused GLU)
    {
        int n;
        n = 4 * DPROJ * DM / 4;      conv_copy_h<<<(n + 255) / 256, 256>>>(inw, winw, n);
        n = 4 * DM * DI / 4;         conv_copy_h<<<(n + 255) / 256, 256>>>(ow, wow, n);
        n = 4 * 2 * DINTER * DM / 4; conv_interleave_f1_h<<<(n + 255) / 256, 256>>>(f1w, wf1);
        n = 4 * DM * DINTER / 4;     conv_copy_h<<<(n + 255) / 256, 256>>>(f2w, wf2, n);
    }

    for (int i = 0; i < 4; i++) {
        int rev = i & 1;
        const float* xin = (i == 0) ? in_x : xb;

        add_ln_kernel<<<ROWS, 128>>>(xin, resid, n1w + i * DM, n1b + i * DM, hh, (i == 0) ? 1 : 0, 1);

        {   // in_proj [8192 x 2096 x 512] -> zx fp16
            dim3 grid((DPROJ + 255) / 256, ROWS / 128);
            h16_gemm_nt<<<grid, 256, GEMM_SMEM>>>(ROWS, DPROJ, DM, hh, winw + (size_t)i * DPROJ * DM, zx, 2);
        }

        conv_silu<<<((ROWS / 4) * CONVD + 255) / 256, 256>>>(zx, cw + (size_t)i * CONVD * 4, cb + i * CONVD, xbc, rev);

        {
            dim3 gs(NC, NH, BATCH);
            chunk_state_kernel<<<gs, 256>>>(xbc, zx, dtb + i * NH, alog + i * NH, sloc, cdec, rev);
            chunk_scan_state<<<BATCH * NH, 256>>>(sloc, cdec, hinit);
            chunk_output_kernel<<<gs, 256>>>(xbc, zx, dtb + i * NH, alog + i * NH, hinit, Dp + i * NH, ybuf, rev);
        }

        gate_rms<<<ROWS, 256>>>(zx, ybuf, gw + i * DI, yh);

        {   // out_proj [8192 x 512 x 1024]
            dim3 grid(DM / 256, ROWS / 128);
            h16_gemm_nt<<<grid, 256, GEMM_SMEM>>>(ROWS, DM, DI, yh, wow + (size_t)i * DM * DI, tmp, 0);
        }

        add_ln_kernel<<<ROWS, 128>>>(tmp, resid, n2w + i * DM, n2b + i * DM, hh, 0, 1);

        {   // FFN f1 + fused GLU
            dim3 grid(DM / 256, ROWS / 128);
            h16_gemm_nt<<<grid, 256, GEMM_SMEM>>>(ROWS, DM, DM, hh, wf1 + (size_t)i * DM * DM, gluh, 1);
        }

        {   // FFN f2 [8192 x 512 x 256]
            dim3 grid(DM / 256, ROWS / 128);
            h16_gemm_nt<<<grid, 256, GEMM_SMEM>>>(ROWS, DM, DINTER, gluh, wf2 + (size_t)i * DM * DINTER, xb, 0);
        }
    }

    add_ln_kernel<<<ROWS, 128>>>(xb, resid, nfw, nfb, (float*)d_out, 0, 0);
}

// round 11
// speedup vs baseline: 6.3867x; 1.0064x over previous
#include <cuda_runtime.h>
#include <cuda_fp16.h>
#include <math.h>
#include <stdint.h>

#define BATCH 4
#define T 2048
#define DM 512
#define DI 1024
#define NH 16
#define HD 64
#define DS 16
#define CONVD 1056
#define DPROJ 2096
#define DINTER 256
#define ROWS (BATCH*T)

// chunked scan
#define CQ 64
#define NC (T/CQ)

// fp16 GEMM tiling: block 128(M) x 256(N), BK=64 halves, 4 stages
#define BKH 64
#define LDA 72                      // halves per smem row (144 B)
#define A_ST_BYTES (128*144)
#define B_ST_BYTES (256*144)
#define ST_BYTES (A_ST_BYTES+B_ST_BYTES)   // 55296
#define STG 4
#define GEMM_SMEM (STG*ST_BYTES)    // 221184

// ---------------- scratch ----------------
__device__ float g_resid[ROWS*DM];
__device__ __half g_hh[ROWS*DM];          // LN output (fp16, GEMM A)
__device__ __half g_zx[ROWS*DPROJ];       // in_proj output (fp16)
__device__ float g_xbc[ROWS*CONVD];
__device__ float g_y[ROWS*DI];
__device__ __half g_yh[ROWS*DI];
__device__ float g_tmp[ROWS*DM];
__device__ __half g_gluh[ROWS*DINTER];
__device__ float g_x[ROWS*DM];
__device__ float g_sloc[BATCH*NH*NC*HD*DS];
__device__ float g_hinit[BATCH*NH*NC*HD*DS];
__device__ float g_cdecay[BATCH*NH*NC];
// fp16 weights
__device__ __half g_winw[4*DPROJ*DM];
__device__ __half g_wow[4*DM*DI];
__device__ __half g_wf1[4*2*DINTER*DM];
__device__ __half g_wf2[4*DM*DINTER];

// ---------------- weight conversion ----------------
__global__ void conv_copy_h(const float* __restrict__ src, __half* __restrict__ dst, int n4) {
    int i = blockIdx.x * blockDim.x + threadIdx.x;
    if (i >= n4) return;
    float4 v = ((const float4*)src)[i];
    ((__half2*)dst)[2 * i]     = __floats2half2_rn(v.x, v.y);
    ((__half2*)dst)[2 * i + 1] = __floats2half2_rn(v.z, v.w);
}

__global__ void conv_interleave_f1_h(const float* __restrict__ src, __half* __restrict__ dst) {
    int i = blockIdx.x * blockDim.x + threadIdx.x;
    int total4 = 4 * 512 * 512 / 4;
    if (i >= total4) return;
    int k4 = i & 127;
    int row = (i >> 7) & 511;
    int l = i >> 16;
    float4 v = ((const float4*)src)[i];
    int drow = (row < 256) ? (2 * row) : (2 * (row - 256) + 1);
    size_t o = (((size_t)l * 512 + drow) * 512 + k4 * 4);
    ((__half2*)(dst + o))[0] = __floats2half2_rn(v.x, v.y);
    ((__half2*)(dst + o))[1] = __floats2half2_rn(v.z, v.w);
}

// ---------------- residual add + LayerNorm ----------------
__global__ void add_ln_kernel(const float* __restrict__ xin, float* __restrict__ resid,
                              const float* __restrict__ w, const float* __restrict__ bch,
                              void* __restrict__ out, int first, int to_half) {
    int row = blockIdx.x;
    const float* xr = xin + (size_t)row * DM;
    float* rr = resid + (size_t)row * DM;
    int tid = threadIdx.x;
    float v[4]; float s = 0.f, s2 = 0.f;
#pragma unroll
    for (int j = 0; j < 4; j++) {
        int c = tid + j * 128;
        float val = xr[c];
        if (!first) val += rr[c];
        v[j] = val; s += val; s2 += val * val;
    }
#pragma unroll
    for (int o = 16; o > 0; o >>= 1) {
        s  += __shfl_xor_sync(0xffffffffu, s, o);
        s2 += __shfl_xor_sync(0xffffffffu, s2, o);
    }
    __shared__ float rs[4], rs2[4];
    int wid = tid >> 5;
    if ((tid & 31) == 0) { rs[wid] = s; rs2[wid] = s2; }
    __syncthreads();
    float tot  = rs[0] + rs[1] + rs[2] + rs[3];
    float tot2 = rs2[0] + rs2[1] + rs2[2] + rs2[3];
    float mu = tot * (1.f / DM);
    float var = tot2 * (1.f / DM) - mu * mu;
    float inv = rsqrtf(var + 1e-5f);
#pragma unroll
    for (int j = 0; j < 4; j++) {
        int c = tid + j * 128;
        float val = v[j];
        rr[c] = val;
        float o2 = (val - mu) * inv * w[c] + bch[c];
        if (to_half) ((__half*)out)[(size_t)row * DM + c] = __float2half_rn(o2);
        else         ((float*)out)[(size_t)row * DM + c] = o2;
    }
}

// ---------------- fp16 tensor-core NT GEMM (128x256 block, 4-stage, 1 sync/iter) ----------------
#define MMA_F16(d, a, b) \
    asm volatile("mma.sync.aligned.m16n8k16.row.col.f32.f16.f16.f32 " \
                 "{%0,%1,%2,%3},{%4,%5,%6,%7},{%8,%9},{%0,%1,%2,%3};" \
                 : "+f"(d[0]), "+f"(d[1]), "+f"(d[2]), "+f"(d[3]) \
                 : "r"(a[0]), "r"(a[1]), "r"(a[2]), "r"(a[3]), "r"(b[0]), "r"(b[1]))

#define LDSM_X4(R, addr) \
    asm volatile("ldmatrix.sync.aligned.m8n8.x4.shared.b16 {%0,%1,%2,%3}, [%4];" \
                 : "=r"((R)[0]), "=r"((R)[1]), "=r"((R)[2]), "=r"((R)[3]) : "r"(addr))

__device__ __forceinline__ void gemm_load_stage(
    const __half* __restrict__ A, const __half* __restrict__ Bw,
    int K, int N, int bm, int bn, int it, int s, int tid, uint32_t sbase)
{
    int k0 = it * BKH;
    uint32_t stA = sbase + (uint32_t)s * ST_BYTES;
    uint32_t stB = stA + A_ST_BYTES;
#pragma unroll
    for (int i = 0; i < 4; i++) {
        int idx = i * 256 + tid;
        int row = idx >> 3, c = idx & 7;
        uint32_t dst = stA + (uint32_t)row * 144u + (uint32_t)(c << 4);
        const __half* gp = A + (size_t)(bm + row) * K + k0 + c * 8;
        asm volatile("cp.async.cg.shared.global [%0], [%1], 16;" :: "r"(dst), "l"(gp));
    }
#pragma unroll
    for (int i = 0; i < 8; i++) {
        int idx = i * 256 + tid;
        int row = idx >> 3, c = idx & 7;
        int rb = bn + row;
        int valid = (rb < N);
        uint32_t dst = stB + (uint32_t)row * 144u + (uint32_t)(c << 4);
        const __half* gp = Bw + (size_t)(valid ? rb : 0) * K + k0 + c * 8;
        int ssz = valid ? 16 : 0;
        asm volatile("cp.async.cg.shared.global [%0], [%1], 16, %2;" :: "r"(dst), "l"(gp), "r"(ssz));
    }
    asm volatile("cp.async.commit_group;" ::: "memory");
}

// out_mode: 0 = fp32 C, 1 = fused GLU (fp16, N/2 cols), 2 = fp16 C
__global__ void __launch_bounds__(256) h16_gemm_nt(int M, int N, int K,
                                                   const __half* __restrict__ A,
                                                   const __half* __restrict__ Bw,
                                                   void* __restrict__ Cv, int out_mode) {
    extern __shared__ char smem[];
    uint32_t sbase = (uint32_t)__cvta_generic_to_shared(smem);
    int bm = blockIdx.y * 128, bn = blockIdx.x * 256;
    int tid = threadIdx.x;
    int wid = tid >> 5, lane = tid & 31;
    int wm = (wid & 1) * 64;
    int wn = (wid >> 1) * 64;
    int g = lane >> 2, tig = lane & 3;

    int arow = lane & 15;
    int acol = (lane >> 4) << 3;
    int brow = ((lane >> 4) << 3) + (lane & 7);
    int bcol = ((lane >> 3) & 1) << 3;
    uint32_t aoff = ((uint32_t)((wm + arow) * LDA + acol)) * 2u;
    uint32_t boff = ((uint32_t)((wn + brow) * LDA + bcol)) * 2u + A_ST_BYTES;

    float acc[4][8][4];
#pragma unroll
    for (int i = 0; i < 4; i++)
#pragma unroll
        for (int j = 0; j < 8; j++)
#pragma unroll
            for (int k = 0; k < 4; k++) acc[i][j][k] = 0.f;

    int NIT = K / BKH;
    // prologue: fill STG-1 stages
#pragma unroll
    for (int p = 0; p < STG - 1; p++)
        if (p < NIT) gemm_load_stage(A, Bw, K, N, bm, bn, p, p, tid, sbase);

    for (int it = 0; it < NIT; ++it) {
        // groups newer than tile `it` after all commits so far:
        int pend = NIT - it - 1; if (pend > STG - 2) pend = STG - 2;
        if (pend == 2)      asm volatile("cp.async.wait_group 2;" ::: "memory");
        else if (pend == 1) asm volatile("cp.async.wait_group 1;" ::: "memory");
        else                asm volatile("cp.async.wait_group 0;" ::: "memory");
        __syncthreads();   // all warps done with stage (it-1)%STG reads

        // prefetch tile it+STG-1 into slot (it-1)%STG — safe after the sync above
        int ld = it + STG - 1;
        if (ld < NIT) gemm_load_stage(A, Bw, K, N, bm, bn, ld, ld % STG, tid, sbase);

        int s = it % STG;
        uint32_t Ab = sbase + (uint32_t)s * ST_BYTES + aoff;
        uint32_t Bb = sbase + (uint32_t)s * ST_BYTES + boff;
#pragma unroll
        for (int ks = 0; ks < 4; ks++) {
            uint32_t kbyte = (uint32_t)(ks * 16 * 2);
            uint32_t a[4][4], b[4][4];
#pragma unroll
            for (int mt = 0; mt < 4; mt++)
                LDSM_X4(a[mt], Ab + (uint32_t)(mt * 16 * LDA) * 2u + kbyte);
#pragma unroll
            for (int np = 0; np < 4; np++)
                LDSM_X4(b[np], Bb + (uint32_t)(np * 16 * LDA) * 2u + kbyte);
#pragma unroll
            for (int mt = 0; mt < 4; mt++)
#pragma unroll
                for (int np = 0; np < 4; np++) {
                    MMA_F16(acc[mt][2 * np], a[mt], b[np]);
                    uint32_t bhi[2] = { b[np][2], b[np][3] };
                    MMA_F16(acc[mt][2 * np + 1], a[mt], bhi);
                }
        }
        // no trailing sync: next iteration's barrier protects stage reuse
    }

    if (out_mode == 0) {
        float* C = (float*)Cv;
#pragma unroll
        for (int mt = 0; mt < 4; mt++) {
            int r0 = bm + wm + mt * 16 + g;
#pragma unroll
            for (int nt = 0; nt < 8; nt++) {
                int c0 = bn + wn + nt * 8 + tig * 2;
                if (c0 < N) {
                    *(float2*)&C[(size_t)r0 * N + c0] = make_float2(acc[mt][nt][0], acc[mt][nt][1]);
                    *(float2*)&C[(size_t)(r0 + 8) * N + c0] = make_float2(acc[mt][nt][2], acc[mt][nt][3]);
                }
            }
        }
    } else if (out_mode == 2) {
        __half* C = (__half*)Cv;
#pragma unroll
        for (int mt = 0; mt < 4; mt++) {
            int r0 = bm + wm + mt * 16 + g;
#pragma unroll
            for (int nt = 0; nt < 8; nt++) {
                int c0 = bn + wn + nt * 8 + tig * 2;
                if (c0 < N) {
                    *(__half2*)&C[(size_t)r0 * N + c0] = __floats2half2_rn(acc[mt][nt][0], acc[mt][nt][1]);
                    *(__half2*)&C[(size_t)(r0 + 8) * N + c0] = __floats2half2_rn(acc[mt][nt][2], acc[mt][nt][3]);
                }
            }
        }
    } else {
        __half* C = (__half*)Cv;
        int No = N >> 1;
#pragma unroll
        for (int mt = 0; mt < 4; mt++) {
            int r0 = bm + wm + mt * 16 + g;
#pragma unroll
            for (int nt = 0; nt < 8; nt++) {
                int c0 = bn + wn + nt * 8 + tig * 2;
                if (c0 < N) {
                    float a0 = acc[mt][nt][0], g0 = acc[mt][nt][1];
                    float a1 = acc[mt][nt][2], g1 = acc[mt][nt][3];
                    C[(size_t)r0 * No + (c0 >> 1)] = __float2half_rn(a0 * g0 / (1.f + expf(-g0)));
                    C[(size_t)(r0 + 8) * No + (c0 >> 1)] = __float2half_rn(a1 * g1 / (1.f + expf(-g1)));
                }
            }
        }
    }
}

// ---------------- depthwise causal conv (fp16 in, fp32 out): 4 t-steps/thread ----------------
__global__ void conv_silu(const __half* __restrict__ zx, const float* __restrict__ cw,
                          const float* __restrict__ cb, float* __restrict__ out, int rev) {
    int idx = blockIdx.x * blockDim.x + threadIdx.x;
    if (idx >= (ROWS / 4) * CONVD) return;
    int c = idx % CONVD; int tt = idx / CONVD;
    int b = tt / (T / 4); int t0 = (tt % (T / 4)) * 4;
    const float* w = cw + c * 4;
    const __half* col = zx + (size_t)b * T * DPROJ + DI + c;
    float bias = cb[c];
    float win[7];
    if (!rev) {
#pragma unroll
        for (int j = 0; j < 7; j++) {
            int t = t0 - 3 + j;
            win[j] = (t >= 0) ? __half2float(col[(size_t)t * DPROJ]) : 0.f;
        }
#pragma unroll
        for (int i = 0; i < 4; i++) {
            float acc = bias;
#pragma unroll
            for (int k = 0; k < 4; k++) acc += w[k] * win[i + k];
            out[((size_t)b * T + t0 + i) * CONVD + c] = acc / (1.f + expf(-acc));
        }
    } else {
#pragma unroll
        for (int j = 0; j < 7; j++) {
            int t = t0 + j;
            win[j] = (t < T) ? __half2float(col[(size_t)t * DPROJ]) : 0.f;
        }
#pragma unroll
        for (int i = 0; i < 4; i++) {
            float acc = bias;
#pragma unroll
            for (int k = 0; k < 4; k++) acc += w[k] * win[i + 3 - k];
            out[((size_t)b * T + t0 + i) * CONVD + c] = acc / (1.f + expf(-acc));
        }
    }
}

// ---------------- chunked SSD scan (dt computed inline from zx) ----------------
__global__ void __launch_bounds__(256) chunk_state_kernel(
    const float* __restrict__ xbc, const __half* __restrict__ zx,
    const float* __restrict__ dtb, const float* __restrict__ alog,
    float* __restrict__ sloc, float* __restrict__ cdecay, int rev)
{
    int c = blockIdx.x, head = blockIdx.y, b = blockIdx.z;
    int tid = threadIdx.x;
    __shared__ float Xs[CQ][HD + 4];
    __shared__ float Bs[CQ][DS + 1];
    __shared__ float Ls[CQ];
    __shared__ float wdt[CQ];
    size_t tbase = (size_t)b * T;
    float A = -expf(alog[head]);

    for (int i = tid; i < CQ * HD; i += 256) {
        int j = i >> 6, p = i & 63;
        int s = c * CQ + j;
        int t = rev ? (T - 1 - s) : s;
        Xs[j][p] = xbc[(tbase + t) * CONVD + head * HD + p];
    }
    for (int i = tid; i < CQ * DS; i += 256) {
        int j = i >> 4, n = i & 15;
        int s = c * CQ + j;
        int t = rev ? (T - 1 - s) : s;
        Bs[j][n] = xbc[(tbase + t) * CONVD + DI + n];
    }
    if (tid < CQ) {
        int s = c * CQ + tid;
        int t = rev ? (T - 1 - s) : s;
        float raw = __half2float(zx[(tbase + t) * DPROJ + (DI + CONVD) + head]) + dtb[head];
        float d = (raw > 20.f) ? raw : log1pf(expf(raw));
        wdt[tid] = d;
        Ls[tid] = d * A;
    }
    __syncthreads();
    for (int off = 1; off < CQ; off <<= 1) {
        float v = 0.f;
        if (tid < CQ) v = Ls[tid] + ((tid >= off) ? Ls[tid - off] : 0.f);
        __syncthreads();
        if (tid < CQ) Ls[tid] = v;
        __syncthreads();
    }
    float Lend = Ls[CQ - 1];

    int p = tid >> 2, ng = (tid & 3) << 2;
    float acc0 = 0.f, acc1 = 0.f, acc2 = 0.f, acc3 = 0.f;
    for (int j = 0; j < CQ; j++) {
        float w = expf(Lend - Ls[j]) * wdt[j];
        float xv = w * Xs[j][p];
        acc0 += xv * Bs[j][ng + 0];
        acc1 += xv * Bs[j][ng + 1];
        acc2 += xv * Bs[j][ng + 2];
        acc3 += xv * Bs[j][ng + 3];
    }
    size_t o = ((((size_t)b * NH + head) * NC + c) * HD + p) * DS + ng;
    sloc[o + 0] = acc0; sloc[o + 1] = acc1; sloc[o + 2] = acc2; sloc[o + 3] = acc3;
    if (tid == 0) cdecay[((size_t)b * NH + head) * NC + c] = expf(Lend);
}

__global__ void __launch_bounds__(256) chunk_scan_state(
    const float* __restrict__ sloc, const float* __restrict__ cdecay,
    float* __restrict__ hinit)
{
    int bh = blockIdx.x;
    int tid = threadIdx.x;
    float h0 = 0.f, h1 = 0.f, h2 = 0.f, h3 = 0.f;
    for (int c = 0; c < NC; c++) {
        size_t base = ((size_t)bh * NC + c) * (HD * DS);
        float d = cdecay[(size_t)bh * NC + c];
        size_t i0 = base + tid, i1 = base + tid + 256, i2 = base + tid + 512, i3 = base + tid + 768;
        hinit[i0] = h0; hinit[i1] = h1; hinit[i2] = h2; hinit[i3] = h3;
        h0 = d * h0 + sloc[i0];
        h1 = d * h1 + sloc[i1];
        h2 = d * h2 + sloc[i2];
        h3 = d * h3 + sloc[i3];
    }
}

__global__ void __launch_bounds__(256) chunk_output_kernel(
    const float* __restrict__ xbc, const __half* __restrict__ zx,
    const float* __restrict__ dtb, const float* __restrict__ alog,
    const float* __restrict__ hinit, const float* __restrict__ Dp,
    float* __restrict__ y, int rev)
{
    int c = blockIdx.x, head = blockIdx.y, b = blockIdx.z;
    int tid = threadIdx.x;
    __shared__ float Xs[CQ][HD + 4];
    __shared__ float Bs[CQ][DS + 1];
    __shared__ float Cs[CQ][DS + 1];
    __shared__ float h0s[HD][DS + 1];
    __shared__ float Ls[CQ];
    __shared__ float wdt[CQ];
    __shared__ float Ss[CQ][CQ + 1];
    size_t tbase = (size_t)b * T;
    float A = -expf(alog[head]);

    for (int i = tid; i < CQ * HD; i += 256) {
        int j = i >> 6, p = i & 63;
        int s = c * CQ + j;
        int t = rev ? (T - 1 - s) : s;
        Xs[j][p] = xbc[(tbase + t) * CONVD + head * HD + p];
    }
    for (int i = tid; i < CQ * DS; i += 256) {
        int j = i >> 4, n = i & 15;
        int s = c * CQ + j;
        int t = rev ? (T - 1 - s) : s;
        size_t row = (tbase + t) * CONVD + DI;
        Bs[j][n] = xbc[row + n];
        Cs[j][n] = xbc[row + DS + n];
    }
    {
        size_t hb = ((((size_t)b * NH + head) * NC + c) * HD) * DS;
        for (int i = tid; i < HD * DS; i += 256) {
            int p = i >> 4, n = i & 15;
            h0s[p][n] = hinit[hb + i];
        }
    }
    if (tid < CQ) {
        int s = c * CQ + tid;
        int t = rev ? (T - 1 - s) : s;
        float raw = __half2float(zx[(tbase + t) * DPROJ + (DI + CONVD) + head]) + dtb[head];
        float d = (raw > 20.f) ? raw : log1pf(expf(raw));
        wdt[tid] = d;
        Ls[tid] = d * A;
    }
    __syncthreads();
    for (int off = 1; off < CQ; off <<= 1) {
        float v = 0.f;
        if (tid < CQ) v = Ls[tid] + ((tid >= off) ? Ls[tid - off] : 0.f);
        __syncthreads();
        if (tid < CQ) Ls[tid] = v;
        __syncthreads();
    }

    int t = tid >> 2;
    int quad = tid & 3;
    float Ct[DS];
#pragma unroll
    for (int n = 0; n < DS; n++) Ct[n] = Cs[t][n];
    float Lt = Ls[t];

    int jb = quad * 16;
#pragma unroll
    for (int q = 0; q < 16; q++) {
        int j = jb + q;
        float sv = 0.f;
        if (j <= t) {
            float dot = 0.f;
#pragma unroll
            for (int n = 0; n < DS; n++) dot += Ct[n] * Bs[j][n];
            sv = expf(Lt - Ls[j]) * wdt[j] * dot;
        }
        Ss[t][j] = sv;
    }
    __syncthreads();

    int pb = quad * 16;
    float acc[16];
#pragma unroll
    for (int k = 0; k < 16; k++) acc[k] = 0.f;
    for (int j = 0; j <= t; j++) {
        float sv = Ss[t][j];
#pragma unroll
        for (int k4 = 0; k4 < 4; k4++) {
            float4 xv = *(const float4*)&Xs[j][pb + k4 * 4];
            acc[k4 * 4 + 0] += sv * xv.x;
            acc[k4 * 4 + 1] += sv * xv.y;
            acc[k4 * 4 + 2] += sv * xv.z;
            acc[k4 * 4 + 3] += sv * xv.w;
        }
    }
    float et = expf(Lt);
    float Dv = Dp[head];
#pragma unroll
    for (int k = 0; k < 16; k++) {
        int p = pb + k;
        float dot = 0.f;
#pragma unroll
        for (int n = 0; n < DS; n++) dot += Ct[n] * h0s[p][n];
        acc[k] += et * dot + Dv * Xs[t][p];
    }
    int s_idx = c * CQ + t;
    int trow = rev ? (T - 1 - s_idx) : s_idx;
    float* yr = y + (tbase + trow) * DI + head * HD + pb;
#pragma unroll
    for (int k4 = 0; k4 < 4; k4++) {
        *(float4*)(yr + k4 * 4) = make_float4(acc[k4 * 4 + 0], acc[k4 * 4 + 1], acc[k4 * 4 + 2], acc[k4 * 4 + 3]);
    }
}

// ---------------- y = y * silu(z); RMSNorm(y) * gw -> fp16 ----------------
__global__ void gate_rms(const __half* __restrict__ zx, const float* __restrict__ y,
                         const float* __restrict__ gw, __half* __restrict__ yh) {
    int row = blockIdx.x;
    const __half* z = zx + (size_t)row * DPROJ;
    const float* yr = y + (size_t)row * DI;
    __half* yo = yh + (size_t)row * DI;
    int tid = threadIdx.x;
    float v[4]; float s2 = 0.f;
#pragma unroll
    for (int j = 0; j < 4; j++) {
        int c = tid + j * 256;
        float zz = __half2float(z[c]);
        float val = yr[c] * (zz / (1.f + expf(-zz)));
        v[j] = val; s2 += val * val;
    }
#pragma unroll
    for (int o = 16; o > 0; o >>= 1) s2 += __shfl_xor_sync(0xffffffffu, s2, o);
    __shared__ float rs[8];
    int wid = tid >> 5;
    if ((tid & 31) == 0) rs[wid] = s2;
    __syncthreads();
    float tot = 0.f;
#pragma unroll
    for (int i = 0; i < 8; i++) tot += rs[i];
    float inv = rsqrtf(tot * (1.f / DI) + 1e-5f);
#pragma unroll
    for (int j = 0; j < 4; j++) {
        int c = tid + j * 256;
        yo[c] = __float2half_rn(v[j] * inv * gw[c]);
    }
}

// ---------------- host ----------------
static void* sym_addr_v(const void* sym) {
    void* p = nullptr;
    cudaGetSymbolAddress(&p, sym);
    return p;
}

extern "C" void kernel_launch(void* const* d_in, const int* in_sizes, int n_in,
                              void* d_out, int out_size) {
    const float* in_x   = (const float*)d_in[0];
    const float* n1w    = (const float*)d_in[1];
    const float* n1b    = (const float*)d_in[2];
    const float* inw    = (const float*)d_in[3];
    const float* cw     = (const float*)d_in[4];
    const float* cb     = (const float*)d_in[5];
    const float* dtb    = (const float*)d_in[6];
    const float* alog   = (const float*)d_in[7];
    const float* Dp     = (const float*)d_in[8];
    const float* gw     = (const float*)d_in[9];
    const float* ow     = (const float*)d_in[10];
    const float* n2w    = (const float*)d_in[11];
    const float* n2b    = (const float*)d_in[12];
    const float* f1w    = (const float*)d_in[13];
    const float* f2w    = (const float*)d_in[14];
    const float* nfw    = (const float*)d_in[15];
    const float* nfb    = (const float*)d_in[16];

    float*  resid = (float*) sym_addr_v(g_resid);
    __half* hh    = (__half*)sym_addr_v(g_hh);
    __half* zx    = (__half*)sym_addr_v(g_zx);
    float*  xbc   = (float*) sym_addr_v(g_xbc);
    float*  ybuf  = (float*) sym_addr_v(g_y);
    __half* yh    = (__half*)sym_addr_v(g_yh);
    float*  tmp   = (float*) sym_addr_v(g_tmp);
    __half* gluh  = (__half*)sym_addr_v(g_gluh);
    float*  xb    = (float*) sym_addr_v(g_x);
    float*  sloc  = (float*) sym_addr_v(g_sloc);
    float*  hinit = (float*) sym_addr_v(g_hinit);
    float*  cdec  = (float*) sym_addr_v(g_cdecay);
    __half* winw  = (__half*)sym_addr_v(g_winw);
    __half* wow   = (__half*)sym_addr_v(g_wow);
    __half* wf1   = (__half*)sym_addr_v(g_wf1);
    __half* wf2   = (__half*)sym_addr_v(g_wf2);

    static int smem_set = 0;
    if (!smem_set) {
        cudaFuncSetAttribute(h16_gemm_nt, cudaFuncAttributeMaxDynamicSharedMemorySize, GEMM_SMEM);
        smem_set = 1;
    }

    // convert weights to fp16 (f1 also row-interleaved for fused GLU)
    {
        int n;
        n = 4 * DPROJ * DM / 4;      conv_copy_h<<<(n + 255) / 256, 256>>>(inw, winw, n);
        n = 4 * DM * DI / 4;         conv_copy_h<<<(n + 255) / 256, 256>>>(ow, wow, n);
        n = 4 * 2 * DINTER * DM / 4; conv_interleave_f1_h<<<(n + 255) / 256, 256>>>(f1w, wf1);
        n = 4 * DM * DINTER / 4;     conv_copy_h<<<(n + 255) / 256, 256>>>(f2w, wf2, n);
    }

    for (int i = 0; i < 4; i++) {
        int rev = i & 1;
        const float* xin = (i == 0) ? in_x : xb;

        add_ln_kernel<<<ROWS, 128>>>(xin, resid, n1w + i * DM, n1b + i * DM, hh, (i == 0) ? 1 : 0, 1);

        {   // in_proj [8192 x 2096 x 512] -> zx fp16
            dim3 grid((DPROJ + 255) / 256, ROWS / 128);
            h16_gemm_nt<<<grid, 256, GEMM_SMEM>>>(ROWS, DPROJ, DM, hh, winw + (size_t)i * DPROJ * DM, zx, 2);
        }

        conv_silu<<<((ROWS / 4) * CONVD + 255) / 256, 256>>>(zx, cw + (size_t)i * CONVD * 4, cb + i * CONVD, xbc, rev);

        {
            dim3 gs(NC, NH, BATCH);
            chunk_state_kernel<<<gs, 256>>>(xbc, zx, dtb + i * NH, alog + i * NH, sloc, cdec, rev);
            chunk_scan_state<<<BATCH * NH, 256>>>(sloc, cdec, hinit);
            chunk_output_kernel<<<gs, 256>>>(xbc, zx, dtb + i * NH, alog + i * NH, hinit, Dp + i * NH, ybuf, rev);
        }

        gate_rms<<<ROWS, 256>>>(zx, ybuf, gw + i * DI, yh);

        {   // out_proj [8192 x 512 x 1024]
            dim3 grid(DM / 256, ROWS / 128);
            h16_gemm_nt<<<grid, 256, GEMM_SMEM>>>(ROWS, DM, DI, yh, wow + (size_t)i * DM * DI, tmp, 0);
        }

        add_ln_kernel<<<ROWS, 128>>>(tmp, resid, n2w + i * DM, n2b + i * DM, hh, 0, 1);

        {   // FFN f1 + fused GLU
            dim3 grid(DM / 256, ROWS / 128);
            h16_gemm_nt<<<grid, 256, GEMM_SMEM>>>(ROWS, DM, DM, hh, wf1 + (size_t)i * DM * DM, gluh, 1);
        }

        {   // FFN f2 [8192 x 512 x 256]
            dim3 grid(DM / 256, ROWS / 128);
            h16_gemm_nt<<<grid, 256, GEMM_SMEM>>>(ROWS, DM, DINTER, gluh, wf2 + (size_t)i * DM * DINTER, xb, 0);
        }
    }

    add_ln_kernel<<<ROWS, 128>>>(xb, resid, nfw, nfb, (float*)d_out, 0, 0);
}